// round 1
// baseline (speedup 1.0000x reference)
#include <cuda_runtime.h>
#include <math.h>

#define BATCH 2
#define T_SEQ 2048
#define C_DIM 1024
#define NH 16
#define NKV 8
#define HD 64
#define M_ROWS (BATCH * T_SEQ)   // 4096

// Scratch (allocation-free rule: __device__ globals)
__device__ float g_q[M_ROWS * NH * HD];    // (b,t,h,d)  16 MB
__device__ float g_k[M_ROWS * NKV * HD];   //  8 MB
__device__ float g_v[M_ROWS * NKV * HD];   //  8 MB
__device__ float g_y[M_ROWS * NH * HD];    // (b,t,h,d)  16 MB
__device__ float g_sq[BATCH * NH * T_SEQ];
__device__ float g_sk[BATCH * NKV * T_SEQ];

// ---------------------------------------------------------------------------
// 128x128x16 fp32 GEMM block: C[m,n] = sum_k A[m,k] * Wt[n,k]
// 256 threads, 8x8 micro-tile per thread.
// ---------------------------------------------------------------------------
__device__ __forceinline__ void gemm_block(const float* __restrict__ A,
                                           const float* __restrict__ Wt,
                                           float* __restrict__ Ct,
                                           int ldc) {
    const int K = 1024;
    __shared__ float As[16][132];
    __shared__ float Ws[16][132];

    int tid = threadIdx.x;
    int tx = tid & 15;        // n-direction (0..15)
    int ty = tid >> 4;        // m-direction (0..15)
    int m0 = blockIdx.x * 128;

    float acc[8][8];
#pragma unroll
    for (int i = 0; i < 8; i++)
#pragma unroll
        for (int j = 0; j < 8; j++) acc[i][j] = 0.f;

    const float* Ap = A + (size_t)m0 * K;

    for (int k0 = 0; k0 < K; k0 += 16) {
#pragma unroll
        for (int it = 0; it < 2; it++) {
            int r  = (tid >> 2) + it * 64;
            int kq = (tid & 3) << 2;
            float4 a = *(const float4*)(Ap + (size_t)r * K + k0 + kq);
            As[kq + 0][r] = a.x; As[kq + 1][r] = a.y;
            As[kq + 2][r] = a.z; As[kq + 3][r] = a.w;
            float4 w = *(const float4*)(Wt + (size_t)r * K + k0 + kq);
            Ws[kq + 0][r] = w.x; Ws[kq + 1][r] = w.y;
            Ws[kq + 2][r] = w.z; Ws[kq + 3][r] = w.w;
        }
        __syncthreads();
#pragma unroll
        for (int k = 0; k < 16; k++) {
            float af[8], wf[8];
            *(float4*)(af)     = *(const float4*)&As[k][ty * 8];
            *(float4*)(af + 4) = *(const float4*)&As[k][ty * 8 + 4];
            *(float4*)(wf)     = *(const float4*)&Ws[k][tx * 8];
            *(float4*)(wf + 4) = *(const float4*)&Ws[k][tx * 8 + 4];
#pragma unroll
            for (int i = 0; i < 8; i++)
#pragma unroll
                for (int j = 0; j < 8; j++)
                    acc[i][j] += af[i] * wf[j];
        }
        __syncthreads();
    }

#pragma unroll
    for (int i = 0; i < 8; i++) {
        float* crow = Ct + (size_t)(m0 + ty * 8 + i) * ldc + tx * 8;
        float4 v0 = make_float4(acc[i][0], acc[i][1], acc[i][2], acc[i][3]);
        float4 v1 = make_float4(acc[i][4], acc[i][5], acc[i][6], acc[i][7]);
        *(float4*)(crow)     = v0;
        *(float4*)(crow + 4) = v1;
    }
}

// Fused QKV GEMM: grid (32, 16). nb<8 -> Q cols, 8..11 -> K cols, 12..15 -> V.
__global__ void __launch_bounds__(256) qkv_gemm_k(const float* __restrict__ x,
                                                  const float* __restrict__ Wq,
                                                  const float* __restrict__ Wk,
                                                  const float* __restrict__ Wv) {
    int nb = blockIdx.y;
    if (nb < 8) {
        gemm_block(x, Wq + (size_t)nb * 128 * 1024, g_q + nb * 128, 1024);
    } else if (nb < 12) {
        gemm_block(x, Wk + (size_t)(nb - 8) * 128 * 1024, g_k + (nb - 8) * 128, 512);
    } else {
        gemm_block(x, Wv + (size_t)(nb - 12) * 128 * 1024, g_v + (nb - 12) * 128, 512);
    }
}

// Output projection: grid (32, 8)
__global__ void __launch_bounds__(256) proj_gemm_k(float* __restrict__ out,
                                                   const float* __restrict__ Wp) {
    gemm_block(g_y, Wp + (size_t)blockIdx.y * 128 * 1024, out + blockIdx.y * 128, 1024);
}

// ---------------------------------------------------------------------------
// RoPE + RMSNorm + braid dot. One warp per (b,t,h) row of 64. Only the scalar
// s = normalize(rope(row)) . w_braid is needed downstream; no writeback.
// ---------------------------------------------------------------------------
__device__ __forceinline__ void rope_rms_body(const float* __restrict__ src,
                                              const float* __restrict__ cosp,
                                              const float* __restrict__ sinp,
                                              const float* __restrict__ wb,
                                              float* __restrict__ sout,
                                              int nheads) {
    int warp = (blockIdx.x * blockDim.x + threadIdx.x) >> 5;
    int lane = threadIdx.x & 31;
    int total = BATCH * T_SEQ * nheads;
    if (warp >= total) return;
    int h  = warp % nheads;
    int bt = warp / nheads;
    int t  = bt % T_SEQ;
    int b  = bt / T_SEQ;

    const float* row = src + (size_t)warp * HD;
    float x1 = row[lane];
    float x2 = row[lane + 32];
    float c = cosp[t * 32 + lane];
    float s = sinp[t * 32 + lane];
    float o1 = x1 * c + x2 * s;
    float o2 = x2 * c - x1 * s;

    float ss = o1 * o1 + o2 * o2;
#pragma unroll
    for (int off = 16; off; off >>= 1)
        ss += __shfl_xor_sync(0xffffffffu, ss, off);
    float scale = rsqrtf(ss * (1.f / 64.f) + 1e-6f);

    float d = (o1 * wb[lane] + o2 * wb[lane + 32]) * scale;
#pragma unroll
    for (int off = 16; off; off >>= 1)
        d += __shfl_xor_sync(0xffffffffu, d, off);
    if (lane == 0)
        sout[((size_t)b * nheads + h) * T_SEQ + t] = d;
}

__global__ void __launch_bounds__(256) rope_q_k(const float* cosp, const float* sinp,
                                                const float* wb) {
    rope_rms_body(g_q, cosp, sinp, wb, g_sq, NH);
}
__global__ void __launch_bounds__(256) rope_k_k(const float* cosp, const float* sinp,
                                                const float* wb) {
    rope_rms_body(g_k, cosp, sinp, wb, g_sk, NKV);
}

// ---------------------------------------------------------------------------
// Attention: y[b,h,t,:] = scale * sum_{s<=t} sigmoid(sq[t]+sk[s]) * v[b,h/2,s,:]
// grid (T/64, NH, B). Block: 64 t-rows x 64 d-cols; 256 threads, 4 threads/row,
// each owning 16 interleaved columns (c0 + {0,16,32,48} + 0..3).
// ---------------------------------------------------------------------------
__global__ void __launch_bounds__(256) attn_k() {
    int tt = blockIdx.x;
    int h  = blockIdx.y;
    int b  = blockIdx.z;
    int kh = h >> 1;

    __shared__ float Vs[64][64];
    __shared__ float SKs[64];

    int tid = threadIdx.x;
    int row = tid >> 2;
    int c0  = (tid & 3) << 2;
    int t   = tt * 64 + row;

    float sq = g_sq[((size_t)b * NH + h) * T_SEQ + t];
    float acc[16];
#pragma unroll
    for (int i = 0; i < 16; i++) acc[i] = 0.f;

    const float* sk_base = g_sk + ((size_t)b * NKV + kh) * T_SEQ;

    for (int s0 = 0; s0 <= tt * 64; s0 += 64) {
        // Load V tile (64x64) coalesced
#pragma unroll
        for (int i = 0; i < 4; i++) {
            int idx = tid + i * 256;
            int r   = idx >> 4;
            int c   = (idx & 15) << 2;
            *(float4*)&Vs[r][c] =
                *(const float4*)&g_v[(((size_t)b * T_SEQ + s0 + r) * NKV + kh) * HD + c];
        }
        if (tid < 64) SKs[tid] = sk_base[s0 + tid];
        __syncthreads();

        if (s0 + 64 <= tt * 64) {  // full (strictly-causal) tile
#pragma unroll 2
            for (int s = 0; s < 64; s++) {
                float z = sq + SKs[s];
                float p = __fdividef(1.f, 1.f + __expf(-z));
#pragma unroll
                for (int j = 0; j < 4; j++) {
                    float4 v = *(const float4*)&Vs[s][c0 + j * 16];
                    acc[j * 4 + 0] += p * v.x;
                    acc[j * 4 + 1] += p * v.y;
                    acc[j * 4 + 2] += p * v.z;
                    acc[j * 4 + 3] += p * v.w;
                }
            }
        } else {  // diagonal tile: s <= row
            for (int s = 0; s <= row; s++) {
                float z = sq + SKs[s];
                float p = __fdividef(1.f, 1.f + __expf(-z));
#pragma unroll
                for (int j = 0; j < 4; j++) {
                    float4 v = *(const float4*)&Vs[s][c0 + j * 16];
                    acc[j * 4 + 0] += p * v.x;
                    acc[j * 4 + 1] += p * v.y;
                    acc[j * 4 + 2] += p * v.z;
                    acc[j * 4 + 3] += p * v.w;
                }
            }
        }
        __syncthreads();
    }

    const float inv = 1.f / (sqrtf((float)T_SEQ) + 1e-6f);
    float* yrow = g_y + (((size_t)b * T_SEQ + t) * NH + h) * HD;
#pragma unroll
    for (int j = 0; j < 4; j++) {
        float4 v = make_float4(acc[j * 4 + 0] * inv, acc[j * 4 + 1] * inv,
                               acc[j * 4 + 2] * inv, acc[j * 4 + 3] * inv);
        *(float4*)&yrow[c0 + j * 16] = v;
    }
}

// ---------------------------------------------------------------------------
extern "C" void kernel_launch(void* const* d_in, const int* in_sizes, int n_in,
                              void* d_out, int out_size) {
    const float* x    = (const float*)d_in[0];
    const float* cosp = (const float*)d_in[1];
    const float* sinp = (const float*)d_in[2];
    const float* Wq   = (const float*)d_in[3];
    const float* Wk   = (const float*)d_in[4];
    const float* Wv   = (const float*)d_in[5];
    const float* Wp   = (const float*)d_in[6];
    const float* wb   = (const float*)d_in[7];
    float* out = (float*)d_out;

    qkv_gemm_k<<<dim3(32, 16), 256>>>(x, Wq, Wk, Wv);

    // q rows: 2*2048*16 = 65536 warps -> 8192 blocks of 8 warps
    rope_q_k<<<8192, 256>>>(cosp, sinp, wb);
    // k rows: 2*2048*8 = 32768 warps -> 4096 blocks
    rope_k_k<<<4096, 256>>>(cosp, sinp, wb);

    attn_k<<<dim3(T_SEQ / 64, NH, BATCH), 256>>>();

    proj_gemm_k<<<dim3(32, 8), 256>>>(out, Wp);
}

// round 3
// speedup vs baseline: 1.4237x; 1.4237x over previous
#include <cuda_runtime.h>
#include <math.h>

#define BATCH 2
#define T_SEQ 2048
#define C_DIM 1024
#define NH 16
#define NKV 8
#define HD 64
#define M_ROWS (BATCH * T_SEQ)   // 4096

// Scratch (allocation-free rule: __device__ globals)
__device__ float g_q[M_ROWS * NH * HD];    // (b,t,h,d)  16 MB
__device__ float g_k[M_ROWS * NKV * HD];   //  8 MB
__device__ float g_v[M_ROWS * NKV * HD];   //  8 MB
__device__ float g_y[M_ROWS * NH * HD];    // (b,t,h,d)  16 MB
__device__ float g_sq[BATCH * NH * T_SEQ];
__device__ float g_sk[BATCH * NKV * T_SEQ];

// ---------------------------------------------------------------------------
// 128x128x16 fp32 GEMM block: C[m,n] = sum_k A[m,k] * Wt[n,k]
// 256 threads, 8x8 micro-tile per thread.  (unchanged from passing round 1)
// ---------------------------------------------------------------------------
__device__ __forceinline__ void gemm_block(const float* __restrict__ A,
                                           const float* __restrict__ Wt,
                                           float* __restrict__ Ct,
                                           int ldc) {
    const int K = 1024;
    __shared__ float As[16][132];
    __shared__ float Ws[16][132];

    int tid = threadIdx.x;
    int tx = tid & 15;        // n-direction (0..15)
    int ty = tid >> 4;        // m-direction (0..15)
    int m0 = blockIdx.x * 128;

    float acc[8][8];
#pragma unroll
    for (int i = 0; i < 8; i++)
#pragma unroll
        for (int j = 0; j < 8; j++) acc[i][j] = 0.f;

    const float* Ap = A + (size_t)m0 * K;

    for (int k0 = 0; k0 < K; k0 += 16) {
#pragma unroll
        for (int it = 0; it < 2; it++) {
            int r  = (tid >> 2) + it * 64;
            int kq = (tid & 3) << 2;
            float4 a = *(const float4*)(Ap + (size_t)r * K + k0 + kq);
            As[kq + 0][r] = a.x; As[kq + 1][r] = a.y;
            As[kq + 2][r] = a.z; As[kq + 3][r] = a.w;
            float4 w = *(const float4*)(Wt + (size_t)r * K + k0 + kq);
            Ws[kq + 0][r] = w.x; Ws[kq + 1][r] = w.y;
            Ws[kq + 2][r] = w.z; Ws[kq + 3][r] = w.w;
        }
        __syncthreads();
#pragma unroll
        for (int k = 0; k < 16; k++) {
            float af[8], wf[8];
            *(float4*)(af)     = *(const float4*)&As[k][ty * 8];
            *(float4*)(af + 4) = *(const float4*)&As[k][ty * 8 + 4];
            *(float4*)(wf)     = *(const float4*)&Ws[k][tx * 8];
            *(float4*)(wf + 4) = *(const float4*)&Ws[k][tx * 8 + 4];
#pragma unroll
            for (int i = 0; i < 8; i++)
#pragma unroll
                for (int j = 0; j < 8; j++)
                    acc[i][j] += af[i] * wf[j];
        }
        __syncthreads();
    }

#pragma unroll
    for (int i = 0; i < 8; i++) {
        float* crow = Ct + (size_t)(m0 + ty * 8 + i) * ldc + tx * 8;
        float4 v0 = make_float4(acc[i][0], acc[i][1], acc[i][2], acc[i][3]);
        float4 v1 = make_float4(acc[i][4], acc[i][5], acc[i][6], acc[i][7]);
        *(float4*)(crow)     = v0;
        *(float4*)(crow + 4) = v1;
    }
}

// Fused QKV GEMM: grid (32, 16). nb<8 -> Q cols, 8..11 -> K cols, 12..15 -> V.
__global__ void __launch_bounds__(256) qkv_gemm_k(const float* __restrict__ x,
                                                  const float* __restrict__ Wq,
                                                  const float* __restrict__ Wk,
                                                  const float* __restrict__ Wv) {
    int nb = blockIdx.y;
    if (nb < 8) {
        gemm_block(x, Wq + (size_t)nb * 128 * 1024, g_q + nb * 128, 1024);
    } else if (nb < 12) {
        gemm_block(x, Wk + (size_t)(nb - 8) * 128 * 1024, g_k + (nb - 8) * 128, 512);
    } else {
        gemm_block(x, Wv + (size_t)(nb - 12) * 128 * 1024, g_v + (nb - 12) * 128, 512);
    }
}

// Output projection: grid (32, 8)
__global__ void __launch_bounds__(256) proj_gemm_k(float* __restrict__ out,
                                                   const float* __restrict__ Wp) {
    gemm_block(g_y, Wp + (size_t)blockIdx.y * 128 * 1024, out + blockIdx.y * 128, 1024);
}

// ---------------------------------------------------------------------------
// RoPE + RMSNorm + braid dot. One warp per (b,t,h) row of 64.
// ---------------------------------------------------------------------------
__device__ __forceinline__ void rope_rms_body(const float* __restrict__ src,
                                              const float* __restrict__ cosp,
                                              const float* __restrict__ sinp,
                                              const float* __restrict__ wb,
                                              float* __restrict__ sout,
                                              int nheads) {
    int warp = (blockIdx.x * blockDim.x + threadIdx.x) >> 5;
    int lane = threadIdx.x & 31;
    int total = BATCH * T_SEQ * nheads;
    if (warp >= total) return;
    int h  = warp % nheads;
    int bt = warp / nheads;
    int t  = bt % T_SEQ;
    int b  = bt / T_SEQ;

    const float* row = src + (size_t)warp * HD;
    float x1 = row[lane];
    float x2 = row[lane + 32];
    float c = cosp[t * 32 + lane];
    float s = sinp[t * 32 + lane];
    float o1 = x1 * c + x2 * s;
    float o2 = x2 * c - x1 * s;

    float ss = o1 * o1 + o2 * o2;
#pragma unroll
    for (int off = 16; off; off >>= 1)
        ss += __shfl_xor_sync(0xffffffffu, ss, off);
    float scale = rsqrtf(ss * (1.f / 64.f) + 1e-6f);

    float d = (o1 * wb[lane] + o2 * wb[lane + 32]) * scale;
#pragma unroll
    for (int off = 16; off; off >>= 1)
        d += __shfl_xor_sync(0xffffffffu, d, off);
    if (lane == 0)
        sout[((size_t)b * nheads + h) * T_SEQ + t] = d;
}

__global__ void __launch_bounds__(256) rope_q_k(const float* cosp, const float* sinp,
                                                const float* wb) {
    rope_rms_body(g_q, cosp, sinp, wb, g_sq, NH);
}
__global__ void __launch_bounds__(256) rope_k_k(const float* cosp, const float* sinp,
                                                const float* wb) {
    rope_rms_body(g_k, cosp, sinp, wb, g_sk, NKV);
}

// ---------------------------------------------------------------------------
// Attention v3: P-tile GEMM with GQA sharing.
// One block: kv-head kh, both q-heads (2*kh, 2*kh+1), 64 t-rows, all 64 d.
// Output tile = 128 rows (head-major: row = hl*64 + tl) x 64 cols.
// 256 threads, micro-tile 8 rows x 4 cols (ty in [0,16) rows, tx in [0,16) cols).
// Per s-tile (32 wide): Ps[s][row] = sigmoid(sq[h][t]+sk[kh][s]) (masked),
// Vs[s][d] shared by both heads; then 128x64x32 GEMM from shared.
// ---------------------------------------------------------------------------
__global__ void __launch_bounds__(256) attn_k() {
    int tt = (T_SEQ / 64 - 1) - blockIdx.x;   // heavy tiles first
    int kh = blockIdx.y;
    int b  = blockIdx.z;
    int t0 = tt * 64;

    __shared__ float Ps[32][132];   // [s][row], row = hl*64 + tl
    __shared__ float Vs[32][68];    // [s][d]
    __shared__ float SQs[128];      // per-row braid-q scalar

    int tid = threadIdx.x;
    int tx  = tid & 15;             // col group: d = tx*4 .. tx*4+3
    int ty  = tid >> 4;             // row group: rows ty*8 .. ty*8+7

    if (tid < 128) {
        int hl = tid >> 6;
        int tl = tid & 63;
        SQs[tid] = g_sq[((size_t)b * NH + kh * 2 + hl) * T_SEQ + t0 + tl];
    }
    __syncthreads();

    float acc[8][4];
#pragma unroll
    for (int i = 0; i < 8; i++)
#pragma unroll
        for (int j = 0; j < 4; j++) acc[i][j] = 0.f;

    const float* sk_base = g_sk + ((size_t)b * NKV + kh) * T_SEQ;

    // P materialization mapping: ps = tid&31 (s within tile),
    // rows rq..rq+15 with rq = (tid>>5)*16.  STS.128 phases stride 132 floats
    // = 4 banks -> conflict-free.
    int ps = tid & 31;
    int rq = (tid >> 5) << 4;

    for (int s0 = 0; s0 < t0 + 64; s0 += 32) {
        // Load V tile (32 x 64) coalesced: 512 float4s, 2 per thread.
#pragma unroll
        for (int i = 0; i < 2; i++) {
            int idx = tid + i * 256;
            int r   = idx >> 4;
            int c   = (idx & 15) << 2;
            *(float4*)&Vs[r][c] =
                *(const float4*)&g_v[(((size_t)b * T_SEQ + s0 + r) * NKV + kh) * HD + c];
        }

        // Materialize P tile.
        {
            float skv = sk_base[s0 + ps];
            int   s   = s0 + ps;
            bool  partial = (s0 + 31 > t0);   // tile straddles the diagonal
#pragma unroll
            for (int j = 0; j < 16; j += 4) {
                float4 p4;
                float* pp = &p4.x;
#pragma unroll
                for (int u = 0; u < 4; u++) {
                    int row = rq + j + u;
                    float z = SQs[row] + skv;
                    float p = __fdividef(1.f, 1.f + __expf(-z));
                    if (partial && s > t0 + (row & 63)) p = 0.f;
                    pp[u] = p;
                }
                *(float4*)&Ps[ps][rq + j] = p4;
            }
        }
        __syncthreads();

        // 128x64x32 GEMM: acc[i][j] += Ps[k][ty*8+i] * Vs[k][tx*4+j]
#pragma unroll 8
        for (int k = 0; k < 32; k++) {
            float af[8], wf[4];
            *(float4*)(af)     = *(const float4*)&Ps[k][ty * 8];
            *(float4*)(af + 4) = *(const float4*)&Ps[k][ty * 8 + 4];
            *(float4*)(wf)     = *(const float4*)&Vs[k][tx * 4];
#pragma unroll
            for (int i = 0; i < 8; i++)
#pragma unroll
                for (int j = 0; j < 4; j++)
                    acc[i][j] += af[i] * wf[j];
        }
        __syncthreads();
    }

    const float inv = 1.f / (sqrtf((float)T_SEQ) + 1e-6f);
#pragma unroll
    for (int i = 0; i < 8; i++) {
        int row = ty * 8 + i;
        int hl  = row >> 6;
        int t   = t0 + (row & 63);
        float* yrow = g_y + (((size_t)b * T_SEQ + t) * NH + kh * 2 + hl) * HD + tx * 4;
        float4 v = make_float4(acc[i][0] * inv, acc[i][1] * inv,
                               acc[i][2] * inv, acc[i][3] * inv);
        *(float4*)yrow = v;
    }
}

// ---------------------------------------------------------------------------
extern "C" void kernel_launch(void* const* d_in, const int* in_sizes, int n_in,
                              void* d_out, int out_size) {
    const float* x    = (const float*)d_in[0];
    const float* cosp = (const float*)d_in[1];
    const float* sinp = (const float*)d_in[2];
    const float* Wq   = (const float*)d_in[3];
    const float* Wk   = (const float*)d_in[4];
    const float* Wv   = (const float*)d_in[5];
    const float* Wp   = (const float*)d_in[6];
    const float* wb   = (const float*)d_in[7];
    float* out = (float*)d_out;

    qkv_gemm_k<<<dim3(32, 16), 256>>>(x, Wq, Wk, Wv);

    rope_q_k<<<8192, 256>>>(cosp, sinp, wb);
    rope_k_k<<<4096, 256>>>(cosp, sinp, wb);

    attn_k<<<dim3(T_SEQ / 64, NKV, BATCH), 256>>>();

    proj_gemm_k<<<dim3(32, 8), 256>>>(out, Wp);
}

// round 5
// speedup vs baseline: 1.9841x; 1.3936x over previous
#include <cuda_runtime.h>
#include <cuda_bf16.h>
#include <math.h>
#include <stdint.h>

#define BATCH 2
#define T_SEQ 2048
#define C_DIM 1024
#define NH 16
#define NKV 8
#define HD 64
#define M_ROWS (BATCH * T_SEQ)   // 4096

// ---------------------------------------------------------------------------
// Scratch (__device__ globals; no allocation allowed)
// ---------------------------------------------------------------------------
__device__ float g_q[M_ROWS * NH * HD];
__device__ float g_k[M_ROWS * NKV * HD];
__device__ float g_v[M_ROWS * NKV * HD];
__device__ float g_y[M_ROWS * NH * HD];
__device__ float g_sq[BATCH * NH * T_SEQ];
__device__ float g_sk[BATCH * NKV * T_SEQ];

// split-precision bf16 copies
__device__ __nv_bfloat16 g_xh[M_ROWS * C_DIM];
__device__ __nv_bfloat16 g_xl[M_ROWS * C_DIM];
__device__ __nv_bfloat16 g_wh[2048 * C_DIM];   // rows: 0-1023 Wq, 1024-1535 Wk, 1536-2047 Wv
__device__ __nv_bfloat16 g_wl[2048 * C_DIM];
__device__ __nv_bfloat16 g_wph[C_DIM * C_DIM];
__device__ __nv_bfloat16 g_wpl[C_DIM * C_DIM];
__device__ __nv_bfloat16 g_yh[M_ROWS * C_DIM];
__device__ __nv_bfloat16 g_yl[M_ROWS * C_DIM];

// ---------------------------------------------------------------------------
// Warp-MMA helpers (plain sm_80-era PTX; works on non-'a' targets)
// ---------------------------------------------------------------------------
static __device__ __forceinline__ uint32_t s2u(const void* p) {
    uint32_t a;
    asm("{ .reg .u64 t; cvta.to.shared.u64 t, %1; cvt.u32.u64 %0, t; }"
        : "=r"(a) : "l"(p));
    return a;
}

static __device__ __forceinline__ void ldsm4(uint32_t* r, uint32_t addr) {
    asm volatile("ldmatrix.sync.aligned.m8n8.x4.shared.b16 {%0,%1,%2,%3}, [%4];"
                 : "=r"(r[0]), "=r"(r[1]), "=r"(r[2]), "=r"(r[3]) : "r"(addr));
}

static __device__ __forceinline__ void mma16816(float* c, const uint32_t* a,
                                                const uint32_t* b) {
    asm volatile(
        "mma.sync.aligned.m16n8k16.row.col.f32.bf16.bf16.f32 "
        "{%0,%1,%2,%3}, {%4,%5,%6,%7}, {%8,%9}, {%0,%1,%2,%3};"
        : "+f"(c[0]), "+f"(c[1]), "+f"(c[2]), "+f"(c[3])
        : "r"(a[0]), "r"(a[1]), "r"(a[2]), "r"(a[3]), "r"(b[0]), "r"(b[1]));
}

// ---------------------------------------------------------------------------
// Split fp32 -> bf16 hi + bf16 lo (residual)
// ---------------------------------------------------------------------------
static __device__ __forceinline__ void split_body(const float* __restrict__ src,
                                                  __nv_bfloat16* __restrict__ hi,
                                                  __nv_bfloat16* __restrict__ lo,
                                                  int n4) {
    int i = blockIdx.x * blockDim.x + threadIdx.x;
    if (i >= n4) return;
    float4 v = *(const float4*)(src + (size_t)i * 4);
    __nv_bfloat16 h0 = __float2bfloat16(v.x), h1 = __float2bfloat16(v.y);
    __nv_bfloat16 h2 = __float2bfloat16(v.z), h3 = __float2bfloat16(v.w);
    __nv_bfloat162 hh0 = {h0, h1}, hh1 = {h2, h3};
    *(__nv_bfloat162*)(hi + (size_t)i * 4)     = hh0;
    *(__nv_bfloat162*)(hi + (size_t)i * 4 + 2) = hh1;
    __nv_bfloat162 ll0 = {__float2bfloat16(v.x - __bfloat162float(h0)),
                          __float2bfloat16(v.y - __bfloat162float(h1))};
    __nv_bfloat162 ll1 = {__float2bfloat16(v.z - __bfloat162float(h2)),
                          __float2bfloat16(v.w - __bfloat162float(h3))};
    *(__nv_bfloat162*)(lo + (size_t)i * 4)     = ll0;
    *(__nv_bfloat162*)(lo + (size_t)i * 4 + 2) = ll1;
}

__global__ void __launch_bounds__(256) conv_x_k(const float* src) {
    split_body(src, g_xh, g_xl, M_ROWS * C_DIM / 4);
}
__global__ void __launch_bounds__(256) conv_wq_k(const float* src) {
    split_body(src, g_wh, g_wl, 1024 * 1024 / 4);
}
__global__ void __launch_bounds__(256) conv_wk_k(const float* src) {
    split_body(src, g_wh + 1024 * 1024, g_wl + 1024 * 1024, 512 * 1024 / 4);
}
__global__ void __launch_bounds__(256) conv_wv_k(const float* src) {
    split_body(src, g_wh + 1536 * 1024, g_wl + 1536 * 1024, 512 * 1024 / 4);
}
__global__ void __launch_bounds__(256) conv_wp_k(const float* src) {
    split_body(src, g_wph, g_wpl, 1024 * 1024 / 4);
}
__global__ void __launch_bounds__(256) conv_y_k() {
    split_body(g_y, g_yh, g_yl, M_ROWS * C_DIM / 4);
}

// ---------------------------------------------------------------------------
// Warp-MMA GEMM tile: C[128,128] = A[128,1024] * B[128,1024]^T, hi/lo split.
// 256 threads = 8 warps in a 4(M) x 2(N) grid; warp tile 32x64.
// K-chunk 32; smem tiles padded to 40 halves/row (conflict-free ldmatrix).
// ---------------------------------------------------------------------------
#define KC 32
#define LDT 40

static __device__ __forceinline__ void tc_gemm_tile(
    const __nv_bfloat16* __restrict__ Ah, const __nv_bfloat16* __restrict__ Al,
    const __nv_bfloat16* __restrict__ Bh, const __nv_bfloat16* __restrict__ Bl,
    int m0, float* __restrict__ C, int ldc, int ccol0) {

    __shared__ __nv_bfloat16 sAh[128][LDT], sAl[128][LDT];
    __shared__ __nv_bfloat16 sBh[128][LDT], sBl[128][LDT];

    int tid  = threadIdx.x;
    int wid  = tid >> 5;
    int lane = tid & 31;
    int wm   = wid >> 1;          // 0..3  (M)
    int wn   = wid & 1;           // 0..1  (N)

    float acc[2][8][4];
#pragma unroll
    for (int mi = 0; mi < 2; mi++)
#pragma unroll
        for (int nj = 0; nj < 8; nj++)
#pragma unroll
            for (int u = 0; u < 4; u++) acc[mi][nj][u] = 0.f;

    // ldmatrix base addresses
    uint32_t aA_h = s2u(&sAh[wm * 32 + (lane & 15)][(lane >> 4) * 8]);
    uint32_t aA_l = s2u(&sAl[wm * 32 + (lane & 15)][(lane >> 4) * 8]);
    int rB = wn * 64 + ((lane >> 3) & 1) * 8 + (lane & 7);
    int cB = (lane >> 4) * 8;
    uint32_t aB_h = s2u(&sBh[rB][cB]);
    uint32_t aB_l = s2u(&sBl[rB][cB]);

    // Global load mapping: per tile 512 uint4 (row = idx>>2, seg = idx&3)
    int r0 = tid >> 2, s0g = (tid & 3) * 8;
    int r1 = (tid + 256) >> 2, s1g = ((tid + 256) & 3) * 8;

    for (int k0 = 0; k0 < C_DIM; k0 += KC) {
        uint4 pf[8];
        {
            const __nv_bfloat16* a0 = Ah + (size_t)(m0 + r0) * C_DIM + k0 + s0g;
            const __nv_bfloat16* a1 = Ah + (size_t)(m0 + r1) * C_DIM + k0 + s1g;
            const __nv_bfloat16* b0 = Al + (size_t)(m0 + r0) * C_DIM + k0 + s0g;
            const __nv_bfloat16* b1 = Al + (size_t)(m0 + r1) * C_DIM + k0 + s1g;
            const __nv_bfloat16* c0 = Bh + (size_t)r0 * C_DIM + k0 + s0g;
            const __nv_bfloat16* c1 = Bh + (size_t)r1 * C_DIM + k0 + s1g;
            const __nv_bfloat16* d0 = Bl + (size_t)r0 * C_DIM + k0 + s0g;
            const __nv_bfloat16* d1 = Bl + (size_t)r1 * C_DIM + k0 + s1g;
            pf[0] = *(const uint4*)a0; pf[1] = *(const uint4*)a1;
            pf[2] = *(const uint4*)b0; pf[3] = *(const uint4*)b1;
            pf[4] = *(const uint4*)c0; pf[5] = *(const uint4*)c1;
            pf[6] = *(const uint4*)d0; pf[7] = *(const uint4*)d1;
        }
        __syncthreads();
        *(uint4*)&sAh[r0][s0g] = pf[0]; *(uint4*)&sAh[r1][s1g] = pf[1];
        *(uint4*)&sAl[r0][s0g] = pf[2]; *(uint4*)&sAl[r1][s1g] = pf[3];
        *(uint4*)&sBh[r0][s0g] = pf[4]; *(uint4*)&sBh[r1][s1g] = pf[5];
        *(uint4*)&sBl[r0][s0g] = pf[6]; *(uint4*)&sBl[r1][s1g] = pf[7];
        __syncthreads();

#pragma unroll
        for (int ks = 0; ks < 2; ks++) {
            uint32_t koff = ks * 32;   // 16 halves = 32 bytes
            uint32_t ah[2][4], al[2][4], b[4][4];
#pragma unroll
            for (int mi = 0; mi < 2; mi++) {
                ldsm4(ah[mi], aA_h + mi * 16 * (LDT * 2) + koff);
                ldsm4(al[mi], aA_l + mi * 16 * (LDT * 2) + koff);
            }
            // B hi: passes AhBh and AlBh
#pragma unroll
            for (int njp = 0; njp < 4; njp++)
                ldsm4(b[njp], aB_h + njp * 16 * (LDT * 2) + koff);
#pragma unroll
            for (int mi = 0; mi < 2; mi++)
#pragma unroll
                for (int njp = 0; njp < 4; njp++) {
                    uint32_t be[2] = {b[njp][0], b[njp][2]};
                    uint32_t bo[2] = {b[njp][1], b[njp][3]};
                    mma16816(acc[mi][2 * njp + 0], ah[mi], be);
                    mma16816(acc[mi][2 * njp + 1], ah[mi], bo);
                    mma16816(acc[mi][2 * njp + 0], al[mi], be);
                    mma16816(acc[mi][2 * njp + 1], al[mi], bo);
                }
            // B lo: pass AhBl
#pragma unroll
            for (int njp = 0; njp < 4; njp++)
                ldsm4(b[njp], aB_l + njp * 16 * (LDT * 2) + koff);
#pragma unroll
            for (int mi = 0; mi < 2; mi++)
#pragma unroll
                for (int njp = 0; njp < 4; njp++) {
                    uint32_t be[2] = {b[njp][0], b[njp][2]};
                    uint32_t bo[2] = {b[njp][1], b[njp][3]};
                    mma16816(acc[mi][2 * njp + 0], ah[mi], be);
                    mma16816(acc[mi][2 * njp + 1], ah[mi], bo);
                }
        }
    }

    // Epilogue: c0,c1 -> (row, col..col+1); c2,c3 -> (row+8, ...)
    int erow = wm * 32 + (lane >> 2);
    int ecol = wn * 64 + (lane & 3) * 2;
#pragma unroll
    for (int mi = 0; mi < 2; mi++)
#pragma unroll
        for (int nj = 0; nj < 8; nj++) {
            int row = erow + mi * 16;
            int col = ccol0 + ecol + nj * 8;
            float* p0 = C + (size_t)(m0 + row) * ldc + col;
            float* p1 = C + (size_t)(m0 + row + 8) * ldc + col;
            *(float2*)p0 = make_float2(acc[mi][nj][0], acc[mi][nj][1]);
            *(float2*)p1 = make_float2(acc[mi][nj][2], acc[mi][nj][3]);
        }
}

// QKV: grid (32, 16). nb<8 -> Q, 8..11 -> K, 12..15 -> V.
__global__ void __launch_bounds__(256) qkv_tc_k() {
    int mt = blockIdx.x, nb = blockIdx.y;
    int n0 = nb * 128;
    const __nv_bfloat16* Bh = g_wh + (size_t)n0 * C_DIM;
    const __nv_bfloat16* Bl = g_wl + (size_t)n0 * C_DIM;
    if (nb < 8)
        tc_gemm_tile(g_xh, g_xl, Bh, Bl, mt * 128, g_q, 1024, n0);
    else if (nb < 12)
        tc_gemm_tile(g_xh, g_xl, Bh, Bl, mt * 128, g_k, 512, n0 - 1024);
    else
        tc_gemm_tile(g_xh, g_xl, Bh, Bl, mt * 128, g_v, 512, n0 - 1536);
}

// Proj: grid (32, 8)
__global__ void __launch_bounds__(256) proj_tc_k(float* __restrict__ out) {
    int mt = blockIdx.x, nb = blockIdx.y;
    tc_gemm_tile(g_yh, g_yl, g_wph + (size_t)nb * 128 * C_DIM,
                 g_wpl + (size_t)nb * 128 * C_DIM, mt * 128, out, 1024, nb * 128);
}

// ---------------------------------------------------------------------------
// RoPE + RMSNorm + braid dot (unchanged, validated)
// ---------------------------------------------------------------------------
__device__ __forceinline__ void rope_rms_body(const float* __restrict__ src,
                                              const float* __restrict__ cosp,
                                              const float* __restrict__ sinp,
                                              const float* __restrict__ wb,
                                              float* __restrict__ sout,
                                              int nheads) {
    int warp = (blockIdx.x * blockDim.x + threadIdx.x) >> 5;
    int lane = threadIdx.x & 31;
    int total = BATCH * T_SEQ * nheads;
    if (warp >= total) return;
    int h  = warp % nheads;
    int bt = warp / nheads;
    int t  = bt % T_SEQ;
    int b  = bt / T_SEQ;

    const float* row = src + (size_t)warp * HD;
    float x1 = row[lane];
    float x2 = row[lane + 32];
    float c = cosp[t * 32 + lane];
    float s = sinp[t * 32 + lane];
    float o1 = x1 * c + x2 * s;
    float o2 = x2 * c - x1 * s;

    float ss = o1 * o1 + o2 * o2;
#pragma unroll
    for (int off = 16; off; off >>= 1)
        ss += __shfl_xor_sync(0xffffffffu, ss, off);
    float scale = rsqrtf(ss * (1.f / 64.f) + 1e-6f);

    float d = (o1 * wb[lane] + o2 * wb[lane + 32]) * scale;
#pragma unroll
    for (int off = 16; off; off >>= 1)
        d += __shfl_xor_sync(0xffffffffu, d, off);
    if (lane == 0)
        sout[((size_t)b * nheads + h) * T_SEQ + t] = d;
}

__global__ void __launch_bounds__(256) rope_q_k(const float* cosp, const float* sinp,
                                                const float* wb) {
    rope_rms_body(g_q, cosp, sinp, wb, g_sq, NH);
}
__global__ void __launch_bounds__(256) rope_k_k(const float* cosp, const float* sinp,
                                                const float* wb) {
    rope_rms_body(g_k, cosp, sinp, wb, g_sk, NKV);
}

// ---------------------------------------------------------------------------
// Attention (unchanged from round 3, validated)
// ---------------------------------------------------------------------------
__global__ void __launch_bounds__(256) attn_k() {
    int tt = (T_SEQ / 64 - 1) - blockIdx.x;
    int kh = blockIdx.y;
    int b  = blockIdx.z;
    int t0 = tt * 64;

    __shared__ float Ps[32][132];
    __shared__ float Vs[32][68];
    __shared__ float SQs[128];

    int tid = threadIdx.x;
    int tx  = tid & 15;
    int ty  = tid >> 4;

    if (tid < 128) {
        int hl = tid >> 6;
        int tl = tid & 63;
        SQs[tid] = g_sq[((size_t)b * NH + kh * 2 + hl) * T_SEQ + t0 + tl];
    }
    __syncthreads();

    float acc[8][4];
#pragma unroll
    for (int i = 0; i < 8; i++)
#pragma unroll
        for (int j = 0; j < 4; j++) acc[i][j] = 0.f;

    const float* sk_base = g_sk + ((size_t)b * NKV + kh) * T_SEQ;

    int ps = tid & 31;
    int rq = (tid >> 5) << 4;

    for (int s0 = 0; s0 < t0 + 64; s0 += 32) {
#pragma unroll
        for (int i = 0; i < 2; i++) {
            int idx = tid + i * 256;
            int r   = idx >> 4;
            int c   = (idx & 15) << 2;
            *(float4*)&Vs[r][c] =
                *(const float4*)&g_v[(((size_t)b * T_SEQ + s0 + r) * NKV + kh) * HD + c];
        }
        {
            float skv = sk_base[s0 + ps];
            int   s   = s0 + ps;
            bool  partial = (s0 + 31 > t0);
#pragma unroll
            for (int j = 0; j < 16; j += 4) {
                float4 p4;
                float* pp = &p4.x;
#pragma unroll
                for (int u = 0; u < 4; u++) {
                    int row = rq + j + u;
                    float z = SQs[row] + skv;
                    float p = __fdividef(1.f, 1.f + __expf(-z));
                    if (partial && s > t0 + (row & 63)) p = 0.f;
                    pp[u] = p;
                }
                *(float4*)&Ps[ps][rq + j] = p4;
            }
        }
        __syncthreads();

#pragma unroll 8
        for (int k = 0; k < 32; k++) {
            float af[8], wf[4];
            *(float4*)(af)     = *(const float4*)&Ps[k][ty * 8];
            *(float4*)(af + 4) = *(const float4*)&Ps[k][ty * 8 + 4];
            *(float4*)(wf)     = *(const float4*)&Vs[k][tx * 4];
#pragma unroll
            for (int i = 0; i < 8; i++)
#pragma unroll
                for (int j = 0; j < 4; j++)
                    acc[i][j] += af[i] * wf[j];
        }
        __syncthreads();
    }

    const float inv = 1.f / (sqrtf((float)T_SEQ) + 1e-6f);
#pragma unroll
    for (int i = 0; i < 8; i++) {
        int row = ty * 8 + i;
        int hl  = row >> 6;
        int t   = t0 + (row & 63);
        float* yrow = g_y + (((size_t)b * T_SEQ + t) * NH + kh * 2 + hl) * HD + tx * 4;
        float4 v = make_float4(acc[i][0] * inv, acc[i][1] * inv,
                               acc[i][2] * inv, acc[i][3] * inv);
        *(float4*)yrow = v;
    }
}

// ---------------------------------------------------------------------------
extern "C" void kernel_launch(void* const* d_in, const int* in_sizes, int n_in,
                              void* d_out, int out_size) {
    const float* x    = (const float*)d_in[0];
    const float* cosp = (const float*)d_in[1];
    const float* sinp = (const float*)d_in[2];
    const float* Wq   = (const float*)d_in[3];
    const float* Wk   = (const float*)d_in[4];
    const float* Wv   = (const float*)d_in[5];
    const float* Wp   = (const float*)d_in[6];
    const float* wb   = (const float*)d_in[7];
    float* out = (float*)d_out;

    conv_x_k<<<M_ROWS * C_DIM / 4 / 256, 256>>>(x);
    conv_wq_k<<<1024 * 1024 / 4 / 256, 256>>>(Wq);
    conv_wk_k<<<512 * 1024 / 4 / 256, 256>>>(Wk);
    conv_wv_k<<<512 * 1024 / 4 / 256, 256>>>(Wv);
    conv_wp_k<<<1024 * 1024 / 4 / 256, 256>>>(Wp);

    qkv_tc_k<<<dim3(32, 16), 256>>>();

    rope_q_k<<<8192, 256>>>(cosp, sinp, wb);
    rope_k_k<<<4096, 256>>>(cosp, sinp, wb);

    attn_k<<<dim3(T_SEQ / 64, NKV, BATCH), 256>>>();

    conv_y_k<<<M_ROWS * C_DIM / 4 / 256, 256>>>();
    proj_tc_k<<<dim3(32, 8), 256>>>(out);
}

// round 6
// speedup vs baseline: 2.1772x; 1.0973x over previous
#include <cuda_runtime.h>
#include <cuda_bf16.h>
#include <math.h>
#include <stdint.h>

#define BATCH 2
#define T_SEQ 2048
#define C_DIM 1024
#define NH 16
#define NKV 8
#define HD 64
#define M_ROWS (BATCH * T_SEQ)   // 4096

// ---------------------------------------------------------------------------
// Scratch (__device__ globals; no allocation allowed)
// ---------------------------------------------------------------------------
__device__ float g_q[M_ROWS * NH * HD];
__device__ float g_k[M_ROWS * NKV * HD];
__device__ float g_v[M_ROWS * NKV * HD];
__device__ float g_y[M_ROWS * NH * HD];
__device__ float g_sq[BATCH * NH * T_SEQ];
__device__ float g_sk[BATCH * NKV * T_SEQ];

__device__ __nv_bfloat16 g_xh[M_ROWS * C_DIM];
__device__ __nv_bfloat16 g_xl[M_ROWS * C_DIM];
__device__ __nv_bfloat16 g_wh[2048 * C_DIM];   // rows: 0-1023 Wq, 1024-1535 Wk, 1536-2047 Wv
__device__ __nv_bfloat16 g_wl[2048 * C_DIM];
__device__ __nv_bfloat16 g_wph[C_DIM * C_DIM];
__device__ __nv_bfloat16 g_wpl[C_DIM * C_DIM];
__device__ __nv_bfloat16 g_yh[M_ROWS * C_DIM];
__device__ __nv_bfloat16 g_yl[M_ROWS * C_DIM];

// ---------------------------------------------------------------------------
// PTX helpers (sm_80-era; valid on the non-'a' sm_103 target)
// ---------------------------------------------------------------------------
static __device__ __forceinline__ uint32_t s2u(const void* p) {
    uint32_t a;
    asm("{ .reg .u64 t; cvta.to.shared.u64 t, %1; cvt.u32.u64 %0, t; }"
        : "=r"(a) : "l"(p));
    return a;
}

static __device__ __forceinline__ void ldsm4(uint32_t* r, uint32_t addr) {
    asm volatile("ldmatrix.sync.aligned.m8n8.x4.shared.b16 {%0,%1,%2,%3}, [%4];"
                 : "=r"(r[0]), "=r"(r[1]), "=r"(r[2]), "=r"(r[3]) : "r"(addr));
}

static __device__ __forceinline__ void mma16816(float* c, const uint32_t* a,
                                                const uint32_t* b) {
    asm volatile(
        "mma.sync.aligned.m16n8k16.row.col.f32.bf16.bf16.f32 "
        "{%0,%1,%2,%3}, {%4,%5,%6,%7}, {%8,%9}, {%0,%1,%2,%3};"
        : "+f"(c[0]), "+f"(c[1]), "+f"(c[2]), "+f"(c[3])
        : "r"(a[0]), "r"(a[1]), "r"(a[2]), "r"(a[3]), "r"(b[0]), "r"(b[1]));
}

#define CP_ASYNC16(dst, src) \
    asm volatile("cp.async.cg.shared.global [%0], [%1], 16;" :: "r"(dst), "l"(src))
#define CP_COMMIT() asm volatile("cp.async.commit_group;" ::: "memory")
#define CP_WAIT1()  asm volatile("cp.async.wait_group 1;" ::: "memory")
#define CP_WAIT0()  asm volatile("cp.async.wait_group 0;" ::: "memory")

// ---------------------------------------------------------------------------
// Split fp32 -> bf16 hi + bf16 lo (residual)
// ---------------------------------------------------------------------------
static __device__ __forceinline__ void split_one(const float* __restrict__ src,
                                                 __nv_bfloat16* __restrict__ hi,
                                                 __nv_bfloat16* __restrict__ lo,
                                                 size_t i) {
    float4 v = *(const float4*)(src + i * 4);
    __nv_bfloat16 h0 = __float2bfloat16(v.x), h1 = __float2bfloat16(v.y);
    __nv_bfloat16 h2 = __float2bfloat16(v.z), h3 = __float2bfloat16(v.w);
    __nv_bfloat162 hh0 = {h0, h1}, hh1 = {h2, h3};
    *(__nv_bfloat162*)(hi + i * 4)     = hh0;
    *(__nv_bfloat162*)(hi + i * 4 + 2) = hh1;
    __nv_bfloat162 ll0 = {__float2bfloat16(v.x - __bfloat162float(h0)),
                          __float2bfloat16(v.y - __bfloat162float(h1))};
    __nv_bfloat162 ll1 = {__float2bfloat16(v.z - __bfloat162float(h2)),
                          __float2bfloat16(v.w - __bfloat162float(h3))};
    *(__nv_bfloat162*)(lo + i * 4)     = ll0;
    *(__nv_bfloat162*)(lo + i * 4 + 2) = ll1;
}

__global__ void __launch_bounds__(256) conv_x_k(const float* __restrict__ src) {
    int i = blockIdx.x * blockDim.x + threadIdx.x;
    split_one(src, g_xh, g_xl, i);
}
__global__ void __launch_bounds__(256) conv_y_k() {
    int i = blockIdx.x * blockDim.x + threadIdx.x;
    split_one(g_y, g_yh, g_yl, i);
}
// All QKV weights in one kernel: dest rows 0-1023 Wq, 1024-1535 Wk, 1536-2047 Wv
__global__ void __launch_bounds__(256) conv_w_k(const float* __restrict__ Wq,
                                                const float* __restrict__ Wk,
                                                const float* __restrict__ Wv) {
    int i = blockIdx.x * blockDim.x + threadIdx.x;  // float4 index, 0..524287
    const float* src;
    int rel;
    if (i < 262144)      { src = Wq; rel = i; }
    else if (i < 393216) { src = Wk; rel = i - 262144; }
    else                 { src = Wv; rel = i - 393216; }
    // split_one indexes src by rel but dest by i
    float4 v = *(const float4*)(src + (size_t)rel * 4);
    __nv_bfloat16 h0 = __float2bfloat16(v.x), h1 = __float2bfloat16(v.y);
    __nv_bfloat16 h2 = __float2bfloat16(v.z), h3 = __float2bfloat16(v.w);
    __nv_bfloat162 hh0 = {h0, h1}, hh1 = {h2, h3};
    *(__nv_bfloat162*)(g_wh + (size_t)i * 4)     = hh0;
    *(__nv_bfloat162*)(g_wh + (size_t)i * 4 + 2) = hh1;
    __nv_bfloat162 ll0 = {__float2bfloat16(v.x - __bfloat162float(h0)),
                          __float2bfloat16(v.y - __bfloat162float(h1))};
    __nv_bfloat162 ll1 = {__float2bfloat16(v.z - __bfloat162float(h2)),
                          __float2bfloat16(v.w - __bfloat162float(h3))};
    *(__nv_bfloat162*)(g_wl + (size_t)i * 4)     = ll0;
    *(__nv_bfloat162*)(g_wl + (size_t)i * 4 + 2) = ll1;
}
__global__ void __launch_bounds__(256) conv_wp_k(const float* __restrict__ src) {
    int i = blockIdx.x * blockDim.x + threadIdx.x;
    split_one(src, g_wph, g_wpl, i);
}

// ---------------------------------------------------------------------------
// cp.async double-buffered warp-MMA GEMM:
// C[128,128] = A[128,1024] * B[128,1024]^T, hi/lo split (3 passes).
// 8 warps (4M x 2N), warp tile 32x64, K-chunk 32, smem 2 x 4 x 128x40 bf16.
// ---------------------------------------------------------------------------
#define KC 32
#define LDT 40
#define TSB (128 * LDT * 2)     // tile bytes = 10240
#define BUFB (4 * TSB)          // one buffer (4 tiles) = 40960
#define GEMM_SMEM (2 * BUFB)    // 81920

static __device__ __forceinline__ void tc_gemm_tile(
    const __nv_bfloat16* __restrict__ Ah, const __nv_bfloat16* __restrict__ Al,
    const __nv_bfloat16* __restrict__ Bh, const __nv_bfloat16* __restrict__ Bl,
    int m0, float* __restrict__ C, int ldc, int ccol0) {

    extern __shared__ __nv_bfloat16 dsm[];
    uint32_t sbase = s2u(dsm);

    int tid  = threadIdx.x;
    int wid  = tid >> 5;
    int lane = tid & 31;
    int wm   = wid >> 1;
    int wn   = wid & 1;

    float acc[2][8][4];
#pragma unroll
    for (int mi = 0; mi < 2; mi++)
#pragma unroll
        for (int nj = 0; nj < 8; nj++)
#pragma unroll
            for (int u = 0; u < 4; u++) acc[mi][nj][u] = 0.f;

    // ldmatrix in-tile byte offsets
    uint32_t offA = (uint32_t)(wm * 32 + (lane & 15)) * (LDT * 2) + (lane >> 4) * 16;
    int rB = wn * 64 + ((lane >> 3) & 1) * 8 + (lane & 7);
    uint32_t offB = (uint32_t)rB * (LDT * 2) + (lane >> 4) * 16;

    // cp.async mapping: 512 16B segments per tile; 2 per thread per tile.
    int r0 = tid >> 2,          s0h = (tid & 3) * 8;
    int r1 = (tid + 256) >> 2,  s1h = ((tid + 256) & 3) * 8;
    uint32_t d0 = (uint32_t)r0 * (LDT * 2) + s0h * 2;
    uint32_t d1 = (uint32_t)r1 * (LDT * 2) + s1h * 2;

    const __nv_bfloat16* a0p = Ah + (size_t)(m0 + r0) * C_DIM + s0h;
    const __nv_bfloat16* a1p = Ah + (size_t)(m0 + r1) * C_DIM + s1h;
    const __nv_bfloat16* l0p = Al + (size_t)(m0 + r0) * C_DIM + s0h;
    const __nv_bfloat16* l1p = Al + (size_t)(m0 + r1) * C_DIM + s1h;
    const __nv_bfloat16* b0p = Bh + (size_t)r0 * C_DIM + s0h;
    const __nv_bfloat16* b1p = Bh + (size_t)r1 * C_DIM + s1h;
    const __nv_bfloat16* e0p = Bl + (size_t)r0 * C_DIM + s0h;
    const __nv_bfloat16* e1p = Bl + (size_t)r1 * C_DIM + s1h;

#define LOAD_CHUNK(k0, buf) do {                                               \
    uint32_t so = sbase + (buf) * BUFB;                                        \
    CP_ASYNC16(so + 0 * TSB + d0, a0p + (k0));                                 \
    CP_ASYNC16(so + 0 * TSB + d1, a1p + (k0));                                 \
    CP_ASYNC16(so + 1 * TSB + d0, l0p + (k0));                                 \
    CP_ASYNC16(so + 1 * TSB + d1, l1p + (k0));                                 \
    CP_ASYNC16(so + 2 * TSB + d0, b0p + (k0));                                 \
    CP_ASYNC16(so + 2 * TSB + d1, b1p + (k0));                                 \
    CP_ASYNC16(so + 3 * TSB + d0, e0p + (k0));                                 \
    CP_ASYNC16(so + 3 * TSB + d1, e1p + (k0));                                 \
} while (0)

    LOAD_CHUNK(0, 0);
    CP_COMMIT();

    const int NCH = C_DIM / KC;   // 32
    for (int ch = 0; ch < NCH; ch++) {
        int buf = ch & 1;
        if (ch + 1 < NCH) {
            LOAD_CHUNK((ch + 1) * KC, buf ^ 1);
            CP_COMMIT();
            CP_WAIT1();
        } else {
            CP_WAIT0();
        }
        __syncthreads();

        uint32_t so   = sbase + buf * BUFB;
        uint32_t aA_h = so + 0 * TSB + offA;
        uint32_t aA_l = so + 1 * TSB + offA;
        uint32_t aB_h = so + 2 * TSB + offB;
        uint32_t aB_l = so + 3 * TSB + offB;

#pragma unroll
        for (int ks = 0; ks < 2; ks++) {
            uint32_t koff = ks * 32;
            uint32_t ah[2][4], al[2][4], b[4][4];
#pragma unroll
            for (int mi = 0; mi < 2; mi++) {
                ldsm4(ah[mi], aA_h + mi * 16 * (LDT * 2) + koff);
                ldsm4(al[mi], aA_l + mi * 16 * (LDT * 2) + koff);
            }
#pragma unroll
            for (int njp = 0; njp < 4; njp++)
                ldsm4(b[njp], aB_h + njp * 16 * (LDT * 2) + koff);
#pragma unroll
            for (int mi = 0; mi < 2; mi++)
#pragma unroll
                for (int njp = 0; njp < 4; njp++) {
                    uint32_t be[2] = {b[njp][0], b[njp][2]};
                    uint32_t bo[2] = {b[njp][1], b[njp][3]};
                    mma16816(acc[mi][2 * njp + 0], ah[mi], be);
                    mma16816(acc[mi][2 * njp + 1], ah[mi], bo);
                    mma16816(acc[mi][2 * njp + 0], al[mi], be);
                    mma16816(acc[mi][2 * njp + 1], al[mi], bo);
                }
#pragma unroll
            for (int njp = 0; njp < 4; njp++)
                ldsm4(b[njp], aB_l + njp * 16 * (LDT * 2) + koff);
#pragma unroll
            for (int mi = 0; mi < 2; mi++)
#pragma unroll
                for (int njp = 0; njp < 4; njp++) {
                    uint32_t be[2] = {b[njp][0], b[njp][2]};
                    uint32_t bo[2] = {b[njp][1], b[njp][3]};
                    mma16816(acc[mi][2 * njp + 0], ah[mi], be);
                    mma16816(acc[mi][2 * njp + 1], ah[mi], bo);
                }
        }
        __syncthreads();
    }

    int erow = wm * 32 + (lane >> 2);
    int ecol = wn * 64 + (lane & 3) * 2;
#pragma unroll
    for (int mi = 0; mi < 2; mi++)
#pragma unroll
        for (int nj = 0; nj < 8; nj++) {
            int row = erow + mi * 16;
            int col = ccol0 + ecol + nj * 8;
            float* p0 = C + (size_t)(m0 + row) * ldc + col;
            float* p1 = C + (size_t)(m0 + row + 8) * ldc + col;
            *(float2*)p0 = make_float2(acc[mi][nj][0], acc[mi][nj][1]);
            *(float2*)p1 = make_float2(acc[mi][nj][2], acc[mi][nj][3]);
        }
}

__global__ void __launch_bounds__(256) qkv_tc_k() {
    int mt = blockIdx.x, nb = blockIdx.y;
    int n0 = nb * 128;
    const __nv_bfloat16* Bh = g_wh + (size_t)n0 * C_DIM;
    const __nv_bfloat16* Bl = g_wl + (size_t)n0 * C_DIM;
    if (nb < 8)
        tc_gemm_tile(g_xh, g_xl, Bh, Bl, mt * 128, g_q, 1024, n0);
    else if (nb < 12)
        tc_gemm_tile(g_xh, g_xl, Bh, Bl, mt * 128, g_k, 512, n0 - 1024);
    else
        tc_gemm_tile(g_xh, g_xl, Bh, Bl, mt * 128, g_v, 512, n0 - 1536);
}

__global__ void __launch_bounds__(256) proj_tc_k(float* __restrict__ out) {
    int mt = blockIdx.x, nb = blockIdx.y;
    tc_gemm_tile(g_yh, g_yl, g_wph + (size_t)nb * 128 * C_DIM,
                 g_wpl + (size_t)nb * 128 * C_DIM, mt * 128, out, 1024, nb * 128);
}

// ---------------------------------------------------------------------------
// RoPE + RMSNorm + braid dot, q and k merged into one launch.
// ---------------------------------------------------------------------------
__device__ __forceinline__ void rope_rms_warp(const float* __restrict__ src,
                                              const float* __restrict__ cosp,
                                              const float* __restrict__ sinp,
                                              const float* __restrict__ wb,
                                              float* __restrict__ sout,
                                              int nheads, int warp, int lane) {
    int h  = warp % nheads;
    int bt = warp / nheads;
    int t  = bt % T_SEQ;
    int b  = bt / T_SEQ;

    const float* row = src + (size_t)warp * HD;
    float x1 = row[lane];
    float x2 = row[lane + 32];
    float c = cosp[t * 32 + lane];
    float s = sinp[t * 32 + lane];
    float o1 = x1 * c + x2 * s;
    float o2 = x2 * c - x1 * s;

    float ss = o1 * o1 + o2 * o2;
#pragma unroll
    for (int off = 16; off; off >>= 1)
        ss += __shfl_xor_sync(0xffffffffu, ss, off);
    float scale = rsqrtf(ss * (1.f / 64.f) + 1e-6f);

    float d = (o1 * wb[lane] + o2 * wb[lane + 32]) * scale;
#pragma unroll
    for (int off = 16; off; off >>= 1)
        d += __shfl_xor_sync(0xffffffffu, d, off);
    if (lane == 0)
        sout[((size_t)b * nheads + h) * T_SEQ + t] = d;
}

__global__ void __launch_bounds__(256) rope_k(const float* cosp, const float* sinp,
                                              const float* wb) {
    int w    = (blockIdx.x * blockDim.x + threadIdx.x) >> 5;
    int lane = threadIdx.x & 31;
    const int NQ = BATCH * T_SEQ * NH;   // 65536
    if (w < NQ)
        rope_rms_warp(g_q, cosp, sinp, wb, g_sq, NH, w, lane);
    else
        rope_rms_warp(g_k, cosp, sinp, wb, g_sk, NKV, w - NQ, lane);
}

// ---------------------------------------------------------------------------
// Attention (validated round-3 version)
// ---------------------------------------------------------------------------
__global__ void __launch_bounds__(256) attn_k() {
    int tt = (T_SEQ / 64 - 1) - blockIdx.x;
    int kh = blockIdx.y;
    int b  = blockIdx.z;
    int t0 = tt * 64;

    __shared__ float Ps[32][132];
    __shared__ float Vs[32][68];
    __shared__ float SQs[128];

    int tid = threadIdx.x;
    int tx  = tid & 15;
    int ty  = tid >> 4;

    if (tid < 128) {
        int hl = tid >> 6;
        int tl = tid & 63;
        SQs[tid] = g_sq[((size_t)b * NH + kh * 2 + hl) * T_SEQ + t0 + tl];
    }
    __syncthreads();

    float acc[8][4];
#pragma unroll
    for (int i = 0; i < 8; i++)
#pragma unroll
        for (int j = 0; j < 4; j++) acc[i][j] = 0.f;

    const float* sk_base = g_sk + ((size_t)b * NKV + kh) * T_SEQ;

    int ps = tid & 31;
    int rq = (tid >> 5) << 4;

    for (int s0 = 0; s0 < t0 + 64; s0 += 32) {
#pragma unroll
        for (int i = 0; i < 2; i++) {
            int idx = tid + i * 256;
            int r   = idx >> 4;
            int c   = (idx & 15) << 2;
            *(float4*)&Vs[r][c] =
                *(const float4*)&g_v[(((size_t)b * T_SEQ + s0 + r) * NKV + kh) * HD + c];
        }
        {
            float skv = sk_base[s0 + ps];
            int   s   = s0 + ps;
            bool  partial = (s0 + 31 > t0);
#pragma unroll
            for (int j = 0; j < 16; j += 4) {
                float4 p4;
                float* pp = &p4.x;
#pragma unroll
                for (int u = 0; u < 4; u++) {
                    int row = rq + j + u;
                    float z = SQs[row] + skv;
                    float p = __fdividef(1.f, 1.f + __expf(-z));
                    if (partial && s > t0 + (row & 63)) p = 0.f;
                    pp[u] = p;
                }
                *(float4*)&Ps[ps][rq + j] = p4;
            }
        }
        __syncthreads();

#pragma unroll 8
        for (int k = 0; k < 32; k++) {
            float af[8], wf[4];
            *(float4*)(af)     = *(const float4*)&Ps[k][ty * 8];
            *(float4*)(af + 4) = *(const float4*)&Ps[k][ty * 8 + 4];
            *(float4*)(wf)     = *(const float4*)&Vs[k][tx * 4];
#pragma unroll
            for (int i = 0; i < 8; i++)
#pragma unroll
                for (int j = 0; j < 4; j++)
                    acc[i][j] += af[i] * wf[j];
        }
        __syncthreads();
    }

    const float inv = 1.f / (sqrtf((float)T_SEQ) + 1e-6f);
#pragma unroll
    for (int i = 0; i < 8; i++) {
        int row = ty * 8 + i;
        int hl  = row >> 6;
        int t   = t0 + (row & 63);
        float* yrow = g_y + (((size_t)b * T_SEQ + t) * NH + kh * 2 + hl) * HD + tx * 4;
        float4 v = make_float4(acc[i][0] * inv, acc[i][1] * inv,
                               acc[i][2] * inv, acc[i][3] * inv);
        *(float4*)yrow = v;
    }
}

// ---------------------------------------------------------------------------
extern "C" void kernel_launch(void* const* d_in, const int* in_sizes, int n_in,
                              void* d_out, int out_size) {
    const float* x    = (const float*)d_in[0];
    const float* cosp = (const float*)d_in[1];
    const float* sinp = (const float*)d_in[2];
    const float* Wq   = (const float*)d_in[3];
    const float* Wk   = (const float*)d_in[4];
    const float* Wv   = (const float*)d_in[5];
    const float* Wp   = (const float*)d_in[6];
    const float* wb   = (const float*)d_in[7];
    float* out = (float*)d_out;

    cudaFuncSetAttribute(qkv_tc_k,  cudaFuncAttributeMaxDynamicSharedMemorySize, GEMM_SMEM);
    cudaFuncSetAttribute(proj_tc_k, cudaFuncAttributeMaxDynamicSharedMemorySize, GEMM_SMEM);

    conv_x_k<<<M_ROWS * C_DIM / 4 / 256, 256>>>(x);
    conv_w_k<<<2048 * 1024 / 4 / 256, 256>>>(Wq, Wk, Wv);
    conv_wp_k<<<1024 * 1024 / 4 / 256, 256>>>(Wp);

    qkv_tc_k<<<dim3(32, 16), 256, GEMM_SMEM>>>();

    rope_k<<<(65536 + 32768) / 8, 256>>>(cosp, sinp, wb);

    attn_k<<<dim3(T_SEQ / 64, NKV, BATCH), 256>>>();

    conv_y_k<<<M_ROWS * C_DIM / 4 / 256, 256>>>();
    proj_tc_k<<<dim3(32, 8), 256, GEMM_SMEM>>>(out);
}

// round 7
// speedup vs baseline: 2.8667x; 1.3167x over previous
#include <cuda_runtime.h>
#include <cuda_bf16.h>
#include <math.h>
#include <stdint.h>

#define BATCH 2
#define T_SEQ 2048
#define C_DIM 1024
#define NH 16
#define NKV 8
#define HD 64
#define M_ROWS (BATCH * T_SEQ)   // 4096

// ---------------------------------------------------------------------------
// Scratch (__device__ globals)
// ---------------------------------------------------------------------------
__device__ float g_q[M_ROWS * NH * HD];
__device__ float g_k[M_ROWS * NKV * HD];
__device__ float g_v[M_ROWS * NKV * HD];
__device__ float g_sq[BATCH * NH * T_SEQ];
__device__ float g_sk[BATCH * NKV * T_SEQ];

__device__ __nv_bfloat16 g_xh[M_ROWS * C_DIM];
__device__ __nv_bfloat16 g_xl[M_ROWS * C_DIM];
__device__ __nv_bfloat16 g_wh[2048 * C_DIM];
__device__ __nv_bfloat16 g_wl[2048 * C_DIM];
__device__ __nv_bfloat16 g_wph[C_DIM * C_DIM];
__device__ __nv_bfloat16 g_wpl[C_DIM * C_DIM];
__device__ __nv_bfloat16 g_yh[M_ROWS * C_DIM];
__device__ __nv_bfloat16 g_yl[M_ROWS * C_DIM];
// V transposed + split: [b][kh][d][t]
__device__ __nv_bfloat16 g_vth[BATCH * NKV * HD * T_SEQ];
__device__ __nv_bfloat16 g_vtl[BATCH * NKV * HD * T_SEQ];

// ---------------------------------------------------------------------------
// PTX helpers (sm_80-era)
// ---------------------------------------------------------------------------
static __device__ __forceinline__ uint32_t s2u(const void* p) {
    uint32_t a;
    asm("{ .reg .u64 t; cvta.to.shared.u64 t, %1; cvt.u32.u64 %0, t; }"
        : "=r"(a) : "l"(p));
    return a;
}
static __device__ __forceinline__ void ldsm4(uint32_t* r, uint32_t addr) {
    asm volatile("ldmatrix.sync.aligned.m8n8.x4.shared.b16 {%0,%1,%2,%3}, [%4];"
                 : "=r"(r[0]), "=r"(r[1]), "=r"(r[2]), "=r"(r[3]) : "r"(addr));
}
static __device__ __forceinline__ void mma16816(float* c, const uint32_t* a,
                                                const uint32_t* b) {
    asm volatile(
        "mma.sync.aligned.m16n8k16.row.col.f32.bf16.bf16.f32 "
        "{%0,%1,%2,%3}, {%4,%5,%6,%7}, {%8,%9}, {%0,%1,%2,%3};"
        : "+f"(c[0]), "+f"(c[1]), "+f"(c[2]), "+f"(c[3])
        : "r"(a[0]), "r"(a[1]), "r"(a[2]), "r"(a[3]), "r"(b[0]), "r"(b[1]));
}
#define CP_ASYNC16(dst, src) \
    asm volatile("cp.async.cg.shared.global [%0], [%1], 16;" :: "r"(dst), "l"(src))
#define CP_COMMIT() asm volatile("cp.async.commit_group;" ::: "memory")
#define CP_WAIT1()  asm volatile("cp.async.wait_group 1;" ::: "memory")
#define CP_WAIT0()  asm volatile("cp.async.wait_group 0;" ::: "memory")

// ---------------------------------------------------------------------------
// Split fp32 -> bf16 hi + lo
// ---------------------------------------------------------------------------
static __device__ __forceinline__ void split_one(const float* __restrict__ src,
                                                 __nv_bfloat16* __restrict__ hi,
                                                 __nv_bfloat16* __restrict__ lo,
                                                 size_t i) {
    float4 v = *(const float4*)(src + i * 4);
    __nv_bfloat16 h0 = __float2bfloat16(v.x), h1 = __float2bfloat16(v.y);
    __nv_bfloat16 h2 = __float2bfloat16(v.z), h3 = __float2bfloat16(v.w);
    __nv_bfloat162 hh0 = {h0, h1}, hh1 = {h2, h3};
    *(__nv_bfloat162*)(hi + i * 4)     = hh0;
    *(__nv_bfloat162*)(hi + i * 4 + 2) = hh1;
    __nv_bfloat162 ll0 = {__float2bfloat16(v.x - __bfloat162float(h0)),
                          __float2bfloat16(v.y - __bfloat162float(h1))};
    __nv_bfloat162 ll1 = {__float2bfloat16(v.z - __bfloat162float(h2)),
                          __float2bfloat16(v.w - __bfloat162float(h3))};
    *(__nv_bfloat162*)(lo + i * 4)     = ll0;
    *(__nv_bfloat162*)(lo + i * 4 + 2) = ll1;
}

__global__ void __launch_bounds__(256) conv_x_k(const float* __restrict__ src) {
    int i = blockIdx.x * blockDim.x + threadIdx.x;
    split_one(src, g_xh, g_xl, i);
}
__global__ void __launch_bounds__(256) conv_w_k(const float* __restrict__ Wq,
                                                const float* __restrict__ Wk,
                                                const float* __restrict__ Wv) {
    int i = blockIdx.x * blockDim.x + threadIdx.x;
    const float* src;
    int rel;
    if (i < 262144)      { src = Wq; rel = i; }
    else if (i < 393216) { src = Wk; rel = i - 262144; }
    else                 { src = Wv; rel = i - 393216; }
    float4 v = *(const float4*)(src + (size_t)rel * 4);
    __nv_bfloat16 h0 = __float2bfloat16(v.x), h1 = __float2bfloat16(v.y);
    __nv_bfloat16 h2 = __float2bfloat16(v.z), h3 = __float2bfloat16(v.w);
    __nv_bfloat162 hh0 = {h0, h1}, hh1 = {h2, h3};
    *(__nv_bfloat162*)(g_wh + (size_t)i * 4)     = hh0;
    *(__nv_bfloat162*)(g_wh + (size_t)i * 4 + 2) = hh1;
    __nv_bfloat162 ll0 = {__float2bfloat16(v.x - __bfloat162float(h0)),
                          __float2bfloat16(v.y - __bfloat162float(h1))};
    __nv_bfloat162 ll1 = {__float2bfloat16(v.z - __bfloat162float(h2)),
                          __float2bfloat16(v.w - __bfloat162float(h3))};
    *(__nv_bfloat162*)(g_wl + (size_t)i * 4)     = ll0;
    *(__nv_bfloat162*)(g_wl + (size_t)i * 4 + 2) = ll1;
}
__global__ void __launch_bounds__(256) conv_wp_k(const float* __restrict__ src) {
    int i = blockIdx.x * blockDim.x + threadIdx.x;
    split_one(src, g_wph, g_wpl, i);
}

// ---------------------------------------------------------------------------
// V transpose + split: g_v [b][t][kh][d] fp32 -> g_vth/g_vtl [b][kh][d][t] bf16
// grid (T/64, NKV, B), 256 threads, 64x64 tile via smem.
// ---------------------------------------------------------------------------
__global__ void __launch_bounds__(256) conv_vt_k() {
    __shared__ float tile[64][65];
    int tt = blockIdx.x, kh = blockIdx.y, b = blockIdx.z;
    int tid = threadIdx.x;
#pragma unroll
    for (int i = 0; i < 4; i++) {
        int idx = tid + i * 256;
        int r = idx >> 4, c = (idx & 15) * 4;
        float4 v = *(const float4*)&g_v[(((size_t)b * T_SEQ + tt * 64 + r) * NKV + kh) * HD + c];
        tile[r][c] = v.x; tile[r][c + 1] = v.y; tile[r][c + 2] = v.z; tile[r][c + 3] = v.w;
    }
    __syncthreads();
#pragma unroll
    for (int i = 0; i < 4; i++) {
        int idx = tid + i * 256;
        int d = idx >> 4, ts = (idx & 15) * 4;
        float x0 = tile[ts][d], x1 = tile[ts + 1][d], x2 = tile[ts + 2][d], x3 = tile[ts + 3][d];
        __nv_bfloat16 h0 = __float2bfloat16(x0), h1 = __float2bfloat16(x1);
        __nv_bfloat16 h2 = __float2bfloat16(x2), h3 = __float2bfloat16(x3);
        size_t o = (((size_t)b * NKV + kh) * HD + d) * T_SEQ + tt * 64 + ts;
        __nv_bfloat162 hh0 = {h0, h1}, hh1 = {h2, h3};
        *(__nv_bfloat162*)(g_vth + o)     = hh0;
        *(__nv_bfloat162*)(g_vth + o + 2) = hh1;
        __nv_bfloat162 ll0 = {__float2bfloat16(x0 - __bfloat162float(h0)),
                              __float2bfloat16(x1 - __bfloat162float(h1))};
        __nv_bfloat162 ll1 = {__float2bfloat16(x2 - __bfloat162float(h2)),
                              __float2bfloat16(x3 - __bfloat162float(h3))};
        *(__nv_bfloat162*)(g_vtl + o)     = ll0;
        *(__nv_bfloat162*)(g_vtl + o + 2) = ll1;
    }
}

// ---------------------------------------------------------------------------
// cp.async double-buffered GEMM (round-6 version + occupancy 2)
// ---------------------------------------------------------------------------
#define KC 32
#define LDT 40
#define TSB (128 * LDT * 2)
#define BUFB (4 * TSB)
#define GEMM_SMEM (2 * BUFB)

static __device__ __forceinline__ void tc_gemm_tile(
    const __nv_bfloat16* __restrict__ Ah, const __nv_bfloat16* __restrict__ Al,
    const __nv_bfloat16* __restrict__ Bh, const __nv_bfloat16* __restrict__ Bl,
    int m0, float* __restrict__ C, int ldc, int ccol0,
    __nv_bfloat16* __restrict__ Chs, __nv_bfloat16* __restrict__ Cls) {

    extern __shared__ __nv_bfloat16 dsm[];
    uint32_t sbase = s2u(dsm);

    int tid  = threadIdx.x;
    int wid  = tid >> 5;
    int lane = tid & 31;
    int wm   = wid >> 1;
    int wn   = wid & 1;

    float acc[2][8][4];
#pragma unroll
    for (int mi = 0; mi < 2; mi++)
#pragma unroll
        for (int nj = 0; nj < 8; nj++)
#pragma unroll
            for (int u = 0; u < 4; u++) acc[mi][nj][u] = 0.f;

    uint32_t offA = (uint32_t)(wm * 32 + (lane & 15)) * (LDT * 2) + (lane >> 4) * 16;
    int rB = wn * 64 + ((lane >> 3) & 1) * 8 + (lane & 7);
    uint32_t offB = (uint32_t)rB * (LDT * 2) + (lane >> 4) * 16;

    int r0 = tid >> 2,          s0h = (tid & 3) * 8;
    int r1 = (tid + 256) >> 2,  s1h = ((tid + 256) & 3) * 8;
    uint32_t d0 = (uint32_t)r0 * (LDT * 2) + s0h * 2;
    uint32_t d1 = (uint32_t)r1 * (LDT * 2) + s1h * 2;

    const __nv_bfloat16* a0p = Ah + (size_t)(m0 + r0) * C_DIM + s0h;
    const __nv_bfloat16* a1p = Ah + (size_t)(m0 + r1) * C_DIM + s1h;
    const __nv_bfloat16* l0p = Al + (size_t)(m0 + r0) * C_DIM + s0h;
    const __nv_bfloat16* l1p = Al + (size_t)(m0 + r1) * C_DIM + s1h;
    const __nv_bfloat16* b0p = Bh + (size_t)r0 * C_DIM + s0h;
    const __nv_bfloat16* b1p = Bh + (size_t)r1 * C_DIM + s1h;
    const __nv_bfloat16* e0p = Bl + (size_t)r0 * C_DIM + s0h;
    const __nv_bfloat16* e1p = Bl + (size_t)r1 * C_DIM + s1h;

#define LOAD_CHUNK(k0, buf) do {                                               \
    uint32_t so = sbase + (buf) * BUFB;                                        \
    CP_ASYNC16(so + 0 * TSB + d0, a0p + (k0));                                 \
    CP_ASYNC16(so + 0 * TSB + d1, a1p + (k0));                                 \
    CP_ASYNC16(so + 1 * TSB + d0, l0p + (k0));                                 \
    CP_ASYNC16(so + 1 * TSB + d1, l1p + (k0));                                 \
    CP_ASYNC16(so + 2 * TSB + d0, b0p + (k0));                                 \
    CP_ASYNC16(so + 2 * TSB + d1, b1p + (k0));                                 \
    CP_ASYNC16(so + 3 * TSB + d0, e0p + (k0));                                 \
    CP_ASYNC16(so + 3 * TSB + d1, e1p + (k0));                                 \
} while (0)

    LOAD_CHUNK(0, 0);
    CP_COMMIT();

    const int NCH = C_DIM / KC;
    for (int ch = 0; ch < NCH; ch++) {
        int buf = ch & 1;
        if (ch + 1 < NCH) {
            LOAD_CHUNK((ch + 1) * KC, buf ^ 1);
            CP_COMMIT();
            CP_WAIT1();
        } else {
            CP_WAIT0();
        }
        __syncthreads();

        uint32_t so   = sbase + buf * BUFB;
        uint32_t aA_h = so + 0 * TSB + offA;
        uint32_t aA_l = so + 1 * TSB + offA;
        uint32_t aB_h = so + 2 * TSB + offB;
        uint32_t aB_l = so + 3 * TSB + offB;

#pragma unroll
        for (int ks = 0; ks < 2; ks++) {
            uint32_t koff = ks * 32;
            uint32_t ah[2][4], al[2][4], b[4][4];
#pragma unroll
            for (int mi = 0; mi < 2; mi++) {
                ldsm4(ah[mi], aA_h + mi * 16 * (LDT * 2) + koff);
                ldsm4(al[mi], aA_l + mi * 16 * (LDT * 2) + koff);
            }
#pragma unroll
            for (int njp = 0; njp < 4; njp++)
                ldsm4(b[njp], aB_h + njp * 16 * (LDT * 2) + koff);
#pragma unroll
            for (int mi = 0; mi < 2; mi++)
#pragma unroll
                for (int njp = 0; njp < 4; njp++) {
                    uint32_t be[2] = {b[njp][0], b[njp][2]};
                    uint32_t bo[2] = {b[njp][1], b[njp][3]};
                    mma16816(acc[mi][2 * njp + 0], ah[mi], be);
                    mma16816(acc[mi][2 * njp + 1], ah[mi], bo);
                    mma16816(acc[mi][2 * njp + 0], al[mi], be);
                    mma16816(acc[mi][2 * njp + 1], al[mi], bo);
                }
#pragma unroll
            for (int njp = 0; njp < 4; njp++)
                ldsm4(b[njp], aB_l + njp * 16 * (LDT * 2) + koff);
#pragma unroll
            for (int mi = 0; mi < 2; mi++)
#pragma unroll
                for (int njp = 0; njp < 4; njp++) {
                    uint32_t be[2] = {b[njp][0], b[njp][2]};
                    uint32_t bo[2] = {b[njp][1], b[njp][3]};
                    mma16816(acc[mi][2 * njp + 0], ah[mi], be);
                    mma16816(acc[mi][2 * njp + 1], ah[mi], bo);
                }
        }
        __syncthreads();
    }

    int erow = wm * 32 + (lane >> 2);
    int ecol = wn * 64 + (lane & 3) * 2;
#pragma unroll
    for (int mi = 0; mi < 2; mi++)
#pragma unroll
        for (int nj = 0; nj < 8; nj++) {
            int row = erow + mi * 16;
            int col = ccol0 + ecol + nj * 8;
            float* p0 = C + (size_t)(m0 + row) * ldc + col;
            float* p1 = C + (size_t)(m0 + row + 8) * ldc + col;
            *(float2*)p0 = make_float2(acc[mi][nj][0], acc[mi][nj][1]);
            *(float2*)p1 = make_float2(acc[mi][nj][2], acc[mi][nj][3]);
        }
    (void)Chs; (void)Cls;
}

__global__ void __launch_bounds__(256, 2) qkv_tc_k() {
    int mt = blockIdx.x, nb = blockIdx.y;
    int n0 = nb * 128;
    const __nv_bfloat16* Bh = g_wh + (size_t)n0 * C_DIM;
    const __nv_bfloat16* Bl = g_wl + (size_t)n0 * C_DIM;
    if (nb < 8)
        tc_gemm_tile(g_xh, g_xl, Bh, Bl, mt * 128, g_q, 1024, n0, 0, 0);
    else if (nb < 12)
        tc_gemm_tile(g_xh, g_xl, Bh, Bl, mt * 128, g_k, 512, n0 - 1024, 0, 0);
    else
        tc_gemm_tile(g_xh, g_xl, Bh, Bl, mt * 128, g_v, 512, n0 - 1536, 0, 0);
}

__global__ void __launch_bounds__(256, 2) proj_tc_k(float* __restrict__ out) {
    int mt = blockIdx.x, nb = blockIdx.y;
    tc_gemm_tile(g_yh, g_yl, g_wph + (size_t)nb * 128 * C_DIM,
                 g_wpl + (size_t)nb * 128 * C_DIM, mt * 128, out, 1024, nb * 128, 0, 0);
}

// ---------------------------------------------------------------------------
// RoPE + RMSNorm + braid dot (merged q/k launch)
// ---------------------------------------------------------------------------
__device__ __forceinline__ void rope_rms_warp(const float* __restrict__ src,
                                              const float* __restrict__ cosp,
                                              const float* __restrict__ sinp,
                                              const float* __restrict__ wb,
                                              float* __restrict__ sout,
                                              int nheads, int warp, int lane) {
    int h  = warp % nheads;
    int bt = warp / nheads;
    int t  = bt % T_SEQ;
    int b  = bt / T_SEQ;

    const float* row = src + (size_t)warp * HD;
    float x1 = row[lane];
    float x2 = row[lane + 32];
    float c = cosp[t * 32 + lane];
    float s = sinp[t * 32 + lane];
    float o1 = x1 * c + x2 * s;
    float o2 = x2 * c - x1 * s;

    float ss = o1 * o1 + o2 * o2;
#pragma unroll
    for (int off = 16; off; off >>= 1)
        ss += __shfl_xor_sync(0xffffffffu, ss, off);
    float scale = rsqrtf(ss * (1.f / 64.f) + 1e-6f);

    float d = (o1 * wb[lane] + o2 * wb[lane + 32]) * scale;
#pragma unroll
    for (int off = 16; off; off >>= 1)
        d += __shfl_xor_sync(0xffffffffu, d, off);
    if (lane == 0)
        sout[((size_t)b * nheads + h) * T_SEQ + t] = d;
}

__global__ void __launch_bounds__(256) rope_k(const float* cosp, const float* sinp,
                                              const float* wb) {
    int w    = (blockIdx.x * blockDim.x + threadIdx.x) >> 5;
    int lane = threadIdx.x & 31;
    const int NQ = BATCH * T_SEQ * NH;
    if (w < NQ)
        rope_rms_warp(g_q, cosp, sinp, wb, g_sq, NH, w, lane);
    else
        rope_rms_warp(g_k, cosp, sinp, wb, g_sk, NKV, w - NQ, lane);
}

// ---------------------------------------------------------------------------
// Attention on tensor cores.
// Block: (t-tile 64, kv-head, batch). 8 warps, warp tile m16 x n64.
// M rows 0..127 head-major (rows 0-63 head 2kh, 64-127 head 2kh+1).
// A fragment P = sigmoid(sq+sk) computed in registers (hi/lo bf16 split);
// B = V^T tiles [d][s] from g_vth/g_vtl via ldmatrix; K loop over s chunks of 64.
// Epilogue writes y directly as bf16 hi/lo (proj input).
// ---------------------------------------------------------------------------
#define ALDS 72                        // halves per Vs row
#define AVROW (ALDS * 2)               // 144 bytes
#define AVBUF (64 * AVROW)             // one V tile: 9216 bytes

static __device__ __forceinline__ float sigp(float z) {
    return __fdividef(1.f, 1.f + __expf(-z));
}

__global__ void __launch_bounds__(256, 2) attn_tc_k() {
    __shared__ __nv_bfloat16 Vh[2][64][ALDS];
    __shared__ __nv_bfloat16 Vl[2][64][ALDS];
    __shared__ float SQ[128];
    __shared__ float SK[2][64];

    int tt = (T_SEQ / 64 - 1) - blockIdx.x;
    int kh = blockIdx.y;
    int b  = blockIdx.z;
    int t0 = tt * 64;

    int tid  = threadIdx.x;
    int wid  = tid >> 5;
    int lane = tid & 31;

    if (tid < 128) {
        int hl = tid >> 6, tl = tid & 63;
        SQ[tid] = g_sq[((size_t)b * NH + kh * 2 + hl) * T_SEQ + t0 + tl];
    }

    const __nv_bfloat16* gvh = g_vth + ((size_t)b * NKV + kh) * HD * T_SEQ;
    const __nv_bfloat16* gvl = g_vtl + ((size_t)b * NKV + kh) * HD * T_SEQ;
    const float* gsk = g_sk + ((size_t)b * NKV + kh) * T_SEQ;

    uint32_t sVh = s2u(Vh), sVl = s2u(Vl), sSK = s2u(SK);

    // cp.async mapping: V tile 64 d-rows x 64 halves; 512 16B segs, 2/thread.
    int vr0 = tid >> 3,         vs0 = (tid & 7) * 8;
    int vr1 = (tid + 256) >> 3, vs1 = ((tid + 256) & 7) * 8;
    uint32_t vd0 = (uint32_t)vr0 * AVROW + vs0 * 2;
    uint32_t vd1 = (uint32_t)vr1 * AVROW + vs1 * 2;

#define AV_LOAD(s0, buf) do {                                                  \
    uint32_t bo = (buf) * AVBUF;                                               \
    CP_ASYNC16(sVh + bo + vd0, gvh + (size_t)vr0 * T_SEQ + (s0) + vs0);        \
    CP_ASYNC16(sVh + bo + vd1, gvh + (size_t)vr1 * T_SEQ + (s0) + vs1);        \
    CP_ASYNC16(sVl + bo + vd0, gvl + (size_t)vr0 * T_SEQ + (s0) + vs0);        \
    CP_ASYNC16(sVl + bo + vd1, gvl + (size_t)vr1 * T_SEQ + (s0) + vs1);        \
    if (tid < 16) CP_ASYNC16(sSK + (buf) * 256 + tid * 16, gsk + (s0) + tid * 4); \
} while (0)

    float acc[8][4];
#pragma unroll
    for (int nj = 0; nj < 8; nj++)
#pragma unroll
        for (int u = 0; u < 4; u++) acc[nj][u] = 0.f;

    int r  = lane >> 2;           // 0..7
    int c2 = (lane & 3) * 2;      // 0,2,4,6
    int row0 = wid * 16 + r;      // rows row0, row0+8
    int tl0 = row0 & 63, tl1 = (row0 + 8) & 63;

    // ldmatrix B offsets: rB within n16 block, cB = k-halves offset
    int rB = ((lane >> 3) & 1) * 8 + (lane & 7);
    uint32_t offB = (uint32_t)rB * AVROW + (lane >> 4) * 16;

    AV_LOAD(0, 0);
    CP_COMMIT();
    __syncthreads();   // SQ visible

    float sq0 = SQ[row0], sq1 = SQ[row0 + 8];

    const int NCH = tt + 1;
    for (int ch = 0; ch < NCH; ch++) {
        int buf = ch & 1;
        if (ch + 1 < NCH) {
            AV_LOAD((ch + 1) * 64, buf ^ 1);
            CP_COMMIT();
            CP_WAIT1();
        } else {
            CP_WAIT0();
        }
        __syncthreads();

        bool diag = (ch == tt);
        const float* SKb = SK[buf];
        uint32_t vbh = sVh + buf * AVBUF + offB;
        uint32_t vbl = sVl + buf * AVBUF + offB;

#pragma unroll 2
        for (int ks = 0; ks < 4; ks++) {
            int kb = ks * 16 + c2;
            float sk0 = SKb[kb], sk1 = SKb[kb + 1];
            float sk8 = SKb[kb + 8], sk9 = SKb[kb + 9];

            float p00 = sigp(sq0 + sk0), p01 = sigp(sq0 + sk1);
            float p08 = sigp(sq0 + sk8), p09 = sigp(sq0 + sk9);
            float p10 = sigp(sq1 + sk0), p11 = sigp(sq1 + sk1);
            float p18 = sigp(sq1 + sk8), p19 = sigp(sq1 + sk9);
            if (diag) {
                if (kb > tl0)     p00 = 0.f;
                if (kb + 1 > tl0) p01 = 0.f;
                if (kb + 8 > tl0) p08 = 0.f;
                if (kb + 9 > tl0) p09 = 0.f;
                if (kb > tl1)     p10 = 0.f;
                if (kb + 1 > tl1) p11 = 0.f;
                if (kb + 8 > tl1) p18 = 0.f;
                if (kb + 9 > tl1) p19 = 0.f;
            }
            uint32_t ah[4], al[4];
            {
                __nv_bfloat16 h;
                __nv_bfloat162 t2;
                float q[8] = {p00, p01, p10, p11, p08, p09, p18, p19};
                float lres[8];
#pragma unroll
                for (int u = 0; u < 8; u += 2) {
                    __nv_bfloat16 ha = __float2bfloat16(q[u]);
                    __nv_bfloat16 hb = __float2bfloat16(q[u + 1]);
                    lres[u]     = q[u]     - __bfloat162float(ha);
                    lres[u + 1] = q[u + 1] - __bfloat162float(hb);
                    t2.x = ha; t2.y = hb;
                    ah[u >> 1] = *(uint32_t*)&t2;
                }
#pragma unroll
                for (int u = 0; u < 8; u += 2) {
                    t2.x = __float2bfloat16(lres[u]);
                    t2.y = __float2bfloat16(lres[u + 1]);
                    al[u >> 1] = *(uint32_t*)&t2;
                }
                (void)h;
            }

            uint32_t bh[4][4];
#pragma unroll
            for (int njp = 0; njp < 4; njp++)
                ldsm4(bh[njp], vbh + njp * 16 * AVROW + ks * 32);
#pragma unroll
            for (int njp = 0; njp < 4; njp++) {
                uint32_t be[2] = {bh[njp][0], bh[njp][2]};
                uint32_t bo[2] = {bh[njp][1], bh[njp][3]};
                mma16816(acc[2 * njp + 0], ah, be);
                mma16816(acc[2 * njp + 1], ah, bo);
                mma16816(acc[2 * njp + 0], al, be);
                mma16816(acc[2 * njp + 1], al, bo);
            }
            uint32_t bl[4][4];
#pragma unroll
            for (int njp = 0; njp < 4; njp++)
                ldsm4(bl[njp], vbl + njp * 16 * AVROW + ks * 32);
#pragma unroll
            for (int njp = 0; njp < 4; njp++) {
                uint32_t be[2] = {bl[njp][0], bl[njp][2]};
                uint32_t bo[2] = {bl[njp][1], bl[njp][3]};
                mma16816(acc[2 * njp + 0], ah, be);
                mma16816(acc[2 * njp + 1], ah, bo);
            }
        }
        __syncthreads();
    }

    // Epilogue: y scaled + split to bf16 hi/lo, layout [b][t][h][d].
    const float inv = 1.f / (sqrtf((float)T_SEQ) + 1e-6f);
    int hgl = kh * 2 + (row0 >> 6);
    int tA = t0 + tl0, tB = t0 + tl1;
    __nv_bfloat16* yhA = g_yh + (((size_t)b * T_SEQ + tA) * NH + hgl) * HD;
    __nv_bfloat16* ylA = g_yl + (((size_t)b * T_SEQ + tA) * NH + hgl) * HD;
    __nv_bfloat16* yhB = g_yh + (((size_t)b * T_SEQ + tB) * NH + hgl) * HD;
    __nv_bfloat16* ylB = g_yl + (((size_t)b * T_SEQ + tB) * NH + hgl) * HD;
#pragma unroll
    for (int nj = 0; nj < 8; nj++) {
        int d = nj * 8 + c2;
        float v0 = acc[nj][0] * inv, v1 = acc[nj][1] * inv;
        __nv_bfloat16 h0 = __float2bfloat16(v0), h1 = __float2bfloat16(v1);
        __nv_bfloat162 hh = {h0, h1};
        __nv_bfloat162 ll = {__float2bfloat16(v0 - __bfloat162float(h0)),
                             __float2bfloat16(v1 - __bfloat162float(h1))};
        *(__nv_bfloat162*)(yhA + d) = hh;
        *(__nv_bfloat162*)(ylA + d) = ll;
        float v2 = acc[nj][2] * inv, v3 = acc[nj][3] * inv;
        __nv_bfloat16 h2 = __float2bfloat16(v2), h3 = __float2bfloat16(v3);
        __nv_bfloat162 hh2 = {h2, h3};
        __nv_bfloat162 ll2 = {__float2bfloat16(v2 - __bfloat162float(h2)),
                              __float2bfloat16(v3 - __bfloat162float(h3))};
        *(__nv_bfloat162*)(yhB + d) = hh2;
        *(__nv_bfloat162*)(ylB + d) = ll2;
    }
}

// ---------------------------------------------------------------------------
extern "C" void kernel_launch(void* const* d_in, const int* in_sizes, int n_in,
                              void* d_out, int out_size) {
    const float* x    = (const float*)d_in[0];
    const float* cosp = (const float*)d_in[1];
    const float* sinp = (const float*)d_in[2];
    const float* Wq   = (const float*)d_in[3];
    const float* Wk   = (const float*)d_in[4];
    const float* Wv   = (const float*)d_in[5];
    const float* Wp   = (const float*)d_in[6];
    const float* wb   = (const float*)d_in[7];
    float* out = (float*)d_out;

    cudaFuncSetAttribute(qkv_tc_k,  cudaFuncAttributeMaxDynamicSharedMemorySize, GEMM_SMEM);
    cudaFuncSetAttribute(proj_tc_k, cudaFuncAttributeMaxDynamicSharedMemorySize, GEMM_SMEM);

    conv_x_k<<<M_ROWS * C_DIM / 4 / 256, 256>>>(x);
    conv_w_k<<<2048 * 1024 / 4 / 256, 256>>>(Wq, Wk, Wv);
    conv_wp_k<<<1024 * 1024 / 4 / 256, 256>>>(Wp);

    qkv_tc_k<<<dim3(32, 16), 256, GEMM_SMEM>>>();

    rope_k<<<(65536 + 32768) / 8, 256>>>(cosp, sinp, wb);
    conv_vt_k<<<dim3(T_SEQ / 64, NKV, BATCH), 256>>>();

    attn_tc_k<<<dim3(T_SEQ / 64, NKV, BATCH), 256>>>();

    proj_tc_k<<<dim3(32, 8), 256, GEMM_SMEM>>>(out);
}

// round 8
// speedup vs baseline: 6.9304x; 2.4175x over previous
#include <cuda_runtime.h>
#include <cuda_fp16.h>
#include <math.h>
#include <stdint.h>

#define BATCH 2
#define T_SEQ 2048
#define C_DIM 1024
#define NH 16
#define NKV 8
#define HD 64
#define M_ROWS (BATCH * T_SEQ)   // 4096

// ---------------------------------------------------------------------------
// Scratch (__device__ globals)
// ---------------------------------------------------------------------------
__device__ float g_q[M_ROWS * NH * HD];
__device__ float g_k[M_ROWS * NKV * HD];
__device__ float g_v[M_ROWS * NKV * HD];
__device__ float g_sq[BATCH * NH * T_SEQ];
__device__ float g_sk[BATCH * NKV * T_SEQ];

__device__ __half g_xh[M_ROWS * C_DIM];
__device__ __half g_wh[2048 * C_DIM];     // 0-1023 Wq, 1024-1535 Wk, 1536-2047 Wv
__device__ __half g_wph[C_DIM * C_DIM];
__device__ __half g_yh[M_ROWS * C_DIM];   // attn output, [b][t][h][d]
__device__ __half g_vth[BATCH * NKV * HD * T_SEQ];  // V^T [b][kh][d][t]

// ---------------------------------------------------------------------------
// PTX helpers
// ---------------------------------------------------------------------------
static __device__ __forceinline__ uint32_t s2u(const void* p) {
    uint32_t a;
    asm("{ .reg .u64 t; cvta.to.shared.u64 t, %1; cvt.u32.u64 %0, t; }"
        : "=r"(a) : "l"(p));
    return a;
}
static __device__ __forceinline__ void ldsm4(uint32_t* r, uint32_t addr) {
    asm volatile("ldmatrix.sync.aligned.m8n8.x4.shared.b16 {%0,%1,%2,%3}, [%4];"
                 : "=r"(r[0]), "=r"(r[1]), "=r"(r[2]), "=r"(r[3]) : "r"(addr));
}
static __device__ __forceinline__ void mma16816h(float* c, const uint32_t* a,
                                                 const uint32_t* b) {
    asm volatile(
        "mma.sync.aligned.m16n8k16.row.col.f32.f16.f16.f32 "
        "{%0,%1,%2,%3}, {%4,%5,%6,%7}, {%8,%9}, {%0,%1,%2,%3};"
        : "+f"(c[0]), "+f"(c[1]), "+f"(c[2]), "+f"(c[3])
        : "r"(a[0]), "r"(a[1]), "r"(a[2]), "r"(a[3]), "r"(b[0]), "r"(b[1]));
}
static __device__ __forceinline__ uint32_t tanh2(uint32_t x) {
    uint32_t o;
    asm("tanh.approx.f16x2 %0, %1;" : "=r"(o) : "r"(x));
    return o;
}
#define CP_ASYNC16(dst, src) \
    asm volatile("cp.async.cg.shared.global [%0], [%1], 16;" :: "r"(dst), "l"(src))
#define CP_COMMIT() asm volatile("cp.async.commit_group;" ::: "memory")
#define CP_WAIT1()  asm volatile("cp.async.wait_group 1;" ::: "memory")
#define CP_WAIT0()  asm volatile("cp.async.wait_group 0;" ::: "memory")

// ---------------------------------------------------------------------------
// fp32 -> fp16 conversions
// ---------------------------------------------------------------------------
static __device__ __forceinline__ void cvt_one(const float* __restrict__ src,
                                               __half* __restrict__ dst, size_t i) {
    float4 v = *(const float4*)(src + i * 4);
    __half2 a = __floats2half2_rn(v.x, v.y);
    __half2 b = __floats2half2_rn(v.z, v.w);
    *(__half2*)(dst + i * 4)     = a;
    *(__half2*)(dst + i * 4 + 2) = b;
}
__global__ void __launch_bounds__(256) conv_x_k(const float* __restrict__ src) {
    int i = blockIdx.x * blockDim.x + threadIdx.x;
    cvt_one(src, g_xh, i);
}
__global__ void __launch_bounds__(256) conv_w_k(const float* __restrict__ Wq,
                                                const float* __restrict__ Wk,
                                                const float* __restrict__ Wv) {
    int i = blockIdx.x * blockDim.x + threadIdx.x;
    const float* src;
    int rel;
    if (i < 262144)      { src = Wq; rel = i; }
    else if (i < 393216) { src = Wk; rel = i - 262144; }
    else                 { src = Wv; rel = i - 393216; }
    float4 v = *(const float4*)(src + (size_t)rel * 4);
    __half2 a = __floats2half2_rn(v.x, v.y);
    __half2 b = __floats2half2_rn(v.z, v.w);
    *(__half2*)(g_wh + (size_t)i * 4)     = a;
    *(__half2*)(g_wh + (size_t)i * 4 + 2) = b;
}
__global__ void __launch_bounds__(256) conv_wp_k(const float* __restrict__ src) {
    int i = blockIdx.x * blockDim.x + threadIdx.x;
    cvt_one(src, g_wph, i);
}

// V transpose: g_v [b][t][kh][d] fp32 -> g_vth [b][kh][d][t] fp16
__global__ void __launch_bounds__(256) conv_vt_k() {
    __shared__ float tile[64][65];
    int tt = blockIdx.x, kh = blockIdx.y, b = blockIdx.z;
    int tid = threadIdx.x;
#pragma unroll
    for (int i = 0; i < 4; i++) {
        int idx = tid + i * 256;
        int r = idx >> 4, c = (idx & 15) * 4;
        float4 v = *(const float4*)&g_v[(((size_t)b * T_SEQ + tt * 64 + r) * NKV + kh) * HD + c];
        tile[r][c] = v.x; tile[r][c + 1] = v.y; tile[r][c + 2] = v.z; tile[r][c + 3] = v.w;
    }
    __syncthreads();
#pragma unroll
    for (int i = 0; i < 4; i++) {
        int idx = tid + i * 256;
        int d = idx >> 4, ts = (idx & 15) * 4;
        size_t o = (((size_t)b * NKV + kh) * HD + d) * T_SEQ + tt * 64 + ts;
        __half2 a = __floats2half2_rn(tile[ts][d], tile[ts + 1][d]);
        __half2 c = __floats2half2_rn(tile[ts + 2][d], tile[ts + 3][d]);
        *(__half2*)(g_vth + o)     = a;
        *(__half2*)(g_vth + o + 2) = c;
    }
}

// ---------------------------------------------------------------------------
// Single-pass fp16 GEMM: C[128,128] = A[128,1024] * B[128,1024]^T
// 8 warps (4M x 2N), warp tile 32x64, K-chunk 64, double-buffered cp.async.
// ---------------------------------------------------------------------------
#define KC2 64
#define LDT2 72
#define TSB2 (128 * LDT2 * 2)    // 18432
#define BUF2 (2 * TSB2)          // 36864 (A + B)
#define GEMM_SMEM2 (2 * BUF2)    // 73728

static __device__ __forceinline__ void tc_gemm_tile(
    const __half* __restrict__ A, const __half* __restrict__ B,
    int m0, float* __restrict__ C, int ldc, int ccol0) {

    extern __shared__ __half dsm[];
    uint32_t sbase = s2u(dsm);

    int tid  = threadIdx.x;
    int wid  = tid >> 5;
    int lane = tid & 31;
    int wm   = wid >> 1;
    int wn   = wid & 1;

    float acc[2][8][4];
#pragma unroll
    for (int mi = 0; mi < 2; mi++)
#pragma unroll
        for (int nj = 0; nj < 8; nj++)
#pragma unroll
            for (int u = 0; u < 4; u++) acc[mi][nj][u] = 0.f;

    uint32_t offA = (uint32_t)(wm * 32 + (lane & 15)) * (LDT2 * 2) + (lane >> 4) * 16;
    int rB = wn * 64 + ((lane >> 3) & 1) * 8 + (lane & 7);
    uint32_t offB = (uint32_t)rB * (LDT2 * 2) + (lane >> 4) * 16;

    // loader: per tile 1024 16B segs, 4 per thread (row = idx>>3, seg = idx&7)
    int lr[4], lsn[4];
    uint32_t ld[4];
#pragma unroll
    for (int i = 0; i < 4; i++) {
        int idx = tid + i * 256;
        lr[i]  = idx >> 3;
        lsn[i] = (idx & 7) * 8;
        ld[i]  = (uint32_t)lr[i] * (LDT2 * 2) + lsn[i] * 2;
    }

#define G_LOAD(k0, buf) do {                                                   \
    uint32_t so = sbase + (buf) * BUF2;                                        \
    _Pragma("unroll")                                                          \
    for (int i = 0; i < 4; i++) {                                              \
        CP_ASYNC16(so + ld[i], A + (size_t)(m0 + lr[i]) * C_DIM + (k0) + lsn[i]); \
        CP_ASYNC16(so + TSB2 + ld[i], B + (size_t)lr[i] * C_DIM + (k0) + lsn[i]); \
    }                                                                          \
} while (0)

    G_LOAD(0, 0);
    CP_COMMIT();

    const int NCH = C_DIM / KC2;   // 16
    for (int ch = 0; ch < NCH; ch++) {
        int buf = ch & 1;
        if (ch + 1 < NCH) {
            G_LOAD((ch + 1) * KC2, buf ^ 1);
            CP_COMMIT();
            CP_WAIT1();
        } else {
            CP_WAIT0();
        }
        __syncthreads();

        uint32_t aA = sbase + buf * BUF2 + offA;
        uint32_t aB = sbase + buf * BUF2 + TSB2 + offB;

#pragma unroll
        for (int ks = 0; ks < 4; ks++) {
            uint32_t koff = ks * 32;
            uint32_t a[2][4], b[4][4];
#pragma unroll
            for (int mi = 0; mi < 2; mi++)
                ldsm4(a[mi], aA + mi * 16 * (LDT2 * 2) + koff);
#pragma unroll
            for (int njp = 0; njp < 4; njp++)
                ldsm4(b[njp], aB + njp * 16 * (LDT2 * 2) + koff);
#pragma unroll
            for (int mi = 0; mi < 2; mi++)
#pragma unroll
                for (int njp = 0; njp < 4; njp++) {
                    uint32_t be[2] = {b[njp][0], b[njp][2]};
                    uint32_t bo[2] = {b[njp][1], b[njp][3]};
                    mma16816h(acc[mi][2 * njp + 0], a[mi], be);
                    mma16816h(acc[mi][2 * njp + 1], a[mi], bo);
                }
        }
        __syncthreads();
    }

    int erow = wm * 32 + (lane >> 2);
    int ecol = wn * 64 + (lane & 3) * 2;
#pragma unroll
    for (int mi = 0; mi < 2; mi++)
#pragma unroll
        for (int nj = 0; nj < 8; nj++) {
            int row = erow + mi * 16;
            int col = ccol0 + ecol + nj * 8;
            float* p0 = C + (size_t)(m0 + row) * ldc + col;
            float* p1 = C + (size_t)(m0 + row + 8) * ldc + col;
            *(float2*)p0 = make_float2(acc[mi][nj][0], acc[mi][nj][1]);
            *(float2*)p1 = make_float2(acc[mi][nj][2], acc[mi][nj][3]);
        }
}

__global__ void __launch_bounds__(256, 2) qkv_tc_k() {
    int mt = blockIdx.x, nb = blockIdx.y;
    int n0 = nb * 128;
    const __half* B = g_wh + (size_t)n0 * C_DIM;
    if (nb < 8)
        tc_gemm_tile(g_xh, B, mt * 128, g_q, 1024, n0);
    else if (nb < 12)
        tc_gemm_tile(g_xh, B, mt * 128, g_k, 512, n0 - 1024);
    else
        tc_gemm_tile(g_xh, B, mt * 128, g_v, 512, n0 - 1536);
}

__global__ void __launch_bounds__(256, 2) proj_tc_k(float* __restrict__ out) {
    int mt = blockIdx.x, nb = blockIdx.y;
    tc_gemm_tile(g_yh, g_wph + (size_t)nb * 128 * C_DIM, mt * 128, out, 1024, nb * 128);
}

// ---------------------------------------------------------------------------
// RoPE + RMSNorm + braid dot
// ---------------------------------------------------------------------------
__device__ __forceinline__ void rope_rms_warp(const float* __restrict__ src,
                                              const float* __restrict__ cosp,
                                              const float* __restrict__ sinp,
                                              const float* __restrict__ wb,
                                              float* __restrict__ sout,
                                              int nheads, int warp, int lane) {
    int h  = warp % nheads;
    int bt = warp / nheads;
    int t  = bt % T_SEQ;
    int b  = bt / T_SEQ;

    const float* row = src + (size_t)warp * HD;
    float x1 = row[lane];
    float x2 = row[lane + 32];
    float c = cosp[t * 32 + lane];
    float s = sinp[t * 32 + lane];
    float o1 = x1 * c + x2 * s;
    float o2 = x2 * c - x1 * s;

    float ss = o1 * o1 + o2 * o2;
#pragma unroll
    for (int off = 16; off; off >>= 1)
        ss += __shfl_xor_sync(0xffffffffu, ss, off);
    float scale = rsqrtf(ss * (1.f / 64.f) + 1e-6f);

    float d = (o1 * wb[lane] + o2 * wb[lane + 32]) * scale;
#pragma unroll
    for (int off = 16; off; off >>= 1)
        d += __shfl_xor_sync(0xffffffffu, d, off);
    if (lane == 0)
        sout[((size_t)b * nheads + h) * T_SEQ + t] = d;
}

__global__ void __launch_bounds__(256) rope_k(const float* cosp, const float* sinp,
                                              const float* wb) {
    int w    = (blockIdx.x * blockDim.x + threadIdx.x) >> 5;
    int lane = threadIdx.x & 31;
    const int NQ = BATCH * T_SEQ * NH;
    if (w < NQ)
        rope_rms_warp(g_q, cosp, sinp, wb, g_sq, NH, w, lane);
    else
        rope_rms_warp(g_k, cosp, sinp, wb, g_sk, NKV, w - NQ, lane);
}

// ---------------------------------------------------------------------------
// Attention, single-pass fp16.
// Block: (t-tile 64, kv-head, batch). 8 warps, warp tile m16 x n64.
// Rows 0-63: head 2kh; rows 64-127: head 2kh+1.
// A fragment P = sigmoid(sq+sk) via tanh.approx.f16x2; B = V^T via ldmatrix.
// ---------------------------------------------------------------------------
#define ALDS 72
#define AVROW (ALDS * 2)
#define AVBUF (64 * AVROW)

__global__ void __launch_bounds__(256, 2) attn_tc_k() {
    __shared__ __half Vh[2][64][ALDS];
    __shared__ float SQ[128];
    __shared__ float SK[2][64];

    int tt = (T_SEQ / 64 - 1) - blockIdx.x;
    int kh = blockIdx.y;
    int b  = blockIdx.z;
    int t0 = tt * 64;

    int tid  = threadIdx.x;
    int wid  = tid >> 5;
    int lane = tid & 31;

    if (tid < 128) {
        int hl = tid >> 6, tl = tid & 63;
        SQ[tid] = g_sq[((size_t)b * NH + kh * 2 + hl) * T_SEQ + t0 + tl];
    }

    const __half* gvh = g_vth + ((size_t)b * NKV + kh) * HD * T_SEQ;
    const float* gsk = g_sk + ((size_t)b * NKV + kh) * T_SEQ;

    uint32_t sVh = s2u(Vh), sSK = s2u(SK);

    int vr0 = tid >> 3,         vs0 = (tid & 7) * 8;
    int vr1 = (tid + 256) >> 3, vs1 = ((tid + 256) & 7) * 8;
    uint32_t vd0 = (uint32_t)vr0 * AVROW + vs0 * 2;
    uint32_t vd1 = (uint32_t)vr1 * AVROW + vs1 * 2;

#define AV_LOAD(s0, buf) do {                                                  \
    uint32_t bo = (buf) * AVBUF;                                               \
    CP_ASYNC16(sVh + bo + vd0, gvh + (size_t)vr0 * T_SEQ + (s0) + vs0);        \
    CP_ASYNC16(sVh + bo + vd1, gvh + (size_t)vr1 * T_SEQ + (s0) + vs1);        \
    if (tid < 16) CP_ASYNC16(sSK + (buf) * 256 + tid * 16, gsk + (s0) + tid * 4); \
} while (0)

    float acc[8][4];
#pragma unroll
    for (int nj = 0; nj < 8; nj++)
#pragma unroll
        for (int u = 0; u < 4; u++) acc[nj][u] = 0.f;

    int r  = lane >> 2;
    int c2 = (lane & 3) * 2;
    int row0 = wid * 16 + r;
    int tl0 = row0 & 63, tl1 = (row0 + 8) & 63;

    int rB = ((lane >> 3) & 1) * 8 + (lane & 7);
    uint32_t offB = (uint32_t)rB * AVROW + (lane >> 4) * 16;

    AV_LOAD(0, 0);
    CP_COMMIT();
    __syncthreads();

    float sq0 = SQ[row0] * 0.5f, sq1 = SQ[row0 + 8] * 0.5f;
    const __half2 half05 = __floats2half2_rn(0.5f, 0.5f);

    const int NCH = tt + 1;
    for (int ch = 0; ch < NCH; ch++) {
        int buf = ch & 1;
        if (ch + 1 < NCH) {
            AV_LOAD((ch + 1) * 64, buf ^ 1);
            CP_COMMIT();
            CP_WAIT1();
        } else {
            CP_WAIT0();
        }
        __syncthreads();

        bool diag = (ch == tt);
        const float* SKb = SK[buf];
        uint32_t vbh = sVh + buf * AVBUF + offB;

#pragma unroll 2
        for (int ks = 0; ks < 4; ks++) {
            int kb = ks * 16 + c2;
            float sk0 = SKb[kb] * 0.5f,     sk1 = SKb[kb + 1] * 0.5f;
            float sk8 = SKb[kb + 8] * 0.5f, sk9 = SKb[kb + 9] * 0.5f;

            // P fragment: ah[0]=(row0; kb,kb+1) ah[1]=(row0+8; ..) ah[2]=(row0; kb+8,kb+9) ah[3]=(row0+8; ..)
            uint32_t ah[4];
            {
                __half2 z0 = __floats2half2_rn(sq0 + sk0, sq0 + sk1);
                __half2 z1 = __floats2half2_rn(sq1 + sk0, sq1 + sk1);
                __half2 z2 = __floats2half2_rn(sq0 + sk8, sq0 + sk9);
                __half2 z3 = __floats2half2_rn(sq1 + sk8, sq1 + sk9);
                __half2 p0, p1, p2, p3;
                *(uint32_t*)&p0 = tanh2(*(uint32_t*)&z0);
                *(uint32_t*)&p1 = tanh2(*(uint32_t*)&z1);
                *(uint32_t*)&p2 = tanh2(*(uint32_t*)&z2);
                *(uint32_t*)&p3 = tanh2(*(uint32_t*)&z3);
                p0 = __hfma2(p0, half05, half05);
                p1 = __hfma2(p1, half05, half05);
                p2 = __hfma2(p2, half05, half05);
                p3 = __hfma2(p3, half05, half05);
                if (diag) {
                    __half2 m0 = __floats2half2_rn(kb <= tl0 ? 1.f : 0.f,
                                                   kb + 1 <= tl0 ? 1.f : 0.f);
                    __half2 m1 = __floats2half2_rn(kb <= tl1 ? 1.f : 0.f,
                                                   kb + 1 <= tl1 ? 1.f : 0.f);
                    __half2 m2 = __floats2half2_rn(kb + 8 <= tl0 ? 1.f : 0.f,
                                                   kb + 9 <= tl0 ? 1.f : 0.f);
                    __half2 m3 = __floats2half2_rn(kb + 8 <= tl1 ? 1.f : 0.f,
                                                   kb + 9 <= tl1 ? 1.f : 0.f);
                    p0 = __hmul2(p0, m0);
                    p1 = __hmul2(p1, m1);
                    p2 = __hmul2(p2, m2);
                    p3 = __hmul2(p3, m3);
                }
                ah[0] = *(uint32_t*)&p0;
                ah[1] = *(uint32_t*)&p1;
                ah[2] = *(uint32_t*)&p2;
                ah[3] = *(uint32_t*)&p3;
            }

            uint32_t bh[4][4];
#pragma unroll
            for (int njp = 0; njp < 4; njp++)
                ldsm4(bh[njp], vbh + njp * 16 * AVROW + ks * 32);
#pragma unroll
            for (int njp = 0; njp < 4; njp++) {
                uint32_t be[2] = {bh[njp][0], bh[njp][2]};
                uint32_t bo[2] = {bh[njp][1], bh[njp][3]};
                mma16816h(acc[2 * njp + 0], ah, be);
                mma16816h(acc[2 * njp + 1], ah, bo);
            }
        }
        __syncthreads();
    }

    // Epilogue: scale + write y fp16, layout [b][t][h][d]
    const float inv = 1.f / (sqrtf((float)T_SEQ) + 1e-6f);
    int hgl = kh * 2 + (row0 >> 6);
    int tA = t0 + tl0, tB = t0 + tl1;
    __half* yA = g_yh + (((size_t)b * T_SEQ + tA) * NH + hgl) * HD;
    __half* yB = g_yh + (((size_t)b * T_SEQ + tB) * NH + hgl) * HD;
#pragma unroll
    for (int nj = 0; nj < 8; nj++) {
        int d = nj * 8 + c2;
        *(__half2*)(yA + d) = __floats2half2_rn(acc[nj][0] * inv, acc[nj][1] * inv);
        *(__half2*)(yB + d) = __floats2half2_rn(acc[nj][2] * inv, acc[nj][3] * inv);
    }
}

// ---------------------------------------------------------------------------
extern "C" void kernel_launch(void* const* d_in, const int* in_sizes, int n_in,
                              void* d_out, int out_size) {
    const float* x    = (const float*)d_in[0];
    const float* cosp = (const float*)d_in[1];
    const float* sinp = (const float*)d_in[2];
    const float* Wq   = (const float*)d_in[3];
    const float* Wk   = (const float*)d_in[4];
    const float* Wv   = (const float*)d_in[5];
    const float* Wp   = (const float*)d_in[6];
    const float* wb   = (const float*)d_in[7];
    float* out = (float*)d_out;

    cudaFuncSetAttribute(qkv_tc_k,  cudaFuncAttributeMaxDynamicSharedMemorySize, GEMM_SMEM2);
    cudaFuncSetAttribute(proj_tc_k, cudaFuncAttributeMaxDynamicSharedMemorySize, GEMM_SMEM2);

    conv_x_k<<<M_ROWS * C_DIM / 4 / 256, 256>>>(x);
    conv_w_k<<<2048 * 1024 / 4 / 256, 256>>>(Wq, Wk, Wv);
    conv_wp_k<<<1024 * 1024 / 4 / 256, 256>>>(Wp);

    qkv_tc_k<<<dim3(32, 16), 256, GEMM_SMEM2>>>();

    rope_k<<<(65536 + 32768) / 8, 256>>>(cosp, sinp, wb);
    conv_vt_k<<<dim3(T_SEQ / 64, NKV, BATCH), 256>>>();

    attn_tc_k<<<dim3(T_SEQ / 64, NKV, BATCH), 256>>>();

    proj_tc_k<<<dim3(32, 8), 256, GEMM_SMEM2>>>(out);
}

// round 9
// speedup vs baseline: 7.4980x; 1.0819x over previous
#include <cuda_runtime.h>
#include <cuda_fp16.h>
#include <math.h>
#include <stdint.h>

#define BATCH 2
#define T_SEQ 2048
#define C_DIM 1024
#define NH 16
#define NKV 8
#define HD 64
#define M_ROWS (BATCH * T_SEQ)   // 4096

// ---------------------------------------------------------------------------
// Scratch (__device__ globals)
// ---------------------------------------------------------------------------
__device__ float g_sq[BATCH * NH * T_SEQ];
__device__ float g_sk[BATCH * NKV * T_SEQ];

__device__ __half g_xh[M_ROWS * C_DIM];
__device__ __half g_wh[2048 * C_DIM];     // 0-1023 Wq, 1024-1535 Wk, 1536-2047 Wv
__device__ __half g_wph[C_DIM * C_DIM];
__device__ __half g_yh[M_ROWS * C_DIM];   // attn output, [b][t][h][d]
__device__ __half g_vh[M_ROWS * NKV * HD];          // V fp16 [b][t][kh][d]
__device__ __half g_vth[BATCH * NKV * HD * T_SEQ];  // V^T [b][kh][d][t]

// ---------------------------------------------------------------------------
// PTX helpers
// ---------------------------------------------------------------------------
static __device__ __forceinline__ uint32_t s2u(const void* p) {
    uint32_t a;
    asm("{ .reg .u64 t; cvta.to.shared.u64 t, %1; cvt.u32.u64 %0, t; }"
        : "=r"(a) : "l"(p));
    return a;
}
static __device__ __forceinline__ void ldsm4(uint32_t* r, uint32_t addr) {
    asm volatile("ldmatrix.sync.aligned.m8n8.x4.shared.b16 {%0,%1,%2,%3}, [%4];"
                 : "=r"(r[0]), "=r"(r[1]), "=r"(r[2]), "=r"(r[3]) : "r"(addr));
}
static __device__ __forceinline__ void mma16816h(float* c, const uint32_t* a,
                                                 const uint32_t* b) {
    asm volatile(
        "mma.sync.aligned.m16n8k16.row.col.f32.f16.f16.f32 "
        "{%0,%1,%2,%3}, {%4,%5,%6,%7}, {%8,%9}, {%0,%1,%2,%3};"
        : "+f"(c[0]), "+f"(c[1]), "+f"(c[2]), "+f"(c[3])
        : "r"(a[0]), "r"(a[1]), "r"(a[2]), "r"(a[3]), "r"(b[0]), "r"(b[1]));
}
static __device__ __forceinline__ uint32_t tanh2(uint32_t x) {
    uint32_t o;
    asm("tanh.approx.f16x2 %0, %1;" : "=r"(o) : "r"(x));
    return o;
}
#define CP_ASYNC16(dst, src) \
    asm volatile("cp.async.cg.shared.global [%0], [%1], 16;" :: "r"(dst), "l"(src))
#define CP_COMMIT() asm volatile("cp.async.commit_group;" ::: "memory")
#define CP_WAIT1()  asm volatile("cp.async.wait_group 1;" ::: "memory")
#define CP_WAIT0()  asm volatile("cp.async.wait_group 0;" ::: "memory")

// ---------------------------------------------------------------------------
// fp32 -> fp16 conversions
// ---------------------------------------------------------------------------
static __device__ __forceinline__ void cvt_one(const float* __restrict__ src,
                                               __half* __restrict__ dst, size_t i) {
    float4 v = *(const float4*)(src + i * 4);
    *(__half2*)(dst + i * 4)     = __floats2half2_rn(v.x, v.y);
    *(__half2*)(dst + i * 4 + 2) = __floats2half2_rn(v.z, v.w);
}
__global__ void __launch_bounds__(256) conv_x_k(const float* __restrict__ src) {
    int i = blockIdx.x * blockDim.x + threadIdx.x;
    cvt_one(src, g_xh, i);
}
__global__ void __launch_bounds__(256) conv_w_k(const float* __restrict__ Wq,
                                                const float* __restrict__ Wk,
                                                const float* __restrict__ Wv) {
    int i = blockIdx.x * blockDim.x + threadIdx.x;
    const float* src;
    int rel;
    if (i < 262144)      { src = Wq; rel = i; }
    else if (i < 393216) { src = Wk; rel = i - 262144; }
    else                 { src = Wv; rel = i - 393216; }
    float4 v = *(const float4*)(src + (size_t)rel * 4);
    *(__half2*)(g_wh + (size_t)i * 4)     = __floats2half2_rn(v.x, v.y);
    *(__half2*)(g_wh + (size_t)i * 4 + 2) = __floats2half2_rn(v.z, v.w);
}
__global__ void __launch_bounds__(256) conv_wp_k(const float* __restrict__ src) {
    int i = blockIdx.x * blockDim.x + threadIdx.x;
    cvt_one(src, g_wph, i);
}

// V transpose: g_vh [b][t][kh][d] fp16 -> g_vth [b][kh][d][t] fp16
__global__ void __launch_bounds__(256) conv_vt_k() {
    __shared__ __half tile[64][72];
    int tt = blockIdx.x, kh = blockIdx.y, b = blockIdx.z;
    int tid = threadIdx.x;
#pragma unroll
    for (int i = 0; i < 2; i++) {
        int seg = tid + i * 256;       // 512 segs of 8 halves
        int r = seg >> 3, c = (seg & 7) * 8;
        *(uint4*)&tile[r][c] =
            *(const uint4*)&g_vh[(((size_t)b * T_SEQ + tt * 64 + r) * NKV + kh) * HD + c];
    }
    __syncthreads();
    int d = tid >> 2, tg = (tid & 3) * 16;
    size_t o = (((size_t)b * NKV + kh) * HD + d) * T_SEQ + tt * 64 + tg;
#pragma unroll
    for (int j = 0; j < 8; j++) {
        __half2 h2;
        h2.x = tile[tg + 2 * j][d];
        h2.y = tile[tg + 2 * j + 1][d];
        *(__half2*)(g_vth + o + 2 * j) = h2;
    }
}

// ---------------------------------------------------------------------------
// fp16 GEMM mainloop: acc += A[128,1024] * B[128,1024]^T (tile m0, full K)
// 8 warps (4M x 2N), warp tile 32x64, K-chunk 64, double-buffered cp.async.
// ---------------------------------------------------------------------------
#define KC2 64
#define LDT2 72
#define TSB2 (128 * LDT2 * 2)    // 18432
#define BUF2 (2 * TSB2)          // 36864 (A + B)
#define GEMM_SMEM2 (2 * BUF2)    // 73728

static __device__ __forceinline__ void gemm_mainloop(
    const __half* __restrict__ A, const __half* __restrict__ B,
    int m0, float acc[2][8][4]) {

    extern __shared__ __half dsm[];
    uint32_t sbase = s2u(dsm);

    int tid  = threadIdx.x;
    int wid  = tid >> 5;
    int lane = tid & 31;
    int wm   = wid >> 1;
    int wn   = wid & 1;

    uint32_t offA = (uint32_t)(wm * 32 + (lane & 15)) * (LDT2 * 2) + (lane >> 4) * 16;
    int rB = wn * 64 + ((lane >> 3) & 1) * 8 + (lane & 7);
    uint32_t offB = (uint32_t)rB * (LDT2 * 2) + (lane >> 4) * 16;

    int lr[4], lsn[4];
    uint32_t ld[4];
#pragma unroll
    for (int i = 0; i < 4; i++) {
        int idx = tid + i * 256;
        lr[i]  = idx >> 3;
        lsn[i] = (idx & 7) * 8;
        ld[i]  = (uint32_t)lr[i] * (LDT2 * 2) + lsn[i] * 2;
    }

#define G_LOAD(k0, buf) do {                                                   \
    uint32_t so = sbase + (buf) * BUF2;                                        \
    _Pragma("unroll")                                                          \
    for (int i = 0; i < 4; i++) {                                              \
        CP_ASYNC16(so + ld[i], A + (size_t)(m0 + lr[i]) * C_DIM + (k0) + lsn[i]); \
        CP_ASYNC16(so + TSB2 + ld[i], B + (size_t)lr[i] * C_DIM + (k0) + lsn[i]); \
    }                                                                          \
} while (0)

    G_LOAD(0, 0);
    CP_COMMIT();

    const int NCH = C_DIM / KC2;   // 16
    for (int ch = 0; ch < NCH; ch++) {
        int buf = ch & 1;
        if (ch + 1 < NCH) {
            G_LOAD((ch + 1) * KC2, buf ^ 1);
            CP_COMMIT();
            CP_WAIT1();
        } else {
            CP_WAIT0();
        }
        __syncthreads();

        uint32_t aA = sbase + buf * BUF2 + offA;
        uint32_t aB = sbase + buf * BUF2 + TSB2 + offB;

#pragma unroll
        for (int ks = 0; ks < 4; ks++) {
            uint32_t koff = ks * 32;
            uint32_t a[2][4], b[4][4];
#pragma unroll
            for (int mi = 0; mi < 2; mi++)
                ldsm4(a[mi], aA + mi * 16 * (LDT2 * 2) + koff);
#pragma unroll
            for (int njp = 0; njp < 4; njp++)
                ldsm4(b[njp], aB + njp * 16 * (LDT2 * 2) + koff);
#pragma unroll
            for (int mi = 0; mi < 2; mi++)
#pragma unroll
                for (int njp = 0; njp < 4; njp++) {
                    uint32_t be[2] = {b[njp][0], b[njp][2]};
                    uint32_t bo[2] = {b[njp][1], b[njp][3]};
                    mma16816h(acc[mi][2 * njp + 0], a[mi], be);
                    mma16816h(acc[mi][2 * njp + 1], a[mi], bo);
                }
        }
        __syncthreads();
    }
#undef G_LOAD
}

// ---------------------------------------------------------------------------
// QKV GEMM with fused epilogues:
//  nb 0-7  (Q): RoPE+RMS+braid-dot in-register -> g_sq scalars (no Q writeback)
//  nb 8-11 (K): same -> g_sk
//  nb 12-15(V): write fp16 g_vh [b][t][kh][d]
// ---------------------------------------------------------------------------
__global__ void __launch_bounds__(256, 2) qkv_tc_k(const float* __restrict__ cosp,
                                                   const float* __restrict__ sinp,
                                                   const float* __restrict__ wb) {
    int mt = blockIdx.x, nb = blockIdx.y;
    int n0 = nb * 128;
    int m0 = mt * 128;

    float acc[2][8][4];
#pragma unroll
    for (int mi = 0; mi < 2; mi++)
#pragma unroll
        for (int nj = 0; nj < 8; nj++)
#pragma unroll
            for (int u = 0; u < 4; u++) acc[mi][nj][u] = 0.f;

    gemm_mainloop(g_xh, g_wh + (size_t)n0 * C_DIM, m0, acc);

    int tid  = threadIdx.x;
    int wid  = tid >> 5;
    int lane = tid & 31;
    int wm   = wid >> 1;
    int wn   = wid & 1;
    int erow = wm * 32 + (lane >> 2);
    int e    = (lane & 3) * 2;

    if (nb < 12) {
        // Q or K: fused rope + rmsnorm + braid dot
        float* souts;
        int nheads, hh;
        if (nb < 8) { souts = g_sq; nheads = NH;  hh = 2 * nb + wn; }
        else        { souts = g_sk; nheads = NKV; hh = 2 * (nb - 8) + wn; }

#pragma unroll
        for (int mi = 0; mi < 2; mi++)
#pragma unroll
            for (int hf = 0; hf < 2; hf++) {
                int r = erow + mi * 16 + hf * 8;
                int m = m0 + r;
                int t = m & (T_SEQ - 1);
                int b = m >> 11;
                int ub = hf * 2;
                const float* cr = cosp + t * 32;
                const float* sr = sinp + t * 32;
                float ssum = 0.f, dsum = 0.f;
#pragma unroll
                for (int nj = 0; nj < 4; nj++)
#pragma unroll
                    for (int u = 0; u < 2; u++) {
                        int d = e + u + nj * 8;           // 0..31
                        float x1 = acc[mi][nj][ub + u];
                        float x2 = acc[mi][nj + 4][ub + u];
                        float c = cr[d], s = sr[d];
                        float o1 = x1 * c + x2 * s;
                        float o2 = x2 * c - x1 * s;
                        ssum += o1 * o1 + o2 * o2;
                        dsum += o1 * wb[d] + o2 * wb[d + 32];
                    }
                ssum += __shfl_xor_sync(0xffffffffu, ssum, 1);
                dsum += __shfl_xor_sync(0xffffffffu, dsum, 1);
                ssum += __shfl_xor_sync(0xffffffffu, ssum, 2);
                dsum += __shfl_xor_sync(0xffffffffu, dsum, 2);
                if ((lane & 3) == 0) {
                    float scale = rsqrtf(ssum * (1.f / 64.f) + 1e-6f);
                    souts[((size_t)b * nheads + hh) * T_SEQ + t] = dsum * scale;
                }
            }
    } else {
        // V: store fp16 [b][t][kh][d]
        int kh = 2 * (nb - 12) + wn;
#pragma unroll
        for (int mi = 0; mi < 2; mi++)
#pragma unroll
            for (int hf = 0; hf < 2; hf++) {
                int r = erow + mi * 16 + hf * 8;
                int m = m0 + r;
                int t = m & (T_SEQ - 1);
                int b = m >> 11;
                int ub = hf * 2;
                __half* vp = g_vh + (((size_t)b * T_SEQ + t) * NKV + kh) * HD;
#pragma unroll
                for (int nj = 0; nj < 8; nj++)
                    *(__half2*)(vp + e + nj * 8) =
                        __floats2half2_rn(acc[mi][nj][ub], acc[mi][nj][ub + 1]);
            }
    }
}

// ---------------------------------------------------------------------------
// Proj GEMM (unchanged epilogue -> fp32 out)
// ---------------------------------------------------------------------------
__global__ void __launch_bounds__(256, 2) proj_tc_k(float* __restrict__ out) {
    int mt = blockIdx.x, nb = blockIdx.y;
    int m0 = mt * 128;

    float acc[2][8][4];
#pragma unroll
    for (int mi = 0; mi < 2; mi++)
#pragma unroll
        for (int nj = 0; nj < 8; nj++)
#pragma unroll
            for (int u = 0; u < 4; u++) acc[mi][nj][u] = 0.f;

    gemm_mainloop(g_yh, g_wph + (size_t)nb * 128 * C_DIM, m0, acc);

    int tid  = threadIdx.x;
    int wid  = tid >> 5;
    int lane = tid & 31;
    int wm   = wid >> 1;
    int wn   = wid & 1;
    int erow = wm * 32 + (lane >> 2);
    int ecol = wn * 64 + (lane & 3) * 2;
#pragma unroll
    for (int mi = 0; mi < 2; mi++)
#pragma unroll
        for (int nj = 0; nj < 8; nj++) {
            int row = erow + mi * 16;
            int col = nb * 128 + ecol + nj * 8;
            float* p0 = out + (size_t)(m0 + row) * C_DIM + col;
            float* p1 = out + (size_t)(m0 + row + 8) * C_DIM + col;
            *(float2*)p0 = make_float2(acc[mi][nj][0], acc[mi][nj][1]);
            *(float2*)p1 = make_float2(acc[mi][nj][2], acc[mi][nj][3]);
        }
}

// ---------------------------------------------------------------------------
// Attention, single-pass fp16 (validated round-8 version)
// ---------------------------------------------------------------------------
#define ALDS 72
#define AVROW (ALDS * 2)
#define AVBUF (64 * AVROW)

__global__ void __launch_bounds__(256, 2) attn_tc_k() {
    __shared__ __half Vh[2][64][ALDS];
    __shared__ float SQ[128];
    __shared__ float SK[2][64];

    int tt = (T_SEQ / 64 - 1) - blockIdx.x;
    int kh = blockIdx.y;
    int b  = blockIdx.z;
    int t0 = tt * 64;

    int tid  = threadIdx.x;
    int wid  = tid >> 5;
    int lane = tid & 31;

    if (tid < 128) {
        int hl = tid >> 6, tl = tid & 63;
        SQ[tid] = g_sq[((size_t)b * NH + kh * 2 + hl) * T_SEQ + t0 + tl];
    }

    const __half* gvh = g_vth + ((size_t)b * NKV + kh) * HD * T_SEQ;
    const float* gsk = g_sk + ((size_t)b * NKV + kh) * T_SEQ;

    uint32_t sVh = s2u(Vh), sSK = s2u(SK);

    int vr0 = tid >> 3,         vs0 = (tid & 7) * 8;
    int vr1 = (tid + 256) >> 3, vs1 = ((tid + 256) & 7) * 8;
    uint32_t vd0 = (uint32_t)vr0 * AVROW + vs0 * 2;
    uint32_t vd1 = (uint32_t)vr1 * AVROW + vs1 * 2;

#define AV_LOAD(s0, buf) do {                                                  \
    uint32_t bo = (buf) * AVBUF;                                               \
    CP_ASYNC16(sVh + bo + vd0, gvh + (size_t)vr0 * T_SEQ + (s0) + vs0);        \
    CP_ASYNC16(sVh + bo + vd1, gvh + (size_t)vr1 * T_SEQ + (s0) + vs1);        \
    if (tid < 16) CP_ASYNC16(sSK + (buf) * 256 + tid * 16, gsk + (s0) + tid * 4); \
} while (0)

    float acc[8][4];
#pragma unroll
    for (int nj = 0; nj < 8; nj++)
#pragma unroll
        for (int u = 0; u < 4; u++) acc[nj][u] = 0.f;

    int r  = lane >> 2;
    int c2 = (lane & 3) * 2;
    int row0 = wid * 16 + r;
    int tl0 = row0 & 63, tl1 = (row0 + 8) & 63;

    int rB = ((lane >> 3) & 1) * 8 + (lane & 7);
    uint32_t offB = (uint32_t)rB * AVROW + (lane >> 4) * 16;

    AV_LOAD(0, 0);
    CP_COMMIT();
    __syncthreads();

    float sq0 = SQ[row0] * 0.5f, sq1 = SQ[row0 + 8] * 0.5f;
    const __half2 half05 = __floats2half2_rn(0.5f, 0.5f);

    const int NCH = tt + 1;
    for (int ch = 0; ch < NCH; ch++) {
        int buf = ch & 1;
        if (ch + 1 < NCH) {
            AV_LOAD((ch + 1) * 64, buf ^ 1);
            CP_COMMIT();
            CP_WAIT1();
        } else {
            CP_WAIT0();
        }
        __syncthreads();

        bool diag = (ch == tt);
        const float* SKb = SK[buf];
        uint32_t vbh = sVh + buf * AVBUF + offB;

#pragma unroll 2
        for (int ks = 0; ks < 4; ks++) {
            int kb = ks * 16 + c2;
            float sk0 = SKb[kb] * 0.5f,     sk1 = SKb[kb + 1] * 0.5f;
            float sk8 = SKb[kb + 8] * 0.5f, sk9 = SKb[kb + 9] * 0.5f;

            uint32_t ah[4];
            {
                __half2 z0 = __floats2half2_rn(sq0 + sk0, sq0 + sk1);
                __half2 z1 = __floats2half2_rn(sq1 + sk0, sq1 + sk1);
                __half2 z2 = __floats2half2_rn(sq0 + sk8, sq0 + sk9);
                __half2 z3 = __floats2half2_rn(sq1 + sk8, sq1 + sk9);
                __half2 p0, p1, p2, p3;
                *(uint32_t*)&p0 = tanh2(*(uint32_t*)&z0);
                *(uint32_t*)&p1 = tanh2(*(uint32_t*)&z1);
                *(uint32_t*)&p2 = tanh2(*(uint32_t*)&z2);
                *(uint32_t*)&p3 = tanh2(*(uint32_t*)&z3);
                p0 = __hfma2(p0, half05, half05);
                p1 = __hfma2(p1, half05, half05);
                p2 = __hfma2(p2, half05, half05);
                p3 = __hfma2(p3, half05, half05);
                if (diag) {
                    __half2 m0 = __floats2half2_rn(kb <= tl0 ? 1.f : 0.f,
                                                   kb + 1 <= tl0 ? 1.f : 0.f);
                    __half2 m1 = __floats2half2_rn(kb <= tl1 ? 1.f : 0.f,
                                                   kb + 1 <= tl1 ? 1.f : 0.f);
                    __half2 m2 = __floats2half2_rn(kb + 8 <= tl0 ? 1.f : 0.f,
                                                   kb + 9 <= tl0 ? 1.f : 0.f);
                    __half2 m3 = __floats2half2_rn(kb + 8 <= tl1 ? 1.f : 0.f,
                                                   kb + 9 <= tl1 ? 1.f : 0.f);
                    p0 = __hmul2(p0, m0);
                    p1 = __hmul2(p1, m1);
                    p2 = __hmul2(p2, m2);
                    p3 = __hmul2(p3, m3);
                }
                ah[0] = *(uint32_t*)&p0;
                ah[1] = *(uint32_t*)&p1;
                ah[2] = *(uint32_t*)&p2;
                ah[3] = *(uint32_t*)&p3;
            }

            uint32_t bh[4][4];
#pragma unroll
            for (int njp = 0; njp < 4; njp++)
                ldsm4(bh[njp], vbh + njp * 16 * AVROW + ks * 32);
#pragma unroll
            for (int njp = 0; njp < 4; njp++) {
                uint32_t be[2] = {bh[njp][0], bh[njp][2]};
                uint32_t bo[2] = {bh[njp][1], bh[njp][3]};
                mma16816h(acc[2 * njp + 0], ah, be);
                mma16816h(acc[2 * njp + 1], ah, bo);
            }
        }
        __syncthreads();
    }

    const float inv = 1.f / (sqrtf((float)T_SEQ) + 1e-6f);
    int hgl = kh * 2 + (row0 >> 6);
    int tA = t0 + tl0, tB = t0 + tl1;
    __half* yA = g_yh + (((size_t)b * T_SEQ + tA) * NH + hgl) * HD;
    __half* yB = g_yh + (((size_t)b * T_SEQ + tB) * NH + hgl) * HD;
#pragma unroll
    for (int nj = 0; nj < 8; nj++) {
        int d = nj * 8 + c2;
        *(__half2*)(yA + d) = __floats2half2_rn(acc[nj][0] * inv, acc[nj][1] * inv);
        *(__half2*)(yB + d) = __floats2half2_rn(acc[nj][2] * inv, acc[nj][3] * inv);
    }
}

// ---------------------------------------------------------------------------
extern "C" void kernel_launch(void* const* d_in, const int* in_sizes, int n_in,
                              void* d_out, int out_size) {
    const float* x    = (const float*)d_in[0];
    const float* cosp = (const float*)d_in[1];
    const float* sinp = (const float*)d_in[2];
    const float* Wq   = (const float*)d_in[3];
    const float* Wk   = (const float*)d_in[4];
    const float* Wv   = (const float*)d_in[5];
    const float* Wp   = (const float*)d_in[6];
    const float* wb   = (const float*)d_in[7];
    float* out = (float*)d_out;

    cudaFuncSetAttribute(qkv_tc_k,  cudaFuncAttributeMaxDynamicSharedMemorySize, GEMM_SMEM2);
    cudaFuncSetAttribute(proj_tc_k, cudaFuncAttributeMaxDynamicSharedMemorySize, GEMM_SMEM2);

    conv_x_k<<<M_ROWS * C_DIM / 4 / 256, 256>>>(x);
    conv_w_k<<<2048 * 1024 / 4 / 256, 256>>>(Wq, Wk, Wv);
    conv_wp_k<<<1024 * 1024 / 4 / 256, 256>>>(Wp);

    qkv_tc_k<<<dim3(32, 16), 256, GEMM_SMEM2>>>(cosp, sinp, wb);

    conv_vt_k<<<dim3(T_SEQ / 64, NKV, BATCH), 256>>>();

    attn_tc_k<<<dim3(T_SEQ / 64, NKV, BATCH), 256>>>();

    proj_tc_k<<<dim3(32, 8), 256, GEMM_SMEM2>>>(out);
}

// round 10
// speedup vs baseline: 7.5977x; 1.0133x over previous
#include <cuda_runtime.h>
#include <cuda_fp16.h>
#include <math.h>
#include <stdint.h>

#define BATCH 2
#define T_SEQ 2048
#define C_DIM 1024
#define NH 16
#define NKV 8
#define HD 64
#define M_ROWS (BATCH * T_SEQ)   // 4096

// ---------------------------------------------------------------------------
// Scratch (__device__ globals)
// ---------------------------------------------------------------------------
__device__ float g_sq[BATCH * NH * T_SEQ];
__device__ float g_sk[BATCH * NKV * T_SEQ];

__device__ __half g_xh[M_ROWS * C_DIM];
__device__ __half g_wh[2048 * C_DIM];     // 0-1023 Wq, 1024-1535 Wk, 1536-2047 Wv
__device__ __half g_wph[C_DIM * C_DIM];
__device__ __half g_yh[M_ROWS * C_DIM];   // attn output, [b][t][h][d]
__device__ __half g_vh[M_ROWS * NKV * HD];          // V fp16 [b][t][kh][d]
__device__ __half g_vth[BATCH * NKV * HD * T_SEQ];  // V^T [b][kh][d][t]

// ---------------------------------------------------------------------------
// PTX helpers
// ---------------------------------------------------------------------------
static __device__ __forceinline__ uint32_t s2u(const void* p) {
    uint32_t a;
    asm("{ .reg .u64 t; cvta.to.shared.u64 t, %1; cvt.u32.u64 %0, t; }"
        : "=r"(a) : "l"(p));
    return a;
}
static __device__ __forceinline__ void ldsm4(uint32_t* r, uint32_t addr) {
    asm volatile("ldmatrix.sync.aligned.m8n8.x4.shared.b16 {%0,%1,%2,%3}, [%4];"
                 : "=r"(r[0]), "=r"(r[1]), "=r"(r[2]), "=r"(r[3]) : "r"(addr));
}
static __device__ __forceinline__ void mma16816h(float* c, const uint32_t* a,
                                                 const uint32_t* b) {
    asm volatile(
        "mma.sync.aligned.m16n8k16.row.col.f32.f16.f16.f32 "
        "{%0,%1,%2,%3}, {%4,%5,%6,%7}, {%8,%9}, {%0,%1,%2,%3};"
        : "+f"(c[0]), "+f"(c[1]), "+f"(c[2]), "+f"(c[3])
        : "r"(a[0]), "r"(a[1]), "r"(a[2]), "r"(a[3]), "r"(b[0]), "r"(b[1]));
}
static __device__ __forceinline__ uint32_t tanh2(uint32_t x) {
    uint32_t o;
    asm("tanh.approx.f16x2 %0, %1;" : "=r"(o) : "r"(x));
    return o;
}
#define CP_ASYNC16(dst, src) \
    asm volatile("cp.async.cg.shared.global [%0], [%1], 16;" :: "r"(dst), "l"(src))
#define CP_COMMIT() asm volatile("cp.async.commit_group;" ::: "memory")
#define CP_WAIT1()  asm volatile("cp.async.wait_group 1;" ::: "memory")
#define CP_WAIT0()  asm volatile("cp.async.wait_group 0;" ::: "memory")

// ---------------------------------------------------------------------------
// Merged fp32 -> fp16 conversion: x (1048576 f4) | Wq/Wk/Wv (524288) | Wp (262144)
// ---------------------------------------------------------------------------
__global__ void __launch_bounds__(256) conv_all_k(const float* __restrict__ x,
                                                  const float* __restrict__ Wq,
                                                  const float* __restrict__ Wk,
                                                  const float* __restrict__ Wv,
                                                  const float* __restrict__ Wp) {
    int i = blockIdx.x * blockDim.x + threadIdx.x;   // float4 index
    const float* src;
    __half* dst;
    int rel;
    if (i < 1048576) {
        src = x; dst = g_xh; rel = i;
        float4 v = *(const float4*)(src + (size_t)rel * 4);
        *(__half2*)(dst + (size_t)i * 4)     = __floats2half2_rn(v.x, v.y);
        *(__half2*)(dst + (size_t)i * 4 + 2) = __floats2half2_rn(v.z, v.w);
    } else if (i < 1572864) {
        int wrel = i - 1048576;
        if (wrel < 262144)      { src = Wq; rel = wrel; }
        else if (wrel < 393216) { src = Wk; rel = wrel - 262144; }
        else                    { src = Wv; rel = wrel - 393216; }
        float4 v = *(const float4*)(src + (size_t)rel * 4);
        *(__half2*)(g_wh + (size_t)wrel * 4)     = __floats2half2_rn(v.x, v.y);
        *(__half2*)(g_wh + (size_t)wrel * 4 + 2) = __floats2half2_rn(v.z, v.w);
    } else {
        rel = i - 1572864;
        float4 v = *(const float4*)(Wp + (size_t)rel * 4);
        *(__half2*)(g_wph + (size_t)rel * 4)     = __floats2half2_rn(v.x, v.y);
        *(__half2*)(g_wph + (size_t)rel * 4 + 2) = __floats2half2_rn(v.z, v.w);
    }
}

// V transpose: g_vh [b][t][kh][d] fp16 -> g_vth [b][kh][d][t] fp16
__global__ void __launch_bounds__(256) conv_vt_k() {
    __shared__ __half tile[64][72];
    int tt = blockIdx.x, kh = blockIdx.y, b = blockIdx.z;
    int tid = threadIdx.x;
#pragma unroll
    for (int i = 0; i < 2; i++) {
        int seg = tid + i * 256;
        int r = seg >> 3, c = (seg & 7) * 8;
        *(uint4*)&tile[r][c] =
            *(const uint4*)&g_vh[(((size_t)b * T_SEQ + tt * 64 + r) * NKV + kh) * HD + c];
    }
    __syncthreads();
    int d = tid >> 2, tg = (tid & 3) * 16;
    size_t o = (((size_t)b * NKV + kh) * HD + d) * T_SEQ + tt * 64 + tg;
#pragma unroll
    for (int j = 0; j < 8; j++) {
        __half2 h2;
        h2.x = tile[tg + 2 * j][d];
        h2.y = tile[tg + 2 * j + 1][d];
        *(__half2*)(g_vth + o + 2 * j) = h2;
    }
}

// ---------------------------------------------------------------------------
// fp16 GEMM mainloop: 3-stage cp.async pipeline, one sync per chunk.
// 8 warps (4M x 2N), warp tile 32x64, K-chunk 64.
// ---------------------------------------------------------------------------
#define KC2 64
#define LDT2 72
#define TSB2 (128 * LDT2 * 2)    // 18432
#define BUF2 (2 * TSB2)          // 36864 (A + B)
#define GEMM_SMEM3 (3 * BUF2)    // 110592

static __device__ __forceinline__ void gemm_mainloop(
    const __half* __restrict__ A, const __half* __restrict__ B,
    int m0, float acc[2][8][4]) {

    extern __shared__ __half dsm[];
    uint32_t sbase = s2u(dsm);

    int tid  = threadIdx.x;
    int wid  = tid >> 5;
    int lane = tid & 31;
    int wm   = wid >> 1;
    int wn   = wid & 1;

    uint32_t offA = (uint32_t)(wm * 32 + (lane & 15)) * (LDT2 * 2) + (lane >> 4) * 16;
    int rB = wn * 64 + ((lane >> 3) & 1) * 8 + (lane & 7);
    uint32_t offB = (uint32_t)rB * (LDT2 * 2) + (lane >> 4) * 16;

    // Rolling source pointers (advance by KC2 per issued chunk)
    const __half* ap[4];
    const __half* bp[4];
    uint32_t ld[4];
#pragma unroll
    for (int i = 0; i < 4; i++) {
        int idx = tid + i * 256;
        int r  = idx >> 3;
        int sn = (idx & 7) * 8;
        ld[i] = (uint32_t)r * (LDT2 * 2) + sn * 2;
        ap[i] = A + (size_t)(m0 + r) * C_DIM + sn;
        bp[i] = B + (size_t)r * C_DIM + sn;
    }

#define G_LOAD(buf) do {                                                       \
    uint32_t so = sbase + (buf) * BUF2;                                        \
    _Pragma("unroll")                                                          \
    for (int i = 0; i < 4; i++) {                                              \
        CP_ASYNC16(so + ld[i], ap[i]);                                         \
        CP_ASYNC16(so + TSB2 + ld[i], bp[i]);                                  \
        ap[i] += KC2; bp[i] += KC2;                                            \
    }                                                                          \
    CP_COMMIT();                                                               \
} while (0)

    G_LOAD(0);
    G_LOAD(1);

    const int NCH = C_DIM / KC2;   // 16
    int buf = 0, lb = 2;
    for (int ch = 0; ch < NCH; ch++) {
        if (ch + 1 < NCH) CP_WAIT1(); else CP_WAIT0();
        __syncthreads();
        if (ch + 2 < NCH) {
            G_LOAD(lb);
            lb = (lb == 2) ? 0 : lb + 1;
        }

        uint32_t aA = sbase + buf * BUF2 + offA;
        uint32_t aB = sbase + buf * BUF2 + TSB2 + offB;

#pragma unroll
        for (int ks = 0; ks < 4; ks++) {
            uint32_t koff = ks * 32;
            uint32_t a[2][4], b[4][4];
#pragma unroll
            for (int mi = 0; mi < 2; mi++)
                ldsm4(a[mi], aA + mi * 16 * (LDT2 * 2) + koff);
#pragma unroll
            for (int njp = 0; njp < 4; njp++)
                ldsm4(b[njp], aB + njp * 16 * (LDT2 * 2) + koff);
#pragma unroll
            for (int mi = 0; mi < 2; mi++)
#pragma unroll
                for (int njp = 0; njp < 4; njp++) {
                    uint32_t be[2] = {b[njp][0], b[njp][2]};
                    uint32_t bo[2] = {b[njp][1], b[njp][3]};
                    mma16816h(acc[mi][2 * njp + 0], a[mi], be);
                    mma16816h(acc[mi][2 * njp + 1], a[mi], bo);
                }
        }
        buf = (buf == 2) ? 0 : buf + 1;
    }
#undef G_LOAD
}

// ---------------------------------------------------------------------------
// QKV GEMM with fused epilogues (validated round-9 logic)
// ---------------------------------------------------------------------------
__global__ void __launch_bounds__(256, 2) qkv_tc_k(const float* __restrict__ cosp,
                                                   const float* __restrict__ sinp,
                                                   const float* __restrict__ wb) {
    int mt = blockIdx.x, nb = blockIdx.y;
    int n0 = nb * 128;
    int m0 = mt * 128;

    float acc[2][8][4];
#pragma unroll
    for (int mi = 0; mi < 2; mi++)
#pragma unroll
        for (int nj = 0; nj < 8; nj++)
#pragma unroll
            for (int u = 0; u < 4; u++) acc[mi][nj][u] = 0.f;

    gemm_mainloop(g_xh, g_wh + (size_t)n0 * C_DIM, m0, acc);

    int tid  = threadIdx.x;
    int wid  = tid >> 5;
    int lane = tid & 31;
    int wm   = wid >> 1;
    int wn   = wid & 1;
    int erow = wm * 32 + (lane >> 2);
    int e    = (lane & 3) * 2;

    if (nb < 12) {
        float* souts;
        int nheads, hh;
        if (nb < 8) { souts = g_sq; nheads = NH;  hh = 2 * nb + wn; }
        else        { souts = g_sk; nheads = NKV; hh = 2 * (nb - 8) + wn; }

#pragma unroll
        for (int mi = 0; mi < 2; mi++)
#pragma unroll
            for (int hf = 0; hf < 2; hf++) {
                int r = erow + mi * 16 + hf * 8;
                int m = m0 + r;
                int t = m & (T_SEQ - 1);
                int b = m >> 11;
                int ub = hf * 2;
                const float* cr = cosp + t * 32;
                const float* sr = sinp + t * 32;
                float ssum = 0.f, dsum = 0.f;
#pragma unroll
                for (int nj = 0; nj < 4; nj++)
#pragma unroll
                    for (int u = 0; u < 2; u++) {
                        int d = e + u + nj * 8;
                        float x1 = acc[mi][nj][ub + u];
                        float x2 = acc[mi][nj + 4][ub + u];
                        float c = cr[d], s = sr[d];
                        float o1 = x1 * c + x2 * s;
                        float o2 = x2 * c - x1 * s;
                        ssum += o1 * o1 + o2 * o2;
                        dsum += o1 * wb[d] + o2 * wb[d + 32];
                    }
                ssum += __shfl_xor_sync(0xffffffffu, ssum, 1);
                dsum += __shfl_xor_sync(0xffffffffu, dsum, 1);
                ssum += __shfl_xor_sync(0xffffffffu, ssum, 2);
                dsum += __shfl_xor_sync(0xffffffffu, dsum, 2);
                if ((lane & 3) == 0) {
                    float scale = rsqrtf(ssum * (1.f / 64.f) + 1e-6f);
                    souts[((size_t)b * nheads + hh) * T_SEQ + t] = dsum * scale;
                }
            }
    } else {
        int kh = 2 * (nb - 12) + wn;
#pragma unroll
        for (int mi = 0; mi < 2; mi++)
#pragma unroll
            for (int hf = 0; hf < 2; hf++) {
                int r = erow + mi * 16 + hf * 8;
                int m = m0 + r;
                int t = m & (T_SEQ - 1);
                int b = m >> 11;
                int ub = hf * 2;
                __half* vp = g_vh + (((size_t)b * T_SEQ + t) * NKV + kh) * HD;
#pragma unroll
                for (int nj = 0; nj < 8; nj++)
                    *(__half2*)(vp + e + nj * 8) =
                        __floats2half2_rn(acc[mi][nj][ub], acc[mi][nj][ub + 1]);
            }
    }
}

// ---------------------------------------------------------------------------
// Proj GEMM
// ---------------------------------------------------------------------------
__global__ void __launch_bounds__(256, 2) proj_tc_k(float* __restrict__ out) {
    int mt = blockIdx.x, nb = blockIdx.y;
    int m0 = mt * 128;

    float acc[2][8][4];
#pragma unroll
    for (int mi = 0; mi < 2; mi++)
#pragma unroll
        for (int nj = 0; nj < 8; nj++)
#pragma unroll
            for (int u = 0; u < 4; u++) acc[mi][nj][u] = 0.f;

    gemm_mainloop(g_yh, g_wph + (size_t)nb * 128 * C_DIM, m0, acc);

    int tid  = threadIdx.x;
    int wid  = tid >> 5;
    int lane = tid & 31;
    int wm   = wid >> 1;
    int wn   = wid & 1;
    int erow = wm * 32 + (lane >> 2);
    int ecol = wn * 64 + (lane & 3) * 2;
#pragma unroll
    for (int mi = 0; mi < 2; mi++)
#pragma unroll
        for (int nj = 0; nj < 8; nj++) {
            int row = erow + mi * 16;
            int col = nb * 128 + ecol + nj * 8;
            float* p0 = out + (size_t)(m0 + row) * C_DIM + col;
            float* p1 = out + (size_t)(m0 + row + 8) * C_DIM + col;
            *(float2*)p0 = make_float2(acc[mi][nj][0], acc[mi][nj][1]);
            *(float2*)p1 = make_float2(acc[mi][nj][2], acc[mi][nj][3]);
        }
}

// ---------------------------------------------------------------------------
// Attention, single-pass fp16, 3-stage pipeline, one sync per chunk.
// ---------------------------------------------------------------------------
#define ALDS 72
#define AVROW (ALDS * 2)
#define AVBUF (64 * AVROW)

__global__ void __launch_bounds__(256, 2) attn_tc_k() {
    __shared__ __align__(16) __half Vh[3][64][ALDS];
    __shared__ float SQ[128];
    __shared__ __align__(16) float SK[3][64];

    int tt = (T_SEQ / 64 - 1) - blockIdx.x;
    int kh = blockIdx.y;
    int b  = blockIdx.z;
    int t0 = tt * 64;

    int tid  = threadIdx.x;
    int wid  = tid >> 5;
    int lane = tid & 31;

    if (tid < 128) {
        int hl = tid >> 6, tl = tid & 63;
        SQ[tid] = g_sq[((size_t)b * NH + kh * 2 + hl) * T_SEQ + t0 + tl];
    }

    const __half* gvh = g_vth + ((size_t)b * NKV + kh) * HD * T_SEQ;
    const float* gsk = g_sk + ((size_t)b * NKV + kh) * T_SEQ;

    uint32_t sVh = s2u(Vh), sSK = s2u(SK);

    int vr0 = tid >> 3,         vs0 = (tid & 7) * 8;
    int vr1 = (tid + 256) >> 3, vs1 = ((tid + 256) & 7) * 8;
    uint32_t vd0 = (uint32_t)vr0 * AVROW + vs0 * 2;
    uint32_t vd1 = (uint32_t)vr1 * AVROW + vs1 * 2;

    const __half* vp0 = gvh + (size_t)vr0 * T_SEQ + vs0;
    const __half* vp1 = gvh + (size_t)vr1 * T_SEQ + vs1;
    const float*  skp = gsk + (tid & 15) * 4;

#define AV_LOAD(buf) do {                                                      \
    uint32_t bo = (buf) * AVBUF;                                               \
    CP_ASYNC16(sVh + bo + vd0, vp0);                                           \
    CP_ASYNC16(sVh + bo + vd1, vp1);                                           \
    if (tid < 16) CP_ASYNC16(sSK + (buf) * 256 + tid * 16, skp);               \
    vp0 += 64; vp1 += 64; skp += 64;                                           \
    CP_COMMIT();                                                               \
} while (0)

    float acc[8][4];
#pragma unroll
    for (int nj = 0; nj < 8; nj++)
#pragma unroll
        for (int u = 0; u < 4; u++) acc[nj][u] = 0.f;

    int r  = lane >> 2;
    int c2 = (lane & 3) * 2;
    int row0 = wid * 16 + r;
    int tl0 = row0 & 63, tl1 = (row0 + 8) & 63;

    int rB = ((lane >> 3) & 1) * 8 + (lane & 7);
    uint32_t offB = (uint32_t)rB * AVROW + (lane >> 4) * 16;

    AV_LOAD(0);
    AV_LOAD(1);
    __syncthreads();   // SQ visible

    float sq0 = SQ[row0] * 0.5f, sq1 = SQ[row0 + 8] * 0.5f;
    const __half2 half05 = __floats2half2_rn(0.5f, 0.5f);

    const int NCH = tt + 1;
    int buf = 0, lb = 2;
    for (int ch = 0; ch < NCH; ch++) {
        if (ch + 1 < NCH) CP_WAIT1(); else CP_WAIT0();
        __syncthreads();
        if (ch + 2 < NCH) {
            AV_LOAD(lb);
            lb = (lb == 2) ? 0 : lb + 1;
        }

        bool diag = (ch == tt);
        const float* SKb = SK[buf];
        uint32_t vbh = sVh + buf * AVBUF + offB;

#pragma unroll 2
        for (int ks = 0; ks < 4; ks++) {
            int kb = ks * 16 + c2;
            float sk0 = SKb[kb] * 0.5f,     sk1 = SKb[kb + 1] * 0.5f;
            float sk8 = SKb[kb + 8] * 0.5f, sk9 = SKb[kb + 9] * 0.5f;

            uint32_t ah[4];
            {
                __half2 z0 = __floats2half2_rn(sq0 + sk0, sq0 + sk1);
                __half2 z1 = __floats2half2_rn(sq1 + sk0, sq1 + sk1);
                __half2 z2 = __floats2half2_rn(sq0 + sk8, sq0 + sk9);
                __half2 z3 = __floats2half2_rn(sq1 + sk8, sq1 + sk9);
                __half2 p0, p1, p2, p3;
                *(uint32_t*)&p0 = tanh2(*(uint32_t*)&z0);
                *(uint32_t*)&p1 = tanh2(*(uint32_t*)&z1);
                *(uint32_t*)&p2 = tanh2(*(uint32_t*)&z2);
                *(uint32_t*)&p3 = tanh2(*(uint32_t*)&z3);
                p0 = __hfma2(p0, half05, half05);
                p1 = __hfma2(p1, half05, half05);
                p2 = __hfma2(p2, half05, half05);
                p3 = __hfma2(p3, half05, half05);
                if (diag) {
                    __half2 m0 = __floats2half2_rn(kb <= tl0 ? 1.f : 0.f,
                                                   kb + 1 <= tl0 ? 1.f : 0.f);
                    __half2 m1 = __floats2half2_rn(kb <= tl1 ? 1.f : 0.f,
                                                   kb + 1 <= tl1 ? 1.f : 0.f);
                    __half2 m2 = __floats2half2_rn(kb + 8 <= tl0 ? 1.f : 0.f,
                                                   kb + 9 <= tl0 ? 1.f : 0.f);
                    __half2 m3 = __floats2half2_rn(kb + 8 <= tl1 ? 1.f : 0.f,
                                                   kb + 9 <= tl1 ? 1.f : 0.f);
                    p0 = __hmul2(p0, m0);
                    p1 = __hmul2(p1, m1);
                    p2 = __hmul2(p2, m2);
                    p3 = __hmul2(p3, m3);
                }
                ah[0] = *(uint32_t*)&p0;
                ah[1] = *(uint32_t*)&p1;
                ah[2] = *(uint32_t*)&p2;
                ah[3] = *(uint32_t*)&p3;
            }

            uint32_t bh[4][4];
#pragma unroll
            for (int njp = 0; njp < 4; njp++)
                ldsm4(bh[njp], vbh + njp * 16 * AVROW + ks * 32);
#pragma unroll
            for (int njp = 0; njp < 4; njp++) {
                uint32_t be[2] = {bh[njp][0], bh[njp][2]};
                uint32_t bo[2] = {bh[njp][1], bh[njp][3]};
                mma16816h(acc[2 * njp + 0], ah, be);
                mma16816h(acc[2 * njp + 1], ah, bo);
            }
        }
        buf = (buf == 2) ? 0 : buf + 1;
    }

    const float inv = 1.f / (sqrtf((float)T_SEQ) + 1e-6f);
    int hgl = kh * 2 + (row0 >> 6);
    int tA = t0 + tl0, tB = t0 + tl1;
    __half* yA = g_yh + (((size_t)b * T_SEQ + tA) * NH + hgl) * HD;
    __half* yB = g_yh + (((size_t)b * T_SEQ + tB) * NH + hgl) * HD;
#pragma unroll
    for (int nj = 0; nj < 8; nj++) {
        int d = nj * 8 + c2;
        *(__half2*)(yA + d) = __floats2half2_rn(acc[nj][0] * inv, acc[nj][1] * inv);
        *(__half2*)(yB + d) = __floats2half2_rn(acc[nj][2] * inv, acc[nj][3] * inv);
    }
}

// ---------------------------------------------------------------------------
extern "C" void kernel_launch(void* const* d_in, const int* in_sizes, int n_in,
                              void* d_out, int out_size) {
    const float* x    = (const float*)d_in[0];
    const float* cosp = (const float*)d_in[1];
    const float* sinp = (const float*)d_in[2];
    const float* Wq   = (const float*)d_in[3];
    const float* Wk   = (const float*)d_in[4];
    const float* Wv   = (const float*)d_in[5];
    const float* Wp   = (const float*)d_in[6];
    const float* wb   = (const float*)d_in[7];
    float* out = (float*)d_out;

    cudaFuncSetAttribute(qkv_tc_k,  cudaFuncAttributeMaxDynamicSharedMemorySize, GEMM_SMEM3);
    cudaFuncSetAttribute(proj_tc_k, cudaFuncAttributeMaxDynamicSharedMemorySize, GEMM_SMEM3);

    conv_all_k<<<7168, 256>>>(x, Wq, Wk, Wv, Wp);

    qkv_tc_k<<<dim3(32, 16), 256, GEMM_SMEM3>>>(cosp, sinp, wb);

    conv_vt_k<<<dim3(T_SEQ / 64, NKV, BATCH), 256>>>();

    attn_tc_k<<<dim3(T_SEQ / 64, NKV, BATCH), 256>>>();

    proj_tc_k<<<dim3(32, 8), 256, GEMM_SMEM3>>>(out);
}

// round 11
// speedup vs baseline: 7.7149x; 1.0154x over previous
#include <cuda_runtime.h>
#include <cuda_fp16.h>
#include <math.h>
#include <stdint.h>

#define BATCH 2
#define T_SEQ 2048
#define C_DIM 1024
#define NH 16
#define NKV 8
#define HD 64
#define M_ROWS (BATCH * T_SEQ)   // 4096

// ---------------------------------------------------------------------------
// Scratch (__device__ globals)
// ---------------------------------------------------------------------------
__device__ __half g_sqh[BATCH * NH * T_SEQ];   // 0.5 * braid-q scalar, fp16
__device__ __half g_skh[BATCH * NKV * T_SEQ];  // 0.5 * braid-k scalar, fp16

__device__ __half g_xh[M_ROWS * C_DIM];
__device__ __half g_wh[2048 * C_DIM];     // 0-1023 Wq, 1024-1535 Wk, 1536-2047 Wv
__device__ __half g_wph[C_DIM * C_DIM];
__device__ __half g_yh[M_ROWS * C_DIM];   // attn output, [b][t][h][d]
__device__ __half g_vh[M_ROWS * NKV * HD];          // V fp16 [b][t][kh][d]
__device__ __half g_vth[BATCH * NKV * HD * T_SEQ];  // V^T [b][kh][d][t]

// ---------------------------------------------------------------------------
// PTX helpers
// ---------------------------------------------------------------------------
static __device__ __forceinline__ uint32_t s2u(const void* p) {
    uint32_t a;
    asm("{ .reg .u64 t; cvta.to.shared.u64 t, %1; cvt.u32.u64 %0, t; }"
        : "=r"(a) : "l"(p));
    return a;
}
static __device__ __forceinline__ void ldsm4(uint32_t* r, uint32_t addr) {
    asm volatile("ldmatrix.sync.aligned.m8n8.x4.shared.b16 {%0,%1,%2,%3}, [%4];"
                 : "=r"(r[0]), "=r"(r[1]), "=r"(r[2]), "=r"(r[3]) : "r"(addr));
}
static __device__ __forceinline__ void mma16816h(float* c, const uint32_t* a,
                                                 const uint32_t* b) {
    asm volatile(
        "mma.sync.aligned.m16n8k16.row.col.f32.f16.f16.f32 "
        "{%0,%1,%2,%3}, {%4,%5,%6,%7}, {%8,%9}, {%0,%1,%2,%3};"
        : "+f"(c[0]), "+f"(c[1]), "+f"(c[2]), "+f"(c[3])
        : "r"(a[0]), "r"(a[1]), "r"(a[2]), "r"(a[3]), "r"(b[0]), "r"(b[1]));
}
static __device__ __forceinline__ uint32_t tanh2(uint32_t x) {
    uint32_t o;
    asm("tanh.approx.f16x2 %0, %1;" : "=r"(o) : "r"(x));
    return o;
}
#define CP_ASYNC16(dst, src) \
    asm volatile("cp.async.cg.shared.global [%0], [%1], 16;" :: "r"(dst), "l"(src))
#define CP_COMMIT() asm volatile("cp.async.commit_group;" ::: "memory")
#define CP_WAIT1()  asm volatile("cp.async.wait_group 1;" ::: "memory")
#define CP_WAIT0()  asm volatile("cp.async.wait_group 0;" ::: "memory")

// ---------------------------------------------------------------------------
// Merged fp32 -> fp16 conversion: x | Wq/Wk/Wv | Wp
// ---------------------------------------------------------------------------
__global__ void __launch_bounds__(256) conv_all_k(const float* __restrict__ x,
                                                  const float* __restrict__ Wq,
                                                  const float* __restrict__ Wk,
                                                  const float* __restrict__ Wv,
                                                  const float* __restrict__ Wp) {
    int i = blockIdx.x * blockDim.x + threadIdx.x;   // float4 index
    const float* src;
    int rel;
    if (i < 1048576) {
        float4 v = *(const float4*)(x + (size_t)i * 4);
        *(__half2*)(g_xh + (size_t)i * 4)     = __floats2half2_rn(v.x, v.y);
        *(__half2*)(g_xh + (size_t)i * 4 + 2) = __floats2half2_rn(v.z, v.w);
    } else if (i < 1572864) {
        int wrel = i - 1048576;
        if (wrel < 262144)      { src = Wq; rel = wrel; }
        else if (wrel < 393216) { src = Wk; rel = wrel - 262144; }
        else                    { src = Wv; rel = wrel - 393216; }
        float4 v = *(const float4*)(src + (size_t)rel * 4);
        *(__half2*)(g_wh + (size_t)wrel * 4)     = __floats2half2_rn(v.x, v.y);
        *(__half2*)(g_wh + (size_t)wrel * 4 + 2) = __floats2half2_rn(v.z, v.w);
    } else {
        rel = i - 1572864;
        float4 v = *(const float4*)(Wp + (size_t)rel * 4);
        *(__half2*)(g_wph + (size_t)rel * 4)     = __floats2half2_rn(v.x, v.y);
        *(__half2*)(g_wph + (size_t)rel * 4 + 2) = __floats2half2_rn(v.z, v.w);
    }
}

// V transpose: g_vh [b][t][kh][d] fp16 -> g_vth [b][kh][d][t] fp16
__global__ void __launch_bounds__(256) conv_vt_k() {
    __shared__ __half tile[64][72];
    int tt = blockIdx.x, kh = blockIdx.y, b = blockIdx.z;
    int tid = threadIdx.x;
#pragma unroll
    for (int i = 0; i < 2; i++) {
        int seg = tid + i * 256;
        int r = seg >> 3, c = (seg & 7) * 8;
        *(uint4*)&tile[r][c] =
            *(const uint4*)&g_vh[(((size_t)b * T_SEQ + tt * 64 + r) * NKV + kh) * HD + c];
    }
    __syncthreads();
    int d = tid >> 2, tg = (tid & 3) * 16;
    size_t o = (((size_t)b * NKV + kh) * HD + d) * T_SEQ + tt * 64 + tg;
#pragma unroll
    for (int j = 0; j < 8; j++) {
        __half2 h2;
        h2.x = tile[tg + 2 * j][d];
        h2.y = tile[tg + 2 * j + 1][d];
        *(__half2*)(g_vth + o + 2 * j) = h2;
    }
}

// ---------------------------------------------------------------------------
// fp16 GEMM mainloop: 3-stage cp.async pipeline, one sync per chunk.
// ---------------------------------------------------------------------------
#define KC2 64
#define LDT2 72
#define TSB2 (128 * LDT2 * 2)    // 18432
#define BUF2 (2 * TSB2)          // 36864
#define GEMM_SMEM3 (3 * BUF2)    // 110592

static __device__ __forceinline__ void gemm_mainloop(
    const __half* __restrict__ A, const __half* __restrict__ B,
    int m0, float acc[2][8][4]) {

    extern __shared__ __half dsm[];
    uint32_t sbase = s2u(dsm);

    int tid  = threadIdx.x;
    int wid  = tid >> 5;
    int lane = tid & 31;
    int wm   = wid >> 1;
    int wn   = wid & 1;

    uint32_t offA = (uint32_t)(wm * 32 + (lane & 15)) * (LDT2 * 2) + (lane >> 4) * 16;
    int rB = wn * 64 + ((lane >> 3) & 1) * 8 + (lane & 7);
    uint32_t offB = (uint32_t)rB * (LDT2 * 2) + (lane >> 4) * 16;

    const __half* ap[4];
    const __half* bp[4];
    uint32_t ld[4];
#pragma unroll
    for (int i = 0; i < 4; i++) {
        int idx = tid + i * 256;
        int r  = idx >> 3;
        int sn = (idx & 7) * 8;
        ld[i] = (uint32_t)r * (LDT2 * 2) + sn * 2;
        ap[i] = A + (size_t)(m0 + r) * C_DIM + sn;
        bp[i] = B + (size_t)r * C_DIM + sn;
    }

#define G_LOAD(buf) do {                                                       \
    uint32_t so = sbase + (buf) * BUF2;                                        \
    _Pragma("unroll")                                                          \
    for (int i = 0; i < 4; i++) {                                              \
        CP_ASYNC16(so + ld[i], ap[i]);                                         \
        CP_ASYNC16(so + TSB2 + ld[i], bp[i]);                                  \
        ap[i] += KC2; bp[i] += KC2;                                            \
    }                                                                          \
    CP_COMMIT();                                                               \
} while (0)

    G_LOAD(0);
    G_LOAD(1);

    const int NCH = C_DIM / KC2;
    int buf = 0, lb = 2;
    for (int ch = 0; ch < NCH; ch++) {
        if (ch + 1 < NCH) CP_WAIT1(); else CP_WAIT0();
        __syncthreads();
        if (ch + 2 < NCH) {
            G_LOAD(lb);
            lb = (lb == 2) ? 0 : lb + 1;
        }

        uint32_t aA = sbase + buf * BUF2 + offA;
        uint32_t aB = sbase + buf * BUF2 + TSB2 + offB;

#pragma unroll
        for (int ks = 0; ks < 4; ks++) {
            uint32_t koff = ks * 32;
            uint32_t a[2][4], b[4][4];
#pragma unroll
            for (int mi = 0; mi < 2; mi++)
                ldsm4(a[mi], aA + mi * 16 * (LDT2 * 2) + koff);
#pragma unroll
            for (int njp = 0; njp < 4; njp++)
                ldsm4(b[njp], aB + njp * 16 * (LDT2 * 2) + koff);
#pragma unroll
            for (int mi = 0; mi < 2; mi++)
#pragma unroll
                for (int njp = 0; njp < 4; njp++) {
                    uint32_t be[2] = {b[njp][0], b[njp][2]};
                    uint32_t bo[2] = {b[njp][1], b[njp][3]};
                    mma16816h(acc[mi][2 * njp + 0], a[mi], be);
                    mma16816h(acc[mi][2 * njp + 1], a[mi], bo);
                }
        }
        buf = (buf == 2) ? 0 : buf + 1;
    }
#undef G_LOAD
}

// ---------------------------------------------------------------------------
// QKV GEMM with fused epilogues; braid scalars written as fp16 * 0.5.
// ---------------------------------------------------------------------------
__global__ void __launch_bounds__(256, 2) qkv_tc_k(const float* __restrict__ cosp,
                                                   const float* __restrict__ sinp,
                                                   const float* __restrict__ wb) {
    int mt = blockIdx.x, nb = blockIdx.y;
    int n0 = nb * 128;
    int m0 = mt * 128;

    float acc[2][8][4];
#pragma unroll
    for (int mi = 0; mi < 2; mi++)
#pragma unroll
        for (int nj = 0; nj < 8; nj++)
#pragma unroll
            for (int u = 0; u < 4; u++) acc[mi][nj][u] = 0.f;

    gemm_mainloop(g_xh, g_wh + (size_t)n0 * C_DIM, m0, acc);

    int tid  = threadIdx.x;
    int wid  = tid >> 5;
    int lane = tid & 31;
    int wm   = wid >> 1;
    int wn   = wid & 1;
    int erow = wm * 32 + (lane >> 2);
    int e    = (lane & 3) * 2;

    if (nb < 12) {
        __half* souts;
        int nheads, hh;
        if (nb < 8) { souts = g_sqh; nheads = NH;  hh = 2 * nb + wn; }
        else        { souts = g_skh; nheads = NKV; hh = 2 * (nb - 8) + wn; }

#pragma unroll
        for (int mi = 0; mi < 2; mi++)
#pragma unroll
            for (int hf = 0; hf < 2; hf++) {
                int r = erow + mi * 16 + hf * 8;
                int m = m0 + r;
                int t = m & (T_SEQ - 1);
                int b = m >> 11;
                int ub = hf * 2;
                const float* cr = cosp + t * 32;
                const float* sr = sinp + t * 32;
                float ssum = 0.f, dsum = 0.f;
#pragma unroll
                for (int nj = 0; nj < 4; nj++)
#pragma unroll
                    for (int u = 0; u < 2; u++) {
                        int d = e + u + nj * 8;
                        float x1 = acc[mi][nj][ub + u];
                        float x2 = acc[mi][nj + 4][ub + u];
                        float c = cr[d], s = sr[d];
                        float o1 = x1 * c + x2 * s;
                        float o2 = x2 * c - x1 * s;
                        ssum += o1 * o1 + o2 * o2;
                        dsum += o1 * wb[d] + o2 * wb[d + 32];
                    }
                ssum += __shfl_xor_sync(0xffffffffu, ssum, 1);
                dsum += __shfl_xor_sync(0xffffffffu, dsum, 1);
                ssum += __shfl_xor_sync(0xffffffffu, ssum, 2);
                dsum += __shfl_xor_sync(0xffffffffu, dsum, 2);
                if ((lane & 3) == 0) {
                    float scale = rsqrtf(ssum * (1.f / 64.f) + 1e-6f);
                    souts[((size_t)b * nheads + hh) * T_SEQ + t] =
                        __float2half(dsum * scale * 0.5f);
                }
            }
    } else {
        int kh = 2 * (nb - 12) + wn;
#pragma unroll
        for (int mi = 0; mi < 2; mi++)
#pragma unroll
            for (int hf = 0; hf < 2; hf++) {
                int r = erow + mi * 16 + hf * 8;
                int m = m0 + r;
                int t = m & (T_SEQ - 1);
                int b = m >> 11;
                int ub = hf * 2;
                __half* vp = g_vh + (((size_t)b * T_SEQ + t) * NKV + kh) * HD;
#pragma unroll
                for (int nj = 0; nj < 8; nj++)
                    *(__half2*)(vp + e + nj * 8) =
                        __floats2half2_rn(acc[mi][nj][ub], acc[mi][nj][ub + 1]);
            }
    }
}

// ---------------------------------------------------------------------------
// Proj GEMM
// ---------------------------------------------------------------------------
__global__ void __launch_bounds__(256, 2) proj_tc_k(float* __restrict__ out) {
    int mt = blockIdx.x, nb = blockIdx.y;
    int m0 = mt * 128;

    float acc[2][8][4];
#pragma unroll
    for (int mi = 0; mi < 2; mi++)
#pragma unroll
        for (int nj = 0; nj < 8; nj++)
#pragma unroll
            for (int u = 0; u < 4; u++) acc[mi][nj][u] = 0.f;

    gemm_mainloop(g_yh, g_wph + (size_t)nb * 128 * C_DIM, m0, acc);

    int tid  = threadIdx.x;
    int wid  = tid >> 5;
    int lane = tid & 31;
    int wm   = wid >> 1;
    int wn   = wid & 1;
    int erow = wm * 32 + (lane >> 2);
    int ecol = wn * 64 + (lane & 3) * 2;
#pragma unroll
    for (int mi = 0; mi < 2; mi++)
#pragma unroll
        for (int nj = 0; nj < 8; nj++) {
            int row = erow + mi * 16;
            int col = nb * 128 + ecol + nj * 8;
            float* p0 = out + (size_t)(m0 + row) * C_DIM + col;
            float* p1 = out + (size_t)(m0 + row + 8) * C_DIM + col;
            *(float2*)p0 = make_float2(acc[mi][nj][0], acc[mi][nj][1]);
            *(float2*)p1 = make_float2(acc[mi][nj][2], acc[mi][nj][3]);
        }
}

// ---------------------------------------------------------------------------
// Attention, fp16 P-chain: z via HADD2 on pre-halved fp16 scalars.
// ---------------------------------------------------------------------------
#define ALDS 72
#define AVROW (ALDS * 2)
#define AVBUF (64 * AVROW)

__global__ void __launch_bounds__(256, 2) attn_tc_k() {
    __shared__ __align__(16) __half Vh[3][64][ALDS];
    __shared__ __half SQ[128];
    __shared__ __align__(16) __half SK[3][64];

    int tt = (T_SEQ / 64 - 1) - blockIdx.x;
    int kh = blockIdx.y;
    int b  = blockIdx.z;
    int t0 = tt * 64;

    int tid  = threadIdx.x;
    int wid  = tid >> 5;
    int lane = tid & 31;

    if (tid < 128) {
        int hl = tid >> 6, tl = tid & 63;
        SQ[tid] = g_sqh[((size_t)b * NH + kh * 2 + hl) * T_SEQ + t0 + tl];
    }

    const __half* gvh = g_vth + ((size_t)b * NKV + kh) * HD * T_SEQ;
    const __half* gsk = g_skh + ((size_t)b * NKV + kh) * T_SEQ;

    uint32_t sVh = s2u(Vh), sSK = s2u(SK);

    int vr0 = tid >> 3,         vs0 = (tid & 7) * 8;
    int vr1 = (tid + 256) >> 3, vs1 = ((tid + 256) & 7) * 8;
    uint32_t vd0 = (uint32_t)vr0 * AVROW + vs0 * 2;
    uint32_t vd1 = (uint32_t)vr1 * AVROW + vs1 * 2;

    const __half* vp0 = gvh + (size_t)vr0 * T_SEQ + vs0;
    const __half* vp1 = gvh + (size_t)vr1 * T_SEQ + vs1;
    const __half* skp = gsk + (tid & 7) * 8;

#define AV_LOAD(buf) do {                                                      \
    uint32_t bo = (buf) * AVBUF;                                               \
    CP_ASYNC16(sVh + bo + vd0, vp0);                                           \
    CP_ASYNC16(sVh + bo + vd1, vp1);                                           \
    if (tid < 8) CP_ASYNC16(sSK + (buf) * 128 + tid * 16, skp);                \
    vp0 += 64; vp1 += 64; skp += 64;                                           \
    CP_COMMIT();                                                               \
} while (0)

    float acc[8][4];
#pragma unroll
    for (int nj = 0; nj < 8; nj++)
#pragma unroll
        for (int u = 0; u < 4; u++) acc[nj][u] = 0.f;

    int r  = lane >> 2;
    int c2 = (lane & 3) * 2;
    int row0 = wid * 16 + r;
    int tl0 = row0 & 63, tl1 = (row0 + 8) & 63;

    int rB = ((lane >> 3) & 1) * 8 + (lane & 7);
    uint32_t offB = (uint32_t)rB * AVROW + (lane >> 4) * 16;

    AV_LOAD(0);
    AV_LOAD(1);
    __syncthreads();   // SQ visible

    __half2 sq0h = __half2half2(SQ[row0]);
    __half2 sq1h = __half2half2(SQ[row0 + 8]);
    const __half2 half05 = __floats2half2_rn(0.5f, 0.5f);

    const int NCH = tt + 1;
    int buf = 0, lb = 2;
    for (int ch = 0; ch < NCH; ch++) {
        if (ch + 1 < NCH) CP_WAIT1(); else CP_WAIT0();
        __syncthreads();
        if (ch + 2 < NCH) {
            AV_LOAD(lb);
            lb = (lb == 2) ? 0 : lb + 1;
        }

        bool diag = (ch == tt);
        const __half* SKb = SK[buf];
        uint32_t vbh = sVh + buf * AVBUF + offB;

#pragma unroll 2
        for (int ks = 0; ks < 4; ks++) {
            int kb = ks * 16 + c2;
            __half2 s01 = *(const __half2*)&SKb[kb];
            __half2 s89 = *(const __half2*)&SKb[kb + 8];

            uint32_t ah[4];
            {
                __half2 z0 = __hadd2(sq0h, s01);
                __half2 z1 = __hadd2(sq1h, s01);
                __half2 z2 = __hadd2(sq0h, s89);
                __half2 z3 = __hadd2(sq1h, s89);
                __half2 p0, p1, p2, p3;
                *(uint32_t*)&p0 = tanh2(*(uint32_t*)&z0);
                *(uint32_t*)&p1 = tanh2(*(uint32_t*)&z1);
                *(uint32_t*)&p2 = tanh2(*(uint32_t*)&z2);
                *(uint32_t*)&p3 = tanh2(*(uint32_t*)&z3);
                p0 = __hfma2(p0, half05, half05);
                p1 = __hfma2(p1, half05, half05);
                p2 = __hfma2(p2, half05, half05);
                p3 = __hfma2(p3, half05, half05);
                if (diag) {
                    __half2 m0 = __floats2half2_rn(kb <= tl0 ? 1.f : 0.f,
                                                   kb + 1 <= tl0 ? 1.f : 0.f);
                    __half2 m1 = __floats2half2_rn(kb <= tl1 ? 1.f : 0.f,
                                                   kb + 1 <= tl1 ? 1.f : 0.f);
                    __half2 m2 = __floats2half2_rn(kb + 8 <= tl0 ? 1.f : 0.f,
                                                   kb + 9 <= tl0 ? 1.f : 0.f);
                    __half2 m3 = __floats2half2_rn(kb + 8 <= tl1 ? 1.f : 0.f,
                                                   kb + 9 <= tl1 ? 1.f : 0.f);
                    p0 = __hmul2(p0, m0);
                    p1 = __hmul2(p1, m1);
                    p2 = __hmul2(p2, m2);
                    p3 = __hmul2(p3, m3);
                }
                ah[0] = *(uint32_t*)&p0;
                ah[1] = *(uint32_t*)&p1;
                ah[2] = *(uint32_t*)&p2;
                ah[3] = *(uint32_t*)&p3;
            }

            uint32_t bh[4][4];
#pragma unroll
            for (int njp = 0; njp < 4; njp++)
                ldsm4(bh[njp], vbh + njp * 16 * AVROW + ks * 32);
#pragma unroll
            for (int njp = 0; njp < 4; njp++) {
                uint32_t be[2] = {bh[njp][0], bh[njp][2]};
                uint32_t bo[2] = {bh[njp][1], bh[njp][3]};
                mma16816h(acc[2 * njp + 0], ah, be);
                mma16816h(acc[2 * njp + 1], ah, bo);
            }
        }
        buf = (buf == 2) ? 0 : buf + 1;
    }

    const float inv = 1.f / (sqrtf((float)T_SEQ) + 1e-6f);
    int hgl = kh * 2 + (row0 >> 6);
    int tA = t0 + tl0, tB = t0 + tl1;
    __half* yA = g_yh + (((size_t)b * T_SEQ + tA) * NH + hgl) * HD;
    __half* yB = g_yh + (((size_t)b * T_SEQ + tB) * NH + hgl) * HD;
#pragma unroll
    for (int nj = 0; nj < 8; nj++) {
        int d = nj * 8 + c2;
        *(__half2*)(yA + d) = __floats2half2_rn(acc[nj][0] * inv, acc[nj][1] * inv);
        *(__half2*)(yB + d) = __floats2half2_rn(acc[nj][2] * inv, acc[nj][3] * inv);
    }
}

// ---------------------------------------------------------------------------
extern "C" void kernel_launch(void* const* d_in, const int* in_sizes, int n_in,
                              void* d_out, int out_size) {
    const float* x    = (const float*)d_in[0];
    const float* cosp = (const float*)d_in[1];
    const float* sinp = (const float*)d_in[2];
    const float* Wq   = (const float*)d_in[3];
    const float* Wk   = (const float*)d_in[4];
    const float* Wv   = (const float*)d_in[5];
    const float* Wp   = (const float*)d_in[6];
    const float* wb   = (const float*)d_in[7];
    float* out = (float*)d_out;

    cudaFuncSetAttribute(qkv_tc_k,  cudaFuncAttributeMaxDynamicSharedMemorySize, GEMM_SMEM3);
    cudaFuncSetAttribute(proj_tc_k, cudaFuncAttributeMaxDynamicSharedMemorySize, GEMM_SMEM3);

    conv_all_k<<<7168, 256>>>(x, Wq, Wk, Wv, Wp);

    qkv_tc_k<<<dim3(32, 16), 256, GEMM_SMEM3>>>(cosp, sinp, wb);

    conv_vt_k<<<dim3(T_SEQ / 64, NKV, BATCH), 256>>>();

    attn_tc_k<<<dim3(T_SEQ / 64, NKV, BATCH), 256>>>();

    proj_tc_k<<<dim3(32, 8), 256, GEMM_SMEM3>>>(out);
}

// round 12
// speedup vs baseline: 8.4840x; 1.0997x over previous
#include <cuda_runtime.h>
#include <cuda_fp16.h>
#include <math.h>
#include <stdint.h>

#define BATCH 2
#define T_SEQ 2048
#define C_DIM 1024
#define NH 16
#define NKV 8
#define HD 64
#define M_ROWS (BATCH * T_SEQ)   // 4096

// ---------------------------------------------------------------------------
// Scratch (__device__ globals)
// ---------------------------------------------------------------------------
__device__ __half g_sqh[BATCH * NH * T_SEQ];   // 0.5 * braid-q scalar, fp16
__device__ __half g_skh[BATCH * NKV * T_SEQ];  // 0.5 * braid-k scalar, fp16

__device__ __half g_xh[M_ROWS * C_DIM];
__device__ __half g_wh[2048 * C_DIM];     // 0-1023 Wq, 1024-1535 Wk, 1536-2047 Wv
__device__ __half g_wph[C_DIM * C_DIM];
__device__ __half g_yh[M_ROWS * C_DIM];   // attn output, [b][t][h][d]
__device__ __half g_vh[M_ROWS * NKV * HD];  // V fp16 [b][t][kh][d]

// ---------------------------------------------------------------------------
// PTX helpers
// ---------------------------------------------------------------------------
static __device__ __forceinline__ uint32_t s2u(const void* p) {
    uint32_t a;
    asm("{ .reg .u64 t; cvta.to.shared.u64 t, %1; cvt.u32.u64 %0, t; }"
        : "=r"(a) : "l"(p));
    return a;
}
static __device__ __forceinline__ void ldsm4(uint32_t* r, uint32_t addr) {
    asm volatile("ldmatrix.sync.aligned.m8n8.x4.shared.b16 {%0,%1,%2,%3}, [%4];"
                 : "=r"(r[0]), "=r"(r[1]), "=r"(r[2]), "=r"(r[3]) : "r"(addr));
}
static __device__ __forceinline__ void ldsm4t(uint32_t* r, uint32_t addr) {
    asm volatile("ldmatrix.sync.aligned.m8n8.x4.trans.shared.b16 {%0,%1,%2,%3}, [%4];"
                 : "=r"(r[0]), "=r"(r[1]), "=r"(r[2]), "=r"(r[3]) : "r"(addr));
}
static __device__ __forceinline__ void mma16816h(float* c, const uint32_t* a,
                                                 const uint32_t* b) {
    asm volatile(
        "mma.sync.aligned.m16n8k16.row.col.f32.f16.f16.f32 "
        "{%0,%1,%2,%3}, {%4,%5,%6,%7}, {%8,%9}, {%0,%1,%2,%3};"
        : "+f"(c[0]), "+f"(c[1]), "+f"(c[2]), "+f"(c[3])
        : "r"(a[0]), "r"(a[1]), "r"(a[2]), "r"(a[3]), "r"(b[0]), "r"(b[1]));
}
static __device__ __forceinline__ uint32_t tanh2(uint32_t x) {
    uint32_t o;
    asm("tanh.approx.f16x2 %0, %1;" : "=r"(o) : "r"(x));
    return o;
}
#define CP_ASYNC16(dst, src) \
    asm volatile("cp.async.cg.shared.global [%0], [%1], 16;" :: "r"(dst), "l"(src))
#define CP_COMMIT() asm volatile("cp.async.commit_group;" ::: "memory")
#define CP_WAIT1()  asm volatile("cp.async.wait_group 1;" ::: "memory")
#define CP_WAIT0()  asm volatile("cp.async.wait_group 0;" ::: "memory")

// ---------------------------------------------------------------------------
// Merged fp32 -> fp16 conversion: x | Wq/Wk/Wv | Wp
// ---------------------------------------------------------------------------
__global__ void __launch_bounds__(256) conv_all_k(const float* __restrict__ x,
                                                  const float* __restrict__ Wq,
                                                  const float* __restrict__ Wk,
                                                  const float* __restrict__ Wv,
                                                  const float* __restrict__ Wp) {
    int i = blockIdx.x * blockDim.x + threadIdx.x;   // float4 index
    const float* src;
    int rel;
    if (i < 1048576) {
        float4 v = *(const float4*)(x + (size_t)i * 4);
        *(__half2*)(g_xh + (size_t)i * 4)     = __floats2half2_rn(v.x, v.y);
        *(__half2*)(g_xh + (size_t)i * 4 + 2) = __floats2half2_rn(v.z, v.w);
    } else if (i < 1572864) {
        int wrel = i - 1048576;
        if (wrel < 262144)      { src = Wq; rel = wrel; }
        else if (wrel < 393216) { src = Wk; rel = wrel - 262144; }
        else                    { src = Wv; rel = wrel - 393216; }
        float4 v = *(const float4*)(src + (size_t)rel * 4);
        *(__half2*)(g_wh + (size_t)wrel * 4)     = __floats2half2_rn(v.x, v.y);
        *(__half2*)(g_wh + (size_t)wrel * 4 + 2) = __floats2half2_rn(v.z, v.w);
    } else {
        rel = i - 1572864;
        float4 v = *(const float4*)(Wp + (size_t)rel * 4);
        *(__half2*)(g_wph + (size_t)rel * 4)     = __floats2half2_rn(v.x, v.y);
        *(__half2*)(g_wph + (size_t)rel * 4 + 2) = __floats2half2_rn(v.z, v.w);
    }
}

// ---------------------------------------------------------------------------
// fp16 GEMM mainloop (128x128 tile): 3-stage cp.async pipeline.
// ---------------------------------------------------------------------------
#define KC2 64
#define LDT2 72
#define TSB2 (128 * LDT2 * 2)    // 18432
#define BUF2 (2 * TSB2)          // 36864
#define GEMM_SMEM3 (3 * BUF2)    // 110592

static __device__ __forceinline__ void gemm_mainloop(
    const __half* __restrict__ A, const __half* __restrict__ B,
    int m0, float acc[2][8][4]) {

    extern __shared__ __half dsm[];
    uint32_t sbase = s2u(dsm);

    int tid  = threadIdx.x;
    int wid  = tid >> 5;
    int lane = tid & 31;
    int wm   = wid >> 1;
    int wn   = wid & 1;

    uint32_t offA = (uint32_t)(wm * 32 + (lane & 15)) * (LDT2 * 2) + (lane >> 4) * 16;
    int rB = wn * 64 + ((lane >> 3) & 1) * 8 + (lane & 7);
    uint32_t offB = (uint32_t)rB * (LDT2 * 2) + (lane >> 4) * 16;

    const __half* ap[4];
    const __half* bp[4];
    uint32_t ld[4];
#pragma unroll
    for (int i = 0; i < 4; i++) {
        int idx = tid + i * 256;
        int r  = idx >> 3;
        int sn = (idx & 7) * 8;
        ld[i] = (uint32_t)r * (LDT2 * 2) + sn * 2;
        ap[i] = A + (size_t)(m0 + r) * C_DIM + sn;
        bp[i] = B + (size_t)r * C_DIM + sn;
    }

#define G_LOAD(buf) do {                                                       \
    uint32_t so = sbase + (buf) * BUF2;                                        \
    _Pragma("unroll")                                                          \
    for (int i = 0; i < 4; i++) {                                              \
        CP_ASYNC16(so + ld[i], ap[i]);                                         \
        CP_ASYNC16(so + TSB2 + ld[i], bp[i]);                                  \
        ap[i] += KC2; bp[i] += KC2;                                            \
    }                                                                          \
    CP_COMMIT();                                                               \
} while (0)

    G_LOAD(0);
    G_LOAD(1);

    const int NCH = C_DIM / KC2;
    int buf = 0, lb = 2;
    for (int ch = 0; ch < NCH; ch++) {
        if (ch + 1 < NCH) CP_WAIT1(); else CP_WAIT0();
        __syncthreads();
        if (ch + 2 < NCH) {
            G_LOAD(lb);
            lb = (lb == 2) ? 0 : lb + 1;
        }

        uint32_t aA = sbase + buf * BUF2 + offA;
        uint32_t aB = sbase + buf * BUF2 + TSB2 + offB;

#pragma unroll
        for (int ks = 0; ks < 4; ks++) {
            uint32_t koff = ks * 32;
            uint32_t a[2][4], b[4][4];
#pragma unroll
            for (int mi = 0; mi < 2; mi++)
                ldsm4(a[mi], aA + mi * 16 * (LDT2 * 2) + koff);
#pragma unroll
            for (int njp = 0; njp < 4; njp++)
                ldsm4(b[njp], aB + njp * 16 * (LDT2 * 2) + koff);
#pragma unroll
            for (int mi = 0; mi < 2; mi++)
#pragma unroll
                for (int njp = 0; njp < 4; njp++) {
                    uint32_t be[2] = {b[njp][0], b[njp][2]};
                    uint32_t bo[2] = {b[njp][1], b[njp][3]};
                    mma16816h(acc[mi][2 * njp + 0], a[mi], be);
                    mma16816h(acc[mi][2 * njp + 1], a[mi], bo);
                }
        }
        buf = (buf == 2) ? 0 : buf + 1;
    }
#undef G_LOAD
}

// ---------------------------------------------------------------------------
// QKV GEMM with fused epilogues; braid scalars written as fp16 * 0.5.
// ---------------------------------------------------------------------------
__global__ void __launch_bounds__(256, 2) qkv_tc_k(const float* __restrict__ cosp,
                                                   const float* __restrict__ sinp,
                                                   const float* __restrict__ wb) {
    int mt = blockIdx.x, nb = blockIdx.y;
    int n0 = nb * 128;
    int m0 = mt * 128;

    float acc[2][8][4];
#pragma unroll
    for (int mi = 0; mi < 2; mi++)
#pragma unroll
        for (int nj = 0; nj < 8; nj++)
#pragma unroll
            for (int u = 0; u < 4; u++) acc[mi][nj][u] = 0.f;

    gemm_mainloop(g_xh, g_wh + (size_t)n0 * C_DIM, m0, acc);

    int tid  = threadIdx.x;
    int wid  = tid >> 5;
    int lane = tid & 31;
    int wm   = wid >> 1;
    int wn   = wid & 1;
    int erow = wm * 32 + (lane >> 2);
    int e    = (lane & 3) * 2;

    if (nb < 12) {
        __half* souts;
        int nheads, hh;
        if (nb < 8) { souts = g_sqh; nheads = NH;  hh = 2 * nb + wn; }
        else        { souts = g_skh; nheads = NKV; hh = 2 * (nb - 8) + wn; }

#pragma unroll
        for (int mi = 0; mi < 2; mi++)
#pragma unroll
            for (int hf = 0; hf < 2; hf++) {
                int r = erow + mi * 16 + hf * 8;
                int m = m0 + r;
                int t = m & (T_SEQ - 1);
                int b = m >> 11;
                int ub = hf * 2;
                const float* cr = cosp + t * 32;
                const float* sr = sinp + t * 32;
                float ssum = 0.f, dsum = 0.f;
#pragma unroll
                for (int nj = 0; nj < 4; nj++)
#pragma unroll
                    for (int u = 0; u < 2; u++) {
                        int d = e + u + nj * 8;
                        float x1 = acc[mi][nj][ub + u];
                        float x2 = acc[mi][nj + 4][ub + u];
                        float c = cr[d], s = sr[d];
                        float o1 = x1 * c + x2 * s;
                        float o2 = x2 * c - x1 * s;
                        ssum += o1 * o1 + o2 * o2;
                        dsum += o1 * wb[d] + o2 * wb[d + 32];
                    }
                ssum += __shfl_xor_sync(0xffffffffu, ssum, 1);
                dsum += __shfl_xor_sync(0xffffffffu, dsum, 1);
                ssum += __shfl_xor_sync(0xffffffffu, ssum, 2);
                dsum += __shfl_xor_sync(0xffffffffu, dsum, 2);
                if ((lane & 3) == 0) {
                    float scale = rsqrtf(ssum * (1.f / 64.f) + 1e-6f);
                    souts[((size_t)b * nheads + hh) * T_SEQ + t] =
                        __float2half(dsum * scale * 0.5f);
                }
            }
    } else {
        int kh = 2 * (nb - 12) + wn;
#pragma unroll
        for (int mi = 0; mi < 2; mi++)
#pragma unroll
            for (int hf = 0; hf < 2; hf++) {
                int r = erow + mi * 16 + hf * 8;
                int m = m0 + r;
                int t = m & (T_SEQ - 1);
                int b = m >> 11;
                int ub = hf * 2;
                __half* vp = g_vh + (((size_t)b * T_SEQ + t) * NKV + kh) * HD;
#pragma unroll
                for (int nj = 0; nj < 8; nj++)
                    *(__half2*)(vp + e + nj * 8) =
                        __floats2half2_rn(acc[mi][nj][ub], acc[mi][nj][ub + 1]);
            }
    }
}

// ---------------------------------------------------------------------------
// Proj GEMM: 128x64 tiles (512 blocks -> better wave balance).
// 8 warps (4M x 2N), warp tile 32x32, K-chunk 64, 3-stage pipeline.
// ---------------------------------------------------------------------------
#define TSBA (128 * LDT2 * 2)   // 18432
#define TSBB (64 * LDT2 * 2)    // 9216
#define PBUF (TSBA + TSBB)      // 27648
#define PROJ_SMEM3 (3 * PBUF)   // 82944

__global__ void __launch_bounds__(256, 2) proj_tc_k(float* __restrict__ out) {
    int mt = blockIdx.x, nb = blockIdx.y;
    int m0 = mt * 128;
    const __half* A = g_yh;
    const __half* B = g_wph + (size_t)nb * 64 * C_DIM;

    extern __shared__ __half dsm[];
    uint32_t sbase = s2u(dsm);

    int tid  = threadIdx.x;
    int wid  = tid >> 5;
    int lane = tid & 31;
    int wm   = wid >> 1;
    int wn   = wid & 1;

    float acc[2][4][4];
#pragma unroll
    for (int mi = 0; mi < 2; mi++)
#pragma unroll
        for (int nj = 0; nj < 4; nj++)
#pragma unroll
            for (int u = 0; u < 4; u++) acc[mi][nj][u] = 0.f;

    uint32_t offA = (uint32_t)(wm * 32 + (lane & 15)) * (LDT2 * 2) + (lane >> 4) * 16;
    int rB = wn * 32 + ((lane >> 3) & 1) * 8 + (lane & 7);
    uint32_t offB = (uint32_t)rB * (LDT2 * 2) + (lane >> 4) * 16;

    // loaders: A 1024 segs (4/thread), B 512 segs (2/thread)
    const __half* ap[4];
    const __half* bp[2];
    uint32_t lda[4], ldb[2];
#pragma unroll
    for (int i = 0; i < 4; i++) {
        int idx = tid + i * 256;
        int r  = idx >> 3;
        int sn = (idx & 7) * 8;
        lda[i] = (uint32_t)r * (LDT2 * 2) + sn * 2;
        ap[i] = A + (size_t)(m0 + r) * C_DIM + sn;
    }
#pragma unroll
    for (int i = 0; i < 2; i++) {
        int idx = tid + i * 256;
        int r  = idx >> 3;
        int sn = (idx & 7) * 8;
        ldb[i] = (uint32_t)r * (LDT2 * 2) + sn * 2;
        bp[i] = B + (size_t)r * C_DIM + sn;
    }

#define P_LOAD(buf) do {                                                       \
    uint32_t so = sbase + (buf) * PBUF;                                        \
    _Pragma("unroll")                                                          \
    for (int i = 0; i < 4; i++) { CP_ASYNC16(so + lda[i], ap[i]); ap[i] += KC2; } \
    _Pragma("unroll")                                                          \
    for (int i = 0; i < 2; i++) { CP_ASYNC16(so + TSBA + ldb[i], bp[i]); bp[i] += KC2; } \
    CP_COMMIT();                                                               \
} while (0)

    P_LOAD(0);
    P_LOAD(1);

    const int NCH = C_DIM / KC2;
    int buf = 0, lb = 2;
    for (int ch = 0; ch < NCH; ch++) {
        if (ch + 1 < NCH) CP_WAIT1(); else CP_WAIT0();
        __syncthreads();
        if (ch + 2 < NCH) {
            P_LOAD(lb);
            lb = (lb == 2) ? 0 : lb + 1;
        }

        uint32_t aA = sbase + buf * PBUF + offA;
        uint32_t aB = sbase + buf * PBUF + TSBA + offB;

#pragma unroll
        for (int ks = 0; ks < 4; ks++) {
            uint32_t koff = ks * 32;
            uint32_t a[2][4], b[2][4];
#pragma unroll
            for (int mi = 0; mi < 2; mi++)
                ldsm4(a[mi], aA + mi * 16 * (LDT2 * 2) + koff);
#pragma unroll
            for (int njp = 0; njp < 2; njp++)
                ldsm4(b[njp], aB + njp * 16 * (LDT2 * 2) + koff);
#pragma unroll
            for (int mi = 0; mi < 2; mi++)
#pragma unroll
                for (int njp = 0; njp < 2; njp++) {
                    uint32_t be[2] = {b[njp][0], b[njp][2]};
                    uint32_t bo[2] = {b[njp][1], b[njp][3]};
                    mma16816h(acc[mi][2 * njp + 0], a[mi], be);
                    mma16816h(acc[mi][2 * njp + 1], a[mi], bo);
                }
        }
        buf = (buf == 2) ? 0 : buf + 1;
    }
#undef P_LOAD

    int erow = wm * 32 + (lane >> 2);
    int ecol = wn * 32 + (lane & 3) * 2;
#pragma unroll
    for (int mi = 0; mi < 2; mi++)
#pragma unroll
        for (int nj = 0; nj < 4; nj++) {
            int row = erow + mi * 16;
            int col = nb * 64 + ecol + nj * 8;
            float* p0 = out + (size_t)(m0 + row) * C_DIM + col;
            float* p1 = out + (size_t)(m0 + row + 8) * C_DIM + col;
            *(float2*)p0 = make_float2(acc[mi][nj][0], acc[mi][nj][1]);
            *(float2*)p1 = make_float2(acc[mi][nj][2], acc[mi][nj][3]);
        }
}

// ---------------------------------------------------------------------------
// Attention: fp16 P-chain + ldmatrix.trans V (no pre-transpose kernel).
// V tiles loaded as [s][d] rows straight from g_vh.
// ---------------------------------------------------------------------------
#define ALDS 72
#define AVROW (ALDS * 2)
#define AVBUF (64 * AVROW)

__global__ void __launch_bounds__(256, 3) attn_tc_k() {
    __shared__ __align__(16) __half Vh[3][64][ALDS];
    __shared__ __half SQ[128];
    __shared__ __align__(16) __half SK[3][64];

    int tt = (T_SEQ / 64 - 1) - blockIdx.x;
    int kh = blockIdx.y;
    int b  = blockIdx.z;
    int t0 = tt * 64;

    int tid  = threadIdx.x;
    int wid  = tid >> 5;
    int lane = tid & 31;

    if (tid < 128) {
        int hl = tid >> 6, tl = tid & 63;
        SQ[tid] = g_sqh[((size_t)b * NH + kh * 2 + hl) * T_SEQ + t0 + tl];
    }

    // V rows: [b][t][kh][d]; row stride = NKV*HD = 512 halves
    const __half* gv = g_vh + ((size_t)b * T_SEQ * NKV + kh) * HD;
    const __half* gsk = g_skh + ((size_t)b * NKV + kh) * T_SEQ;

    uint32_t sVh = s2u(Vh), sSK = s2u(SK);

    int vr0 = tid >> 3,   vc = (tid & 7) * 8;   // vr0: 0..31
    int vr1 = vr0 + 32;
    uint32_t vd0 = (uint32_t)vr0 * AVROW + vc * 2;
    uint32_t vd1 = (uint32_t)vr1 * AVROW + vc * 2;

    const __half* vp0 = gv + (size_t)vr0 * (NKV * HD) + vc;
    const __half* vp1 = gv + (size_t)vr1 * (NKV * HD) + vc;
    const __half* skp = gsk + (tid & 7) * 8;

#define AV_LOAD(buf) do {                                                      \
    uint32_t bo = (buf) * AVBUF;                                               \
    CP_ASYNC16(sVh + bo + vd0, vp0);                                           \
    CP_ASYNC16(sVh + bo + vd1, vp1);                                           \
    if (tid < 8) CP_ASYNC16(sSK + (buf) * 128 + tid * 16, skp);                \
    vp0 += 64 * NKV * HD; vp1 += 64 * NKV * HD; skp += 64;                     \
    CP_COMMIT();                                                               \
} while (0)

    float acc[8][4];
#pragma unroll
    for (int nj = 0; nj < 8; nj++)
#pragma unroll
        for (int u = 0; u < 4; u++) acc[nj][u] = 0.f;

    int r  = lane >> 2;
    int c2 = (lane & 3) * 2;
    int row0 = wid * 16 + r;
    int tl0 = row0 & 63, tl1 = (row0 + 8) & 63;

    // trans-B lane mapping: row = s (k dim), col = d (n dim)
    int rowpart = ((lane >> 3) & 1) * 8 + (lane & 7);   // s within k16
    uint32_t offBt = (uint32_t)rowpart * AVROW + (lane >> 4) * 16;

    AV_LOAD(0);
    AV_LOAD(1);
    __syncthreads();   // SQ visible

    __half2 sq0h = __half2half2(SQ[row0]);
    __half2 sq1h = __half2half2(SQ[row0 + 8]);
    const __half2 half05 = __floats2half2_rn(0.5f, 0.5f);

    const int NCH = tt + 1;
    int buf = 0, lb = 2;
    for (int ch = 0; ch < NCH; ch++) {
        if (ch + 1 < NCH) CP_WAIT1(); else CP_WAIT0();
        __syncthreads();
        if (ch + 2 < NCH) {
            AV_LOAD(lb);
            lb = (lb == 2) ? 0 : lb + 1;
        }

        bool diag = (ch == tt);
        const __half* SKb = SK[buf];
        uint32_t vbh = sVh + buf * AVBUF + offBt;

#pragma unroll 2
        for (int ks = 0; ks < 4; ks++) {
            int kb = ks * 16 + c2;
            __half2 s01 = *(const __half2*)&SKb[kb];
            __half2 s89 = *(const __half2*)&SKb[kb + 8];

            uint32_t ah[4];
            {
                __half2 z0 = __hadd2(sq0h, s01);
                __half2 z1 = __hadd2(sq1h, s01);
                __half2 z2 = __hadd2(sq0h, s89);
                __half2 z3 = __hadd2(sq1h, s89);
                __half2 p0, p1, p2, p3;
                *(uint32_t*)&p0 = tanh2(*(uint32_t*)&z0);
                *(uint32_t*)&p1 = tanh2(*(uint32_t*)&z1);
                *(uint32_t*)&p2 = tanh2(*(uint32_t*)&z2);
                *(uint32_t*)&p3 = tanh2(*(uint32_t*)&z3);
                p0 = __hfma2(p0, half05, half05);
                p1 = __hfma2(p1, half05, half05);
                p2 = __hfma2(p2, half05, half05);
                p3 = __hfma2(p3, half05, half05);
                if (diag) {
                    __half2 m0 = __floats2half2_rn(kb <= tl0 ? 1.f : 0.f,
                                                   kb + 1 <= tl0 ? 1.f : 0.f);
                    __half2 m1 = __floats2half2_rn(kb <= tl1 ? 1.f : 0.f,
                                                   kb + 1 <= tl1 ? 1.f : 0.f);
                    __half2 m2 = __floats2half2_rn(kb + 8 <= tl0 ? 1.f : 0.f,
                                                   kb + 9 <= tl0 ? 1.f : 0.f);
                    __half2 m3 = __floats2half2_rn(kb + 8 <= tl1 ? 1.f : 0.f,
                                                   kb + 9 <= tl1 ? 1.f : 0.f);
                    p0 = __hmul2(p0, m0);
                    p1 = __hmul2(p1, m1);
                    p2 = __hmul2(p2, m2);
                    p3 = __hmul2(p3, m3);
                }
                ah[0] = *(uint32_t*)&p0;
                ah[1] = *(uint32_t*)&p1;
                ah[2] = *(uint32_t*)&p2;
                ah[3] = *(uint32_t*)&p3;
            }

            // trans ldmatrix: matrices (k0-7,d0-7),(k8-15,d0-7),(k0-7,d8-15),(k8-15,d8-15)
            uint32_t bh[4][4];
#pragma unroll
            for (int njp = 0; njp < 4; njp++)
                ldsm4t(bh[njp], vbh + ks * 16 * AVROW + njp * 32);
#pragma unroll
            for (int njp = 0; njp < 4; njp++) {
                uint32_t be[2] = {bh[njp][0], bh[njp][1]};
                uint32_t bo[2] = {bh[njp][2], bh[njp][3]};
                mma16816h(acc[2 * njp + 0], ah, be);
                mma16816h(acc[2 * njp + 1], ah, bo);
            }
        }
        buf = (buf == 2) ? 0 : buf + 1;
    }

    const float inv = 1.f / (sqrtf((float)T_SEQ) + 1e-6f);
    int hgl = kh * 2 + (row0 >> 6);
    int tA = t0 + tl0, tB = t0 + tl1;
    __half* yA = g_yh + (((size_t)b * T_SEQ + tA) * NH + hgl) * HD;
    __half* yB = g_yh + (((size_t)b * T_SEQ + tB) * NH + hgl) * HD;
#pragma unroll
    for (int nj = 0; nj < 8; nj++) {
        int d = nj * 8 + c2;
        *(__half2*)(yA + d) = __floats2half2_rn(acc[nj][0] * inv, acc[nj][1] * inv);
        *(__half2*)(yB + d) = __floats2half2_rn(acc[nj][2] * inv, acc[nj][3] * inv);
    }
}

// ---------------------------------------------------------------------------
extern "C" void kernel_launch(void* const* d_in, const int* in_sizes, int n_in,
                              void* d_out, int out_size) {
    const float* x    = (const float*)d_in[0];
    const float* cosp = (const float*)d_in[1];
    const float* sinp = (const float*)d_in[2];
    const float* Wq   = (const float*)d_in[3];
    const float* Wk   = (const float*)d_in[4];
    const float* Wv   = (const float*)d_in[5];
    const float* Wp   = (const float*)d_in[6];
    const float* wb   = (const float*)d_in[7];
    float* out = (float*)d_out;

    cudaFuncSetAttribute(qkv_tc_k,  cudaFuncAttributeMaxDynamicSharedMemorySize, GEMM_SMEM3);
    cudaFuncSetAttribute(proj_tc_k, cudaFuncAttributeMaxDynamicSharedMemorySize, PROJ_SMEM3);

    conv_all_k<<<7168, 256>>>(x, Wq, Wk, Wv, Wp);

    qkv_tc_k<<<dim3(32, 16), 256, GEMM_SMEM3>>>(cosp, sinp, wb);

    attn_tc_k<<<dim3(T_SEQ / 64, NKV, BATCH), 256>>>();

    proj_tc_k<<<dim3(32, 16), 256, PROJ_SMEM3>>>(out);
}

// round 13
// speedup vs baseline: 8.6716x; 1.0221x over previous
#include <cuda_runtime.h>
#include <cuda_fp16.h>
#include <math.h>
#include <stdint.h>

#define BATCH 2
#define T_SEQ 2048
#define C_DIM 1024
#define NH 16
#define NKV 8
#define HD 64
#define M_ROWS (BATCH * T_SEQ)   // 4096

// ---------------------------------------------------------------------------
// Scratch (__device__ globals)
// ---------------------------------------------------------------------------
__device__ __half g_sqh[BATCH * NH * T_SEQ];   // 0.5 * braid-q scalar, fp16
__device__ __half g_skh[BATCH * NKV * T_SEQ];  // 0.5 * braid-k scalar, fp16

__device__ __half g_xh[M_ROWS * C_DIM];
__device__ __half g_wh[2048 * C_DIM];     // 0-1023 Wq, 1024-1535 Wk, 1536-2047 Wv
__device__ __half g_wph[C_DIM * C_DIM];
__device__ __half g_yh[M_ROWS * C_DIM];   // attn output, [b][t][h][d]
__device__ __half g_vh[M_ROWS * NKV * HD];  // V fp16 [b][t][kh][d]

// ---------------------------------------------------------------------------
// PTX helpers
// ---------------------------------------------------------------------------
static __device__ __forceinline__ uint32_t s2u(const void* p) {
    uint32_t a;
    asm("{ .reg .u64 t; cvta.to.shared.u64 t, %1; cvt.u32.u64 %0, t; }"
        : "=r"(a) : "l"(p));
    return a;
}
static __device__ __forceinline__ void ldsm4(uint32_t* r, uint32_t addr) {
    asm volatile("ldmatrix.sync.aligned.m8n8.x4.shared.b16 {%0,%1,%2,%3}, [%4];"
                 : "=r"(r[0]), "=r"(r[1]), "=r"(r[2]), "=r"(r[3]) : "r"(addr));
}
static __device__ __forceinline__ void ldsm4t(uint32_t* r, uint32_t addr) {
    asm volatile("ldmatrix.sync.aligned.m8n8.x4.trans.shared.b16 {%0,%1,%2,%3}, [%4];"
                 : "=r"(r[0]), "=r"(r[1]), "=r"(r[2]), "=r"(r[3]) : "r"(addr));
}
static __device__ __forceinline__ void mma16816h(float* c, const uint32_t* a,
                                                 const uint32_t* b) {
    asm volatile(
        "mma.sync.aligned.m16n8k16.row.col.f32.f16.f16.f32 "
        "{%0,%1,%2,%3}, {%4,%5,%6,%7}, {%8,%9}, {%0,%1,%2,%3};"
        : "+f"(c[0]), "+f"(c[1]), "+f"(c[2]), "+f"(c[3])
        : "r"(a[0]), "r"(a[1]), "r"(a[2]), "r"(a[3]), "r"(b[0]), "r"(b[1]));
}
static __device__ __forceinline__ uint32_t tanh2(uint32_t x) {
    uint32_t o;
    asm("tanh.approx.f16x2 %0, %1;" : "=r"(o) : "r"(x));
    return o;
}
#define CP_ASYNC16(dst, src) \
    asm volatile("cp.async.cg.shared.global [%0], [%1], 16;" :: "r"(dst), "l"(src))
#define CP_COMMIT() asm volatile("cp.async.commit_group;" ::: "memory")
#define CP_WAIT1()  asm volatile("cp.async.wait_group 1;" ::: "memory")
#define CP_WAIT0()  asm volatile("cp.async.wait_group 0;" ::: "memory")

// ---------------------------------------------------------------------------
// Merged fp32 -> fp16 conversion: x | Wq/Wk/Wv | Wp
// ---------------------------------------------------------------------------
__global__ void __launch_bounds__(256) conv_all_k(const float* __restrict__ x,
                                                  const float* __restrict__ Wq,
                                                  const float* __restrict__ Wk,
                                                  const float* __restrict__ Wv,
                                                  const float* __restrict__ Wp) {
    int i = blockIdx.x * blockDim.x + threadIdx.x;   // float4 index
    const float* src;
    int rel;
    if (i < 1048576) {
        float4 v = *(const float4*)(x + (size_t)i * 4);
        *(__half2*)(g_xh + (size_t)i * 4)     = __floats2half2_rn(v.x, v.y);
        *(__half2*)(g_xh + (size_t)i * 4 + 2) = __floats2half2_rn(v.z, v.w);
    } else if (i < 1572864) {
        int wrel = i - 1048576;
        if (wrel < 262144)      { src = Wq; rel = wrel; }
        else if (wrel < 393216) { src = Wk; rel = wrel - 262144; }
        else                    { src = Wv; rel = wrel - 393216; }
        float4 v = *(const float4*)(src + (size_t)rel * 4);
        *(__half2*)(g_wh + (size_t)wrel * 4)     = __floats2half2_rn(v.x, v.y);
        *(__half2*)(g_wh + (size_t)wrel * 4 + 2) = __floats2half2_rn(v.z, v.w);
    } else {
        rel = i - 1572864;
        float4 v = *(const float4*)(Wp + (size_t)rel * 4);
        *(__half2*)(g_wph + (size_t)rel * 4)     = __floats2half2_rn(v.x, v.y);
        *(__half2*)(g_wph + (size_t)rel * 4 + 2) = __floats2half2_rn(v.z, v.w);
    }
}

// ---------------------------------------------------------------------------
// fp16 GEMM mainloop (128x128 tile): 3-stage cp.async pipeline.
// ---------------------------------------------------------------------------
#define KC2 64
#define LDT2 72
#define TSB2 (128 * LDT2 * 2)    // 18432
#define BUF2 (2 * TSB2)          // 36864
#define GEMM_SMEM3 (3 * BUF2)    // 110592

static __device__ __forceinline__ void gemm_mainloop(
    const __half* __restrict__ A, const __half* __restrict__ B,
    int m0, float acc[2][8][4]) {

    extern __shared__ __half dsm[];
    uint32_t sbase = s2u(dsm);

    int tid  = threadIdx.x;
    int wid  = tid >> 5;
    int lane = tid & 31;
    int wm   = wid >> 1;
    int wn   = wid & 1;

    uint32_t offA = (uint32_t)(wm * 32 + (lane & 15)) * (LDT2 * 2) + (lane >> 4) * 16;
    int rB = wn * 64 + ((lane >> 3) & 1) * 8 + (lane & 7);
    uint32_t offB = (uint32_t)rB * (LDT2 * 2) + (lane >> 4) * 16;

    const __half* ap[4];
    const __half* bp[4];
    uint32_t ld[4];
#pragma unroll
    for (int i = 0; i < 4; i++) {
        int idx = tid + i * 256;
        int r  = idx >> 3;
        int sn = (idx & 7) * 8;
        ld[i] = (uint32_t)r * (LDT2 * 2) + sn * 2;
        ap[i] = A + (size_t)(m0 + r) * C_DIM + sn;
        bp[i] = B + (size_t)r * C_DIM + sn;
    }

#define G_LOAD(buf) do {                                                       \
    uint32_t so = sbase + (buf) * BUF2;                                        \
    _Pragma("unroll")                                                          \
    for (int i = 0; i < 4; i++) {                                              \
        CP_ASYNC16(so + ld[i], ap[i]);                                         \
        CP_ASYNC16(so + TSB2 + ld[i], bp[i]);                                  \
        ap[i] += KC2; bp[i] += KC2;                                            \
    }                                                                          \
    CP_COMMIT();                                                               \
} while (0)

    G_LOAD(0);
    G_LOAD(1);

    const int NCH = C_DIM / KC2;
    int buf = 0, lb = 2;
    for (int ch = 0; ch < NCH; ch++) {
        if (ch + 1 < NCH) CP_WAIT1(); else CP_WAIT0();
        __syncthreads();
        if (ch + 2 < NCH) {
            G_LOAD(lb);
            lb = (lb == 2) ? 0 : lb + 1;
        }

        uint32_t aA = sbase + buf * BUF2 + offA;
        uint32_t aB = sbase + buf * BUF2 + TSB2 + offB;

#pragma unroll
        for (int ks = 0; ks < 4; ks++) {
            uint32_t koff = ks * 32;
            uint32_t a[2][4], b[4][4];
#pragma unroll
            for (int mi = 0; mi < 2; mi++)
                ldsm4(a[mi], aA + mi * 16 * (LDT2 * 2) + koff);
#pragma unroll
            for (int njp = 0; njp < 4; njp++)
                ldsm4(b[njp], aB + njp * 16 * (LDT2 * 2) + koff);
#pragma unroll
            for (int mi = 0; mi < 2; mi++)
#pragma unroll
                for (int njp = 0; njp < 4; njp++) {
                    uint32_t be[2] = {b[njp][0], b[njp][2]};
                    uint32_t bo[2] = {b[njp][1], b[njp][3]};
                    mma16816h(acc[mi][2 * njp + 0], a[mi], be);
                    mma16816h(acc[mi][2 * njp + 1], a[mi], bo);
                }
        }
        buf = (buf == 2) ? 0 : buf + 1;
    }
#undef G_LOAD
}

// ---------------------------------------------------------------------------
// QKV GEMM with fused epilogues; braid scalars written as fp16 * 0.5.
// ---------------------------------------------------------------------------
__global__ void __launch_bounds__(256, 2) qkv_tc_k(const float* __restrict__ cosp,
                                                   const float* __restrict__ sinp,
                                                   const float* __restrict__ wb) {
    int mt = blockIdx.x, nb = blockIdx.y;
    int n0 = nb * 128;
    int m0 = mt * 128;

    float acc[2][8][4];
#pragma unroll
    for (int mi = 0; mi < 2; mi++)
#pragma unroll
        for (int nj = 0; nj < 8; nj++)
#pragma unroll
            for (int u = 0; u < 4; u++) acc[mi][nj][u] = 0.f;

    gemm_mainloop(g_xh, g_wh + (size_t)n0 * C_DIM, m0, acc);

    int tid  = threadIdx.x;
    int wid  = tid >> 5;
    int lane = tid & 31;
    int wm   = wid >> 1;
    int wn   = wid & 1;
    int erow = wm * 32 + (lane >> 2);
    int e    = (lane & 3) * 2;

    if (nb < 12) {
        __half* souts;
        int nheads, hh;
        if (nb < 8) { souts = g_sqh; nheads = NH;  hh = 2 * nb + wn; }
        else        { souts = g_skh; nheads = NKV; hh = 2 * (nb - 8) + wn; }

#pragma unroll
        for (int mi = 0; mi < 2; mi++)
#pragma unroll
            for (int hf = 0; hf < 2; hf++) {
                int r = erow + mi * 16 + hf * 8;
                int m = m0 + r;
                int t = m & (T_SEQ - 1);
                int b = m >> 11;
                int ub = hf * 2;
                const float* cr = cosp + t * 32;
                const float* sr = sinp + t * 32;
                float ssum = 0.f, dsum = 0.f;
#pragma unroll
                for (int nj = 0; nj < 4; nj++)
#pragma unroll
                    for (int u = 0; u < 2; u++) {
                        int d = e + u + nj * 8;
                        float x1 = acc[mi][nj][ub + u];
                        float x2 = acc[mi][nj + 4][ub + u];
                        float c = cr[d], s = sr[d];
                        float o1 = x1 * c + x2 * s;
                        float o2 = x2 * c - x1 * s;
                        ssum += o1 * o1 + o2 * o2;
                        dsum += o1 * wb[d] + o2 * wb[d + 32];
                    }
                ssum += __shfl_xor_sync(0xffffffffu, ssum, 1);
                dsum += __shfl_xor_sync(0xffffffffu, dsum, 1);
                ssum += __shfl_xor_sync(0xffffffffu, ssum, 2);
                dsum += __shfl_xor_sync(0xffffffffu, dsum, 2);
                if ((lane & 3) == 0) {
                    float scale = rsqrtf(ssum * (1.f / 64.f) + 1e-6f);
                    souts[((size_t)b * nheads + hh) * T_SEQ + t] =
                        __float2half(dsum * scale * 0.5f);
                }
            }
    } else {
        int kh = 2 * (nb - 12) + wn;
#pragma unroll
        for (int mi = 0; mi < 2; mi++)
#pragma unroll
            for (int hf = 0; hf < 2; hf++) {
                int r = erow + mi * 16 + hf * 8;
                int m = m0 + r;
                int t = m & (T_SEQ - 1);
                int b = m >> 11;
                int ub = hf * 2;
                __half* vp = g_vh + (((size_t)b * T_SEQ + t) * NKV + kh) * HD;
#pragma unroll
                for (int nj = 0; nj < 8; nj++)
                    *(__half2*)(vp + e + nj * 8) =
                        __floats2half2_rn(acc[mi][nj][ub], acc[mi][nj][ub + 1]);
            }
    }
}

// ---------------------------------------------------------------------------
// Proj GEMM: 128x128 tile (reverted to validated round-11 config).
// ---------------------------------------------------------------------------
__global__ void __launch_bounds__(256, 2) proj_tc_k(float* __restrict__ out) {
    int mt = blockIdx.x, nb = blockIdx.y;
    int m0 = mt * 128;

    float acc[2][8][4];
#pragma unroll
    for (int mi = 0; mi < 2; mi++)
#pragma unroll
        for (int nj = 0; nj < 8; nj++)
#pragma unroll
            for (int u = 0; u < 4; u++) acc[mi][nj][u] = 0.f;

    gemm_mainloop(g_yh, g_wph + (size_t)nb * 128 * C_DIM, m0, acc);

    int tid  = threadIdx.x;
    int wid  = tid >> 5;
    int lane = tid & 31;
    int wm   = wid >> 1;
    int wn   = wid & 1;
    int erow = wm * 32 + (lane >> 2);
    int ecol = wn * 64 + (lane & 3) * 2;
#pragma unroll
    for (int mi = 0; mi < 2; mi++)
#pragma unroll
        for (int nj = 0; nj < 8; nj++) {
            int row = erow + mi * 16;
            int col = nb * 128 + ecol + nj * 8;
            float* p0 = out + (size_t)(m0 + row) * C_DIM + col;
            float* p1 = out + (size_t)(m0 + row + 8) * C_DIM + col;
            *(float2*)p0 = make_float2(acc[mi][nj][0], acc[mi][nj][1]);
            *(float2*)p1 = make_float2(acc[mi][nj][2], acc[mi][nj][3]);
        }
}

// ---------------------------------------------------------------------------
// Attention: fp16 P-chain + ldmatrix.trans V (validated round-12 version).
// ---------------------------------------------------------------------------
#define ALDS 72
#define AVROW (ALDS * 2)
#define AVBUF (64 * AVROW)

__global__ void __launch_bounds__(256, 3) attn_tc_k() {
    __shared__ __align__(16) __half Vh[3][64][ALDS];
    __shared__ __half SQ[128];
    __shared__ __align__(16) __half SK[3][64];

    int tt = (T_SEQ / 64 - 1) - blockIdx.x;
    int kh = blockIdx.y;
    int b  = blockIdx.z;
    int t0 = tt * 64;

    int tid  = threadIdx.x;
    int wid  = tid >> 5;
    int lane = tid & 31;

    if (tid < 128) {
        int hl = tid >> 6, tl = tid & 63;
        SQ[tid] = g_sqh[((size_t)b * NH + kh * 2 + hl) * T_SEQ + t0 + tl];
    }

    const __half* gv = g_vh + ((size_t)b * T_SEQ * NKV + kh) * HD;
    const __half* gsk = g_skh + ((size_t)b * NKV + kh) * T_SEQ;

    uint32_t sVh = s2u(Vh), sSK = s2u(SK);

    int vr0 = tid >> 3,   vc = (tid & 7) * 8;
    int vr1 = vr0 + 32;
    uint32_t vd0 = (uint32_t)vr0 * AVROW + vc * 2;
    uint32_t vd1 = (uint32_t)vr1 * AVROW + vc * 2;

    const __half* vp0 = gv + (size_t)vr0 * (NKV * HD) + vc;
    const __half* vp1 = gv + (size_t)vr1 * (NKV * HD) + vc;
    const __half* skp = gsk + (tid & 7) * 8;

#define AV_LOAD(buf) do {                                                      \
    uint32_t bo = (buf) * AVBUF;                                               \
    CP_ASYNC16(sVh + bo + vd0, vp0);                                           \
    CP_ASYNC16(sVh + bo + vd1, vp1);                                           \
    if (tid < 8) CP_ASYNC16(sSK + (buf) * 128 + tid * 16, skp);                \
    vp0 += 64 * NKV * HD; vp1 += 64 * NKV * HD; skp += 64;                     \
    CP_COMMIT();                                                               \
} while (0)

    float acc[8][4];
#pragma unroll
    for (int nj = 0; nj < 8; nj++)
#pragma unroll
        for (int u = 0; u < 4; u++) acc[nj][u] = 0.f;

    int r  = lane >> 2;
    int c2 = (lane & 3) * 2;
    int row0 = wid * 16 + r;
    int tl0 = row0 & 63, tl1 = (row0 + 8) & 63;

    int rowpart = ((lane >> 3) & 1) * 8 + (lane & 7);
    uint32_t offBt = (uint32_t)rowpart * AVROW + (lane >> 4) * 16;

    AV_LOAD(0);
    AV_LOAD(1);
    __syncthreads();   // SQ visible

    __half2 sq0h = __half2half2(SQ[row0]);
    __half2 sq1h = __half2half2(SQ[row0 + 8]);
    const __half2 half05 = __floats2half2_rn(0.5f, 0.5f);

    const int NCH = tt + 1;
    int buf = 0, lb = 2;
    for (int ch = 0; ch < NCH; ch++) {
        if (ch + 1 < NCH) CP_WAIT1(); else CP_WAIT0();
        __syncthreads();
        if (ch + 2 < NCH) {
            AV_LOAD(lb);
            lb = (lb == 2) ? 0 : lb + 1;
        }

        bool diag = (ch == tt);
        const __half* SKb = SK[buf];
        uint32_t vbh = sVh + buf * AVBUF + offBt;

#pragma unroll 2
        for (int ks = 0; ks < 4; ks++) {
            int kb = ks * 16 + c2;
            __half2 s01 = *(const __half2*)&SKb[kb];
            __half2 s89 = *(const __half2*)&SKb[kb + 8];

            uint32_t ah[4];
            {
                __half2 z0 = __hadd2(sq0h, s01);
                __half2 z1 = __hadd2(sq1h, s01);
                __half2 z2 = __hadd2(sq0h, s89);
                __half2 z3 = __hadd2(sq1h, s89);
                __half2 p0, p1, p2, p3;
                *(uint32_t*)&p0 = tanh2(*(uint32_t*)&z0);
                *(uint32_t*)&p1 = tanh2(*(uint32_t*)&z1);
                *(uint32_t*)&p2 = tanh2(*(uint32_t*)&z2);
                *(uint32_t*)&p3 = tanh2(*(uint32_t*)&z3);
                p0 = __hfma2(p0, half05, half05);
                p1 = __hfma2(p1, half05, half05);
                p2 = __hfma2(p2, half05, half05);
                p3 = __hfma2(p3, half05, half05);
                if (diag) {
                    __half2 m0 = __floats2half2_rn(kb <= tl0 ? 1.f : 0.f,
                                                   kb + 1 <= tl0 ? 1.f : 0.f);
                    __half2 m1 = __floats2half2_rn(kb <= tl1 ? 1.f : 0.f,
                                                   kb + 1 <= tl1 ? 1.f : 0.f);
                    __half2 m2 = __floats2half2_rn(kb + 8 <= tl0 ? 1.f : 0.f,
                                                   kb + 9 <= tl0 ? 1.f : 0.f);
                    __half2 m3 = __floats2half2_rn(kb + 8 <= tl1 ? 1.f : 0.f,
                                                   kb + 9 <= tl1 ? 1.f : 0.f);
                    p0 = __hmul2(p0, m0);
                    p1 = __hmul2(p1, m1);
                    p2 = __hmul2(p2, m2);
                    p3 = __hmul2(p3, m3);
                }
                ah[0] = *(uint32_t*)&p0;
                ah[1] = *(uint32_t*)&p1;
                ah[2] = *(uint32_t*)&p2;
                ah[3] = *(uint32_t*)&p3;
            }

            uint32_t bh[4][4];
#pragma unroll
            for (int njp = 0; njp < 4; njp++)
                ldsm4t(bh[njp], vbh + ks * 16 * AVROW + njp * 32);
#pragma unroll
            for (int njp = 0; njp < 4; njp++) {
                uint32_t be[2] = {bh[njp][0], bh[njp][1]};
                uint32_t bo[2] = {bh[njp][2], bh[njp][3]};
                mma16816h(acc[2 * njp + 0], ah, be);
                mma16816h(acc[2 * njp + 1], ah, bo);
            }
        }
        buf = (buf == 2) ? 0 : buf + 1;
    }

    const float inv = 1.f / (sqrtf((float)T_SEQ) + 1e-6f);
    int hgl = kh * 2 + (row0 >> 6);
    int tA = t0 + tl0, tB = t0 + tl1;
    __half* yA = g_yh + (((size_t)b * T_SEQ + tA) * NH + hgl) * HD;
    __half* yB = g_yh + (((size_t)b * T_SEQ + tB) * NH + hgl) * HD;
#pragma unroll
    for (int nj = 0; nj < 8; nj++) {
        int d = nj * 8 + c2;
        *(__half2*)(yA + d) = __floats2half2_rn(acc[nj][0] * inv, acc[nj][1] * inv);
        *(__half2*)(yB + d) = __floats2half2_rn(acc[nj][2] * inv, acc[nj][3] * inv);
    }
}

// ---------------------------------------------------------------------------
extern "C" void kernel_launch(void* const* d_in, const int* in_sizes, int n_in,
                              void* d_out, int out_size) {
    const float* x    = (const float*)d_in[0];
    const float* cosp = (const float*)d_in[1];
    const float* sinp = (const float*)d_in[2];
    const float* Wq   = (const float*)d_in[3];
    const float* Wk   = (const float*)d_in[4];
    const float* Wv   = (const float*)d_in[5];
    const float* Wp   = (const float*)d_in[6];
    const float* wb   = (const float*)d_in[7];
    float* out = (float*)d_out;

    cudaFuncSetAttribute(qkv_tc_k,  cudaFuncAttributeMaxDynamicSharedMemorySize, GEMM_SMEM3);
    cudaFuncSetAttribute(proj_tc_k, cudaFuncAttributeMaxDynamicSharedMemorySize, GEMM_SMEM3);

    conv_all_k<<<7168, 256>>>(x, Wq, Wk, Wv, Wp);

    qkv_tc_k<<<dim3(32, 16), 256, GEMM_SMEM3>>>(cosp, sinp, wb);

    attn_tc_k<<<dim3(T_SEQ / 64, NKV, BATCH), 256>>>();

    proj_tc_k<<<dim3(32, 8), 256, GEMM_SMEM3>>>(out);
}